// round 4
// baseline (speedup 1.0000x reference)
#include <cuda_runtime.h>
#include <math.h>
#include <stdint.h>

#define Bq 2
#define SEQ 2048
#define Dm 1024
#define NCx 77
#define DCx 768
#define Hh 16
#define DHd 64
#define FFd 4096
#define SCALE_ATTN 0.125f
#define EPS_LN 1e-5f
#define MROWS (Bq*SEQ)          // 4096
#define CROWS (Bq*NCx)          // 154

// ---------------- scratch (static device memory; allocation-free) ----------------
__device__ float g_h[(size_t)MROWS*Dm];
__device__ float g_q[(size_t)MROWS*Dm];
__device__ float g_k[(size_t)MROWS*Dm];
__device__ float g_v[(size_t)MROWS*Dm];
__device__ float g_att[(size_t)MROWS*Dm];
__device__ float g_s[(size_t)Bq*Hh*SEQ*NCx];      // cross scores (~20MB)
__device__ float g_p[(size_t)MROWS*2*FFd];        // 128 MB
__device__ float g_t[(size_t)MROWS*FFd];          // 64 MB
__device__ float g_w[(size_t)18874368];           // tf32-rounded weights (75.5 MB)

// offsets into g_w
#define OW1Q 0
#define OW1K 1048576
#define OW1V 2097152
#define OW1O 3145728
#define OW2Q 4194304
#define OW2O 5242880
#define OFW1 6291456
#define OFW2 14680064

// ---------------- helpers ----------------
__device__ __forceinline__ uint32_t f2tf32(float f) {
    uint32_t u;
    asm("cvt.rna.tf32.f32 %0, %1;" : "=r"(u) : "f"(f));
    return u;
}
__device__ __forceinline__ float rnaf(float f) { return __uint_as_float(f2tf32(f)); }
__device__ __forceinline__ float ex2f(float x) {
    float y;
    asm("ex2.approx.f32 %0, %1;" : "=f"(y) : "f"(x));
    return y;
}
__device__ __forceinline__ void mma_tf32(float c[4],
                                         uint32_t a0, uint32_t a1, uint32_t a2, uint32_t a3,
                                         uint32_t b0, uint32_t b1) {
    asm volatile(
        "mma.sync.aligned.m16n8k8.row.col.f32.tf32.tf32.f32 "
        "{%0,%1,%2,%3}, {%4,%5,%6,%7}, {%8,%9}, {%0,%1,%2,%3};"
        : "+f"(c[0]), "+f"(c[1]), "+f"(c[2]), "+f"(c[3])
        : "r"(a0), "r"(a1), "r"(a2), "r"(a3), "r"(b0), "r"(b1));
}
__device__ __forceinline__ void cpa16(uint32_t dst, const void* src) {
    asm volatile("cp.async.cg.shared.global [%0], [%1], 16;" :: "r"(dst), "l"(src));
}
#define CP_COMMIT() asm volatile("cp.async.commit_group;")
#define CP_WAIT1()  asm volatile("cp.async.wait_group 1;")

// ---------------- weight pre-round: dst = rna_tf32(src) ----------------
__global__ void round_kernel(const float* __restrict__ src, float* __restrict__ dst, int n4) {
    int i = blockIdx.x * blockDim.x + threadIdx.x;
    if (i < n4) {
        float4 v = reinterpret_cast<const float4*>(src)[i];
        v.x = rnaf(v.x); v.y = rnaf(v.y); v.z = rnaf(v.z); v.w = rnaf(v.w);
        reinterpret_cast<float4*>(dst)[i] = v;
    }
}

// ================= fast dense GEMM (NN, exact 128-multiples) =================
// C = A(MxK)*B(KxN) [+bias] [+res], row-major. BM=BN=128, BK=32.
// 256 threads, 8 warps (2x4), 64x32 per warp. 3-stage cp.async pipeline, 2 CTA/SM.
#define ASTR 36
#define BSTR 132
#define ABUF (128*ASTR)
#define BBUF (32*BSTR)
#define GF_SMEM ((3*(ABUF + BBUF))*4)

__global__ __launch_bounds__(256, 2)
void gemm_fast(const float* __restrict__ A, const float* __restrict__ B,
               const float* __restrict__ bias, const float* __restrict__ res,
               float* __restrict__ C, int M, int N, int K) {
    extern __shared__ float sm[];
    float* As = sm;
    float* Bs = sm + 3*ABUF;
    int bm = blockIdx.y * 128, bn = blockIdx.x * 128;
    int tid = threadIdx.x, warp = tid >> 5, lane = tid & 31;
    int grp = lane >> 2, tig = lane & 3;
    int wm = (warp >> 2) * 64, wn = (warp & 3) * 32;
    uint32_t sAu = (uint32_t)__cvta_generic_to_shared(As);
    uint32_t sBu = (uint32_t)__cvta_generic_to_shared(Bs);
    int niter = K >> 5;

    float acc[4][4][4] = {};

    auto loadTile = [&](int it, int buf) {
        int k0 = it * 32;
        const float* Ap = A + (size_t)bm * K + k0;
        #pragma unroll
        for (int i = 0; i < 4; i++) {
            int c = tid + i * 256;
            int r = c >> 3, kq = c & 7;
            cpa16(sAu + (uint32_t)(buf*ABUF + r*ASTR + kq*4) * 4,
                  Ap + (size_t)r * K + kq * 4);
        }
        const float* Bp = B + (size_t)k0 * N + bn;
        #pragma unroll
        for (int i = 0; i < 4; i++) {
            int c = tid + i * 256;
            int kr = c >> 5, nq = c & 31;
            cpa16(sBu + (uint32_t)(buf*BBUF + kr*BSTR + nq*4) * 4,
                  Bp + (size_t)kr * N + nq * 4);
        }
    };

    loadTile(0, 0); CP_COMMIT();
    loadTile(1, 1); CP_COMMIT();

    for (int it = 0; it < niter; ++it) {
        CP_WAIT1();
        __syncthreads();
        if (it + 2 < niter) { loadTile(it + 2, (it + 2) % 3); CP_COMMIT(); }
        else { CP_COMMIT(); }   // empty group keeps wait-count invariant

        const float* Ab = As + (it % 3) * ABUF;
        const float* Bb = Bs + (it % 3) * BBUF;
        #pragma unroll
        for (int ks = 0; ks < 32; ks += 8) {
            uint32_t af[4][4], bf[4][2];
            #pragma unroll
            for (int mf = 0; mf < 4; mf++) {
                const float* p = Ab + (wm + mf*16 + grp) * ASTR;
                af[mf][0] = __float_as_uint(p[ks + tig]);
                af[mf][1] = __float_as_uint(p[8*ASTR + ks + tig]);
                af[mf][2] = __float_as_uint(p[ks + tig + 4]);
                af[mf][3] = __float_as_uint(p[8*ASTR + ks + tig + 4]);
            }
            #pragma unroll
            for (int nf = 0; nf < 4; nf++) {
                int n = wn + nf*8 + grp;
                bf[nf][0] = __float_as_uint(Bb[(ks + tig    ) * BSTR + n]);
                bf[nf][1] = __float_as_uint(Bb[(ks + tig + 4) * BSTR + n]);
            }
            #pragma unroll
            for (int mf = 0; mf < 4; mf++)
                #pragma unroll
                for (int nf = 0; nf < 4; nf++)
                    mma_tf32(acc[mf][nf], af[mf][0], af[mf][1], af[mf][2], af[mf][3],
                             bf[nf][0], bf[nf][1]);
        }
    }

    // epilogue
    #pragma unroll
    for (int mf = 0; mf < 4; mf++) {
        #pragma unroll
        for (int nf = 0; nf < 4; nf++) {
            int r = bm + wm + mf*16 + grp;
            int c = bn + wn + nf*8 + tig*2;
            float2 v0 = make_float2(acc[mf][nf][0], acc[mf][nf][1]);
            float2 v1 = make_float2(acc[mf][nf][2], acc[mf][nf][3]);
            if (bias) {
                float2 bb = *(const float2*)(bias + c);
                v0.x += bb.x; v0.y += bb.y; v1.x += bb.x; v1.y += bb.y;
            }
            if (res) {
                float2 r0 = *(const float2*)(res + (size_t)r * N + c);
                float2 r1 = *(const float2*)(res + (size_t)(r+8) * N + c);
                v0.x += r0.x; v0.y += r0.y; v1.x += r1.x; v1.y += r1.y;
            }
            *(float2*)(C + (size_t)r * N + c) = v0;
            *(float2*)(C + (size_t)(r+8) * N + c) = v1;
        }
    }
}

// ================= flash attention (self-attn, DH=64, 128x128 tiles) =========
#define QSTR 68
#define PSTR 132
#define FL_SMEM ((3*128*QSTR + 128*PSTR)*4)

__global__ __launch_bounds__(256, 1)
void flash_attn(const float* __restrict__ q, const float* __restrict__ k,
                const float* __restrict__ v, float* __restrict__ o) {
    extern __shared__ float sm[];
    float* Qs = sm;
    float* Ks = sm + 128*QSTR;
    float* Vs = sm + 2*128*QSTR;
    float* Ps = sm + 3*128*QSTR;

    int qt = blockIdx.x, bh = blockIdx.y;
    int b = bh >> 4, h = bh & 15;
    int tid = threadIdx.x, warp = tid >> 5, lane = tid & 31;
    int grp = lane >> 2, tig = lane & 3;

    const float* qb = q + ((size_t)b*SEQ + qt*128) * Dm + h*DHd;
    const float* kb = k + (size_t)b*SEQ*Dm + h*DHd;
    const float* vb = v + (size_t)b*SEQ*Dm + h*DHd;

    {
        int row = tid >> 1, c0 = (tid & 1) * 32;
        const float4* src = (const float4*)(qb + (size_t)row * Dm + c0);
        float* dst = Qs + row*QSTR + c0;
        #pragma unroll
        for (int i = 0; i < 8; i++) {
            float4 t4 = src[i];
            dst[i*4+0] = rnaf(t4.x);
            dst[i*4+1] = rnaf(t4.y);
            dst[i*4+2] = rnaf(t4.z);
            dst[i*4+3] = rnaf(t4.w);
        }
    }
    __syncthreads();

    uint32_t qf[8][4];
    {
        const float* p = Qs + (warp*16 + grp) * QSTR;
        #pragma unroll
        for (int d0 = 0; d0 < 8; d0++) {
            qf[d0][0] = __float_as_uint(p[d0*8 + tig]);
            qf[d0][1] = __float_as_uint(p[8*QSTR + d0*8 + tig]);
            qf[d0][2] = __float_as_uint(p[d0*8 + tig + 4]);
            qf[d0][3] = __float_as_uint(p[8*QSTR + d0*8 + tig + 4]);
        }
    }

    float oacc[8][4] = {};
    float m0 = -1e30f, m1 = -1e30f, l0 = 0.f, l1 = 0.f;
    const float Csc = SCALE_ATTN * 1.4426950408889634f;
    int prow = warp*16 + grp;

    for (int kv0 = 0; kv0 < SEQ; kv0 += 128) {
        {
            int row = tid >> 1, c0 = (tid & 1) * 32;
            const float4* ksrc = (const float4*)(kb + (size_t)(kv0+row) * Dm + c0);
            const float4* vsrc = (const float4*)(vb + (size_t)(kv0+row) * Dm + c0);
            float* kd = Ks + row*QSTR + c0;
            float* vd = Vs + row*QSTR + c0;
            #pragma unroll
            for (int i = 0; i < 8; i++) {
                float4 t4 = ksrc[i];
                kd[i*4+0] = rnaf(t4.x);
                kd[i*4+1] = rnaf(t4.y);
                kd[i*4+2] = rnaf(t4.z);
                kd[i*4+3] = rnaf(t4.w);
                float4 u4 = vsrc[i];
                vd[i*4+0] = rnaf(u4.x);
                vd[i*4+1] = rnaf(u4.y);
                vd[i*4+2] = rnaf(u4.z);
                vd[i*4+3] = rnaf(u4.w);
            }
        }
        __syncthreads();

        float sacc[16][4] = {};
        #pragma unroll
        for (int d0 = 0; d0 < 8; d0++) {
            #pragma unroll
            for (int nf = 0; nf < 16; nf++) {
                const float* kp = Ks + (nf*8 + grp) * QSTR + d0*8;
                uint32_t b0 = __float_as_uint(kp[tig]);
                uint32_t b1 = __float_as_uint(kp[tig + 4]);
                mma_tf32(sacc[nf], qf[d0][0], qf[d0][1], qf[d0][2], qf[d0][3], b0, b1);
            }
        }
        float mx0 = -1e30f, mx1 = -1e30f;
        #pragma unroll
        for (int nf = 0; nf < 16; nf++) {
            sacc[nf][0] *= Csc; sacc[nf][1] *= Csc; sacc[nf][2] *= Csc; sacc[nf][3] *= Csc;
            mx0 = fmaxf(mx0, fmaxf(sacc[nf][0], sacc[nf][1]));
            mx1 = fmaxf(mx1, fmaxf(sacc[nf][2], sacc[nf][3]));
        }
        mx0 = fmaxf(mx0, __shfl_xor_sync(0xffffffffu, mx0, 1));
        mx0 = fmaxf(mx0, __shfl_xor_sync(0xffffffffu, mx0, 2));
        mx1 = fmaxf(mx1, __shfl_xor_sync(0xffffffffu, mx1, 1));
        mx1 = fmaxf(mx1, __shfl_xor_sync(0xffffffffu, mx1, 2));
        float mn0 = fmaxf(m0, mx0), mn1 = fmaxf(m1, mx1);
        float sc0 = ex2f(m0 - mn0), sc1 = ex2f(m1 - mn1);
        float sum0 = 0.f, sum1 = 0.f;
        #pragma unroll
        for (int nf = 0; nf < 16; nf++) {
            float p0 = ex2f(sacc[nf][0] - mn0);
            float p1 = ex2f(sacc[nf][1] - mn0);
            float p2 = ex2f(sacc[nf][2] - mn1);
            float p3 = ex2f(sacc[nf][3] - mn1);
            sum0 += p0 + p1; sum1 += p2 + p3;
            int pc = nf*8 + tig*2;
            *(float2*)(Ps + prow*PSTR + pc) = make_float2(rnaf(p0), rnaf(p1));
            *(float2*)(Ps + (prow+8)*PSTR + pc) = make_float2(rnaf(p2), rnaf(p3));
        }
        sum0 += __shfl_xor_sync(0xffffffffu, sum0, 1);
        sum0 += __shfl_xor_sync(0xffffffffu, sum0, 2);
        sum1 += __shfl_xor_sync(0xffffffffu, sum1, 1);
        sum1 += __shfl_xor_sync(0xffffffffu, sum1, 2);
        l0 = l0 * sc0 + sum0;  l1 = l1 * sc1 + sum1;
        m0 = mn0;  m1 = mn1;
        #pragma unroll
        for (int nf = 0; nf < 8; nf++) {
            oacc[nf][0] *= sc0; oacc[nf][1] *= sc0;
            oacc[nf][2] *= sc1; oacc[nf][3] *= sc1;
        }
        __syncwarp();

        #pragma unroll
        for (int ks = 0; ks < 128; ks += 8) {
            uint32_t a0 = __float_as_uint(Ps[prow*PSTR + ks + tig]);
            uint32_t a1 = __float_as_uint(Ps[(prow+8)*PSTR + ks + tig]);
            uint32_t a2 = __float_as_uint(Ps[prow*PSTR + ks + tig + 4]);
            uint32_t a3 = __float_as_uint(Ps[(prow+8)*PSTR + ks + tig + 4]);
            #pragma unroll
            for (int nf = 0; nf < 8; nf++) {
                uint32_t b0 = __float_as_uint(Vs[(ks + tig    ) * QSTR + nf*8 + grp]);
                uint32_t b1 = __float_as_uint(Vs[(ks + tig + 4) * QSTR + nf*8 + grp]);
                mma_tf32(oacc[nf], a0, a1, a2, a3, b0, b1);
            }
        }
        __syncthreads();
    }

    float i0 = 1.f / l0, i1 = 1.f / l1;
    float* ob = o + ((size_t)b*SEQ + qt*128 + warp*16) * Dm + h*DHd;
    #pragma unroll
    for (int nf = 0; nf < 8; nf++) {
        int c = nf*8 + tig*2;
        *(float2*)(ob + (size_t)grp * Dm + c) =
            make_float2(rnaf(oacc[nf][0]*i0), rnaf(oacc[nf][1]*i0));
        *(float2*)(ob + (size_t)(grp+8) * Dm + c) =
            make_float2(rnaf(oacc[nf][2]*i1), rnaf(oacc[nf][3]*i1));
    }
}

// ================= batched mma GEMM (cross-attn) ============
#define SM_STRIDE 136
template<bool TRANSB>
__global__ __launch_bounds__(256)
void mma_gemm(const float* __restrict__ A, const float* __restrict__ B,
              const float* __restrict__ bias, const float* __restrict__ res,
              float* __restrict__ C,
              int M, int N, int K, int lda, int ldb, int ldc,
              long sAb, long sAh, long sBb, long sBh, long sCb, long sCh,
              int zdiv, float scale) {
    __shared__ uint32_t As[32][SM_STRIDE];
    __shared__ uint32_t Bs[32][SM_STRIDE];
    int z = blockIdx.z;
    const float* Ab = A + (size_t)(z / zdiv) * sAb + (size_t)(z % zdiv) * sAh;
    const float* Bb = B + (size_t)(z / zdiv) * sBb + (size_t)(z % zdiv) * sBh;
    float*       Cb = C + (size_t)(z / zdiv) * sCb + (size_t)(z % zdiv) * sCh;
    int bm = blockIdx.y * 128, bn = blockIdx.x * 128;
    int tid = threadIdx.x;
    int warp = tid >> 5, lane = tid & 31;
    int grp = lane >> 2, tig = lane & 3;
    int wm = (warp >> 2) * 64;
    int wn = (warp & 3) * 32;
    float acc[4][4][4] = {};
    bool ldaVec = ((lda & 3) == 0);
    bool ldbVec = ((ldb & 3) == 0);
    for (int k0 = 0; k0 < K; k0 += 32) {
        if (k0 + 32 <= K && ldaVec) {
            int kq = tid & 7, r0 = tid >> 3;
            #pragma unroll
            for (int stp = 0; stp < 4; stp++) {
                int row = r0 + stp * 32;
                float4 v = make_float4(0.f, 0.f, 0.f, 0.f);
                if (bm + row < M)
                    v = *reinterpret_cast<const float4*>(Ab + (size_t)(bm + row) * lda + k0 + kq * 4);
                As[kq*4+0][row] = f2tf32(v.x);
                As[kq*4+1][row] = f2tf32(v.y);
                As[kq*4+2][row] = f2tf32(v.z);
                As[kq*4+3][row] = f2tf32(v.w);
            }
        } else {
            for (int idx = tid; idx < 128 * 32; idx += 256) {
                int m = idx >> 5, kk = idx & 31;
                float v = (bm + m < M && k0 + kk < K)
                          ? Ab[(size_t)(bm + m) * lda + k0 + kk] : 0.f;
                As[kk][m] = f2tf32(v);
            }
        }
        if (TRANSB) {
            if (k0 + 32 <= K && ldbVec) {
                int kq = tid & 7, n0 = tid >> 3;
                #pragma unroll
                for (int stp = 0; stp < 4; stp++) {
                    int n = n0 + stp * 32;
                    float4 v = make_float4(0.f, 0.f, 0.f, 0.f);
                    if (bn + n < N)
                        v = *reinterpret_cast<const float4*>(Bb + (size_t)(bn + n) * ldb + k0 + kq * 4);
                    Bs[kq*4+0][n] = f2tf32(v.x);
                    Bs[kq*4+1][n] = f2tf32(v.y);
                    Bs[kq*4+2][n] = f2tf32(v.z);
                    Bs[kq*4+3][n] = f2tf32(v.w);
                }
            } else {
                for (int idx = tid; idx < 128 * 32; idx += 256) {
                    int kk = idx & 31, n = idx >> 5;
                    float v = (bn + n < N && k0 + kk < K)
                              ? Bb[(size_t)(bn + n) * ldb + k0 + kk] : 0.f;
                    Bs[kk][n] = f2tf32(v);
                }
            }
        } else {
            if (k0 + 32 <= K && bn + 128 <= N && ldbVec) {
                int n4 = tid & 31, kr0 = tid >> 5;
                #pragma unroll
                for (int stp = 0; stp < 4; stp++) {
                    int kk = kr0 + stp * 8;
                    float4 v = *reinterpret_cast<const float4*>(Bb + (size_t)(k0 + kk) * ldb + bn + n4 * 4);
                    Bs[kk][n4*4+0] = f2tf32(v.x);
                    Bs[kk][n4*4+1] = f2tf32(v.y);
                    Bs[kk][n4*4+2] = f2tf32(v.z);
                    Bs[kk][n4*4+3] = f2tf32(v.w);
                }
            } else {
                for (int idx = tid; idx < 128 * 32; idx += 256) {
                    int n = idx & 127, kk = idx >> 7;
                    float v = (k0 + kk < K && bn + n < N)
                              ? Bb[(size_t)(k0 + kk) * ldb + bn + n] : 0.f;
                    Bs[kk][n] = f2tf32(v);
                }
            }
        }
        __syncthreads();
        #pragma unroll
        for (int ks = 0; ks < 32; ks += 8) {
            uint32_t a[4][4], b[4][2];
            #pragma unroll
            for (int mf = 0; mf < 4; mf++) {
                int m = wm + mf * 16 + grp;
                a[mf][0] = As[ks + tig    ][m];
                a[mf][1] = As[ks + tig    ][m + 8];
                a[mf][2] = As[ks + tig + 4][m];
                a[mf][3] = As[ks + tig + 4][m + 8];
            }
            #pragma unroll
            for (int nf = 0; nf < 4; nf++) {
                int n = wn + nf * 8 + grp;
                b[nf][0] = Bs[ks + tig    ][n];
                b[nf][1] = Bs[ks + tig + 4][n];
            }
            #pragma unroll
            for (int mf = 0; mf < 4; mf++)
                #pragma unroll
                for (int nf = 0; nf < 4; nf++)
                    mma_tf32(acc[mf][nf], a[mf][0], a[mf][1], a[mf][2], a[mf][3],
                             b[nf][0], b[nf][1]);
        }
        __syncthreads();
    }
    #pragma unroll
    for (int mf = 0; mf < 4; mf++) {
        #pragma unroll
        for (int nf = 0; nf < 4; nf++) {
            int r0 = bm + wm + mf * 16 + grp;
            int c0 = bn + wn + nf * 8 + tig * 2;
            #pragma unroll
            for (int e = 0; e < 4; e++) {
                int r = r0 + (e >> 1) * 8;
                int c = c0 + (e & 1);
                if (r < M && c < N) {
                    float v = acc[mf][nf][e] * scale;
                    if (bias) v += bias[c];
                    if (res)  v += res[(size_t)r * ldc + c];
                    Cb[(size_t)r * ldc + c] = v;
                }
            }
        }
    }
}

// ---------------- elementwise copy ----------------
__global__ void copy_kernel(const float* __restrict__ src, float* __restrict__ dst, int n4) {
    int i = blockIdx.x * blockDim.x + threadIdx.x;
    if (i < n4)
        reinterpret_cast<float4*>(dst)[i] = reinterpret_cast<const float4*>(src)[i];
}

// ---------------- layernorm (out rounded to tf32-rna) ----------------
__global__ void ln_kernel(const float* __restrict__ x, const float* __restrict__ g,
                          const float* __restrict__ b, float* __restrict__ out) {
    int row = blockIdx.x;
    const float* xr = x + (size_t)row * Dm;
    float s = 0.f, ss = 0.f;
    for (int i = threadIdx.x; i < Dm; i += 256) {
        float v = xr[i];
        s += v; ss += v * v;
    }
    __shared__ float rs[256], rss[256];
    rs[threadIdx.x] = s; rss[threadIdx.x] = ss;
    __syncthreads();
    for (int st = 128; st > 0; st >>= 1) {
        if (threadIdx.x < st) { rs[threadIdx.x] += rs[threadIdx.x+st]; rss[threadIdx.x] += rss[threadIdx.x+st]; }
        __syncthreads();
    }
    float mu  = rs[0] * (1.0f / Dm);
    float var = rss[0] * (1.0f / Dm) - mu * mu;
    float inv = rsqrtf(var + EPS_LN);
    float* orow = out + (size_t)row * Dm;
    for (int i = threadIdx.x; i < Dm; i += 256)
        orow[i] = rnaf((xr[i] - mu) * inv * g[i] + b[i]);
}

// ---------------- fp32 fallback GEMM (tiny cross-KV proj) ----------------
__global__ void gemm_kernel(const float* __restrict__ A, const float* __restrict__ Bm,
                            const float* __restrict__ bias, const float* __restrict__ res,
                            float* __restrict__ C, int M, int K, int Nn) {
    __shared__ float As[64][17];
    __shared__ float Bs[16][64];
    int bm = blockIdx.y * 64, bn = blockIdx.x * 64;
    int tx = threadIdx.x & 15, ty = threadIdx.x >> 4;
    float acc[4][4] = {};
    for (int k0 = 0; k0 < K; k0 += 16) {
        #pragma unroll
        for (int i = 0; i < 4; i++) {
            int idx = threadIdx.x + i * 256;
            int r = idx >> 4, kk = idx & 15;
            int gr = bm + r;
            As[r][kk] = (gr < M) ? A[(size_t)gr * K + k0 + kk] : 0.f;
            int kb = idx >> 6, c = idx & 63;
            int gc = bn + c;
            Bs[kb][c] = (gc < Nn) ? Bm[(size_t)(k0 + kb) * Nn + gc] : 0.f;
        }
        __syncthreads();
        #pragma unroll
        for (int kk = 0; kk < 16; kk++) {
            float a[4], bb[4];
            #pragma unroll
            for (int i = 0; i < 4; i++) a[i]  = As[ty*4+i][kk];
            #pragma unroll
            for (int j = 0; j < 4; j++) bb[j] = Bs[kk][tx*4+j];
            #pragma unroll
            for (int i = 0; i < 4; i++)
                #pragma unroll
                for (int j = 0; j < 4; j++)
                    acc[i][j] += a[i] * bb[j];
        }
        __syncthreads();
    }
    #pragma unroll
    for (int i = 0; i < 4; i++) {
        int gr = bm + ty*4 + i;
        if (gr >= M) continue;
        #pragma unroll
        for (int j = 0; j < 4; j++) {
            int gc = bn + tx*4 + j;
            if (gc >= Nn) continue;
            float v = acc[i][j];
            if (bias) v += bias[gc];
            if (res)  v += res[(size_t)gr * Nn + gc];
            C[(size_t)gr * Nn + gc] = v;
        }
    }
}

// ---------------- row softmax ----------------
__global__ void softmax_kernel(float* __restrict__ s, int len) {
    float* r = s + (size_t)blockIdx.x * len;
    __shared__ float red[256];
    float mx = -3.4e38f;
    for (int i = threadIdx.x; i < len; i += 256) mx = fmaxf(mx, r[i]);
    red[threadIdx.x] = mx; __syncthreads();
    for (int st = 128; st > 0; st >>= 1) {
        if (threadIdx.x < st) red[threadIdx.x] = fmaxf(red[threadIdx.x], red[threadIdx.x+st]);
        __syncthreads();
    }
    mx = red[0];
    __syncthreads();
    float sum = 0.f;
    for (int i = threadIdx.x; i < len; i += 256) {
        float e = expf(r[i] - mx);
        r[i] = e;
        sum += e;
    }
    red[threadIdx.x] = sum; __syncthreads();
    for (int st = 128; st > 0; st >>= 1) {
        if (threadIdx.x < st) red[threadIdx.x] += red[threadIdx.x+st];
        __syncthreads();
    }
    float inv = 1.f / red[0];
    for (int i = threadIdx.x; i < len; i += 256) r[i] *= inv;
}

// ---------------- GEGLU (out rounded to tf32-rna) ----------------
__global__ void geglu_kernel(const float* __restrict__ p, float* __restrict__ t) {
    size_t idx = (size_t)blockIdx.x * blockDim.x + threadIdx.x;
    if (idx < (size_t)MROWS * FFd) {
        size_t row = idx / FFd, col = idx % FFd;
        float val  = p[row * (2*FFd) + col];
        float gate = p[row * (2*FFd) + FFd + col];
        float ge = 0.5f * gate * (1.f + erff(gate * 0.70710678118654752f));
        t[idx] = rnaf(val * ge);
    }
}

// ---------------- launch ----------------
extern "C" void kernel_launch(void* const* d_in, const int* in_sizes, int n_in,
                              void* d_out, int out_size) {
    const float* x      = (const float*)d_in[0];
    const float* ctx    = (const float*)d_in[1];
    const float* w1_q   = (const float*)d_in[2];
    const float* w1_k   = (const float*)d_in[3];
    const float* w1_v   = (const float*)d_in[4];
    const float* w1_o   = (const float*)d_in[5];
    const float* b1_o   = (const float*)d_in[6];
    const float* w2_q   = (const float*)d_in[7];
    const float* w2_k   = (const float*)d_in[8];
    const float* w2_v   = (const float*)d_in[9];
    const float* w2_o   = (const float*)d_in[10];
    const float* b2_o   = (const float*)d_in[11];
    const float* ln1_g  = (const float*)d_in[12];
    const float* ln1_b  = (const float*)d_in[13];
    const float* ln2_g  = (const float*)d_in[14];
    const float* ln2_b  = (const float*)d_in[15];
    const float* ln3_g  = (const float*)d_in[16];
    const float* ln3_b  = (const float*)d_in[17];
    const float* ff_w1  = (const float*)d_in[18];
    const float* ff_b1  = (const float*)d_in[19];
    const float* ff_w2  = (const float*)d_in[20];
    const float* ff_b2  = (const float*)d_in[21];
    float* xbuf = (float*)d_out;

    float *hB, *qB, *kB, *vB, *attB, *sB, *pB, *tB, *wB;
    cudaGetSymbolAddress((void**)&hB,   g_h);
    cudaGetSymbolAddress((void**)&qB,   g_q);
    cudaGetSymbolAddress((void**)&kB,   g_k);
    cudaGetSymbolAddress((void**)&vB,   g_v);
    cudaGetSymbolAddress((void**)&attB, g_att);
    cudaGetSymbolAddress((void**)&sB,   g_s);
    cudaGetSymbolAddress((void**)&pB,   g_p);
    cudaGetSymbolAddress((void**)&tB,   g_t);
    cudaGetSymbolAddress((void**)&wB,   g_w);

    cudaFuncSetAttribute(gemm_fast,  cudaFuncAttributeMaxDynamicSharedMemorySize, GF_SMEM);
    cudaFuncSetAttribute(flash_attn, cudaFuncAttributeMaxDynamicSharedMemorySize, FL_SMEM);

    dim3 gD(Dm/128, MROWS/128);             // 8 x 32
    dim3 gFF1(2*FFd/128, MROWS/128);        // 64 x 32
    dim3 gFlash(SEQ/128, Bq*Hh);            // 16 x 32
    dim3 gScoresCross(1, SEQ/128, Bq*Hh);
    dim3 gAVc(1, SEQ/128, Bq*Hh);

    // pre-round weights to tf32 (RNA) once per launch
    {
        int nD  = Dm*Dm/4;          // 262144 float4
        int nF1 = Dm*2*FFd/4;
        int nF2 = FFd*Dm/4;
        round_kernel<<<(nD+255)/256, 256>>>(w1_q, wB+OW1Q, nD);
        round_kernel<<<(nD+255)/256, 256>>>(w1_k, wB+OW1K, nD);
        round_kernel<<<(nD+255)/256, 256>>>(w1_v, wB+OW1V, nD);
        round_kernel<<<(nD+255)/256, 256>>>(w1_o, wB+OW1O, nD);
        round_kernel<<<(nD+255)/256, 256>>>(w2_q, wB+OW2Q, nD);
        round_kernel<<<(nD+255)/256, 256>>>(w2_o, wB+OW2O, nD);
        round_kernel<<<(nF1+255)/256, 256>>>(ff_w1, wB+OFW1, nF1);
        round_kernel<<<(nF2+255)/256, 256>>>(ff_w2, wB+OFW2, nF2);
    }

    copy_kernel<<<(MROWS*Dm/4 + 255)/256, 256>>>(x, xbuf, MROWS*Dm/4);

    // ---- self attention (flash) ----
    ln_kernel<<<MROWS, 256>>>(xbuf, ln1_g, ln1_b, hB);
    gemm_fast<<<gD, 256, GF_SMEM>>>(hB, wB+OW1Q, nullptr, nullptr, qB, MROWS, Dm, Dm);
    gemm_fast<<<gD, 256, GF_SMEM>>>(hB, wB+OW1K, nullptr, nullptr, kB, MROWS, Dm, Dm);
    gemm_fast<<<gD, 256, GF_SMEM>>>(hB, wB+OW1V, nullptr, nullptr, vB, MROWS, Dm, Dm);
    flash_attn<<<gFlash, 256, FL_SMEM>>>(qB, kB, vB, attB);
    gemm_fast<<<gD, 256, GF_SMEM>>>(attB, wB+OW1O, b1_o, xbuf, xbuf, MROWS, Dm, Dm);

    // ---- cross attention ----
    ln_kernel<<<MROWS, 256>>>(xbuf, ln2_g, ln2_b, hB);
    gemm_fast<<<gD, 256, GF_SMEM>>>(hB, wB+OW2Q, nullptr, nullptr, qB, MROWS, Dm, Dm);
    dim3 gKV(Dm/64, (CROWS+63)/64);
    gemm_kernel<<<gKV, 256>>>(ctx, w2_k, nullptr, nullptr, kB, CROWS, DCx, Dm);
    gemm_kernel<<<gKV, 256>>>(ctx, w2_v, nullptr, nullptr, vB, CROWS, DCx, Dm);
    mma_gemm<true><<<gScoresCross, 256>>>(qB, kB, nullptr, nullptr, sB,
                                 SEQ, NCx, DHd, Dm, Dm, NCx,
                                 (long)SEQ*Dm, DHd, (long)NCx*Dm, DHd,
                                 (long)Hh*SEQ*NCx, (long)SEQ*NCx, Hh, SCALE_ATTN);
    softmax_kernel<<<Bq*Hh*SEQ, 256>>>(sB, NCx);
    mma_gemm<false><<<gAVc, 256>>>(sB, vB, nullptr, nullptr, attB,
                                 SEQ, DHd, NCx, NCx, Dm, Dm,
                                 (long)Hh*SEQ*NCx, (long)SEQ*NCx, (long)NCx*Dm, DHd,
                                 (long)SEQ*Dm, DHd, Hh, 1.f);
    gemm_fast<<<gD, 256, GF_SMEM>>>(attB, wB+OW2O, b2_o, xbuf, xbuf, MROWS, Dm, Dm);

    // ---- GEGLU FFN ----
    ln_kernel<<<MROWS, 256>>>(xbuf, ln3_g, ln3_b, hB);
    gemm_fast<<<gFF1, 256, GF_SMEM>>>(hB, wB+OFW1, ff_b1, nullptr, pB, MROWS, 2*FFd, Dm);
    geglu_kernel<<<((size_t)MROWS*FFd + 255)/256, 256>>>(pB, tB);
    gemm_fast<<<gD, 256, GF_SMEM>>>(tB, wB+OFW2, ff_b2, xbuf, xbuf, MROWS, Dm, FFd);
}

// round 6
// speedup vs baseline: 1.6751x; 1.6751x over previous
#include <cuda_runtime.h>
#include <cuda_fp16.h>
#include <math.h>
#include <stdint.h>

#define Bq 2
#define SEQ 2048
#define Dm 1024
#define NCx 77
#define DCx 768
#define Hh 16
#define DHd 64
#define FFd 4096
#define SCALE_ATTN 0.125f
#define EPS_LN 1e-5f
#define MROWS (Bq*SEQ)          // 4096
#define CROWS (Bq*NCx)          // 154

// ---------------- scratch (static device memory; allocation-free) ----------------
__device__ __half g_hh[(size_t)MROWS*Dm];
__device__ __half g_qh[(size_t)MROWS*Dm];
__device__ __half g_kh[(size_t)MROWS*Dm];
__device__ __half g_vh[(size_t)MROWS*Dm];
__device__ __half g_atth[(size_t)MROWS*Dm];
__device__ __half g_ph[(size_t)MROWS*2*FFd];
__device__ __half g_th[(size_t)MROWS*FFd];
__device__ __half g_wh[(size_t)18874368];        // transposed half weights [N,K]
__device__ float  g_q[(size_t)MROWS*Dm];         // cross-attn fp32 path
__device__ float  g_k[(size_t)CROWS*Dm + 1024];
__device__ float  g_v[(size_t)CROWS*Dm + 1024];
__device__ float  g_att[(size_t)MROWS*Dm];
__device__ float  g_s[(size_t)Bq*Hh*SEQ*NCx];

// offsets (element counts) into g_wh
#define OW1Q 0
#define OW1K 1048576
#define OW1V 2097152
#define OW1O 3145728
#define OW2Q 4194304
#define OW2O 5242880
#define OFW1 6291456
#define OFW2 14680064

// ---------------- helpers ----------------
__device__ __forceinline__ uint32_t f2tf32(float f) {
    uint32_t u;
    asm("cvt.rna.tf32.f32 %0, %1;" : "=r"(u) : "f"(f));
    return u;
}
__device__ __forceinline__ float ex2f(float x) {
    float y;
    asm("ex2.approx.f32 %0, %1;" : "=f"(y) : "f"(x));
    return y;
}
__device__ __forceinline__ void mma_f16(float c[4],
                                        uint32_t a0, uint32_t a1, uint32_t a2, uint32_t a3,
                                        uint32_t b0, uint32_t b1) {
    asm volatile(
        "mma.sync.aligned.m16n8k16.row.col.f32.f16.f16.f32 "
        "{%0,%1,%2,%3}, {%4,%5,%6,%7}, {%8,%9}, {%0,%1,%2,%3};"
        : "+f"(c[0]), "+f"(c[1]), "+f"(c[2]), "+f"(c[3])
        : "r"(a0), "r"(a1), "r"(a2), "r"(a3), "r"(b0), "r"(b1));
}
__device__ __forceinline__ void mma_tf32(float c[4],
                                         uint32_t a0, uint32_t a1, uint32_t a2, uint32_t a3,
                                         uint32_t b0, uint32_t b1) {
    asm volatile(
        "mma.sync.aligned.m16n8k8.row.col.f32.tf32.tf32.f32 "
        "{%0,%1,%2,%3}, {%4,%5,%6,%7}, {%8,%9}, {%0,%1,%2,%3};"
        : "+f"(c[0]), "+f"(c[1]), "+f"(c[2]), "+f"(c[3])
        : "r"(a0), "r"(a1), "r"(a2), "r"(a3), "r"(b0), "r"(b1));
}
__device__ __forceinline__ void cpa16(uint32_t dst, const void* src) {
    asm volatile("cp.async.cg.shared.global [%0], [%1], 16;" :: "r"(dst), "l"(src));
}
#define CP_COMMIT() asm volatile("cp.async.commit_group;")
#define CP_WAIT1()  asm volatile("cp.async.wait_group 1;")

// ---------------- weight transpose + fp16 convert: dst[N,K] = h(src[K,N]^T) ----
__global__ void transpose_half(const float* __restrict__ src, __half* __restrict__ dst,
                               int K, int N) {
    __shared__ float t[32][33];
    int bx = blockIdx.x * 32;   // N block
    int by = blockIdx.y * 32;   // K block
    int x = bx + threadIdx.x;
    #pragma unroll
    for (int i = 0; i < 32; i += 8) {
        int y = by + threadIdx.y + i;
        t[threadIdx.y + i][threadIdx.x] = src[(size_t)y * N + x];
    }
    __syncthreads();
    int kx = by + threadIdx.x;
    #pragma unroll
    for (int i = 0; i < 32; i += 8) {
        int ny = bx + threadIdx.y + i;
        dst[(size_t)ny * K + kx] = __float2half(t[threadIdx.x][threadIdx.y + i]);
    }
}

// ================= fp16 dense GEMM ==========================================
// C[M,N] = A[M,K] * Bt[N,K]^T (+bias +res). halves in, fp32 accum.
// 128x128 block, BK=32, 256 threads (8 warps 2x4, 64x32 per warp),
// 3-stage cp.async pipeline, 2 CTAs/SM.
#define ASH 40                     // halfs per smem row (stride)
#define HTILE (128*ASH)            // halfs per tile
#define GH_SMEM (3*2*HTILE*2)      // bytes: 3 stages x (A+B) x 2B

template<bool HOUT>
__global__ __launch_bounds__(256, 2)
void gemm_h(const __half* __restrict__ A, const __half* __restrict__ Bt,
            const float* __restrict__ bias, const float* __restrict__ res,
            void* __restrict__ Cv, int M, int N, int K) {
    extern __shared__ __half smh[];
    __half* As = smh;
    __half* Bs = smh + 3*HTILE;
    int bm = blockIdx.y * 128, bn = blockIdx.x * 128;
    int tid = threadIdx.x, warp = tid >> 5, lane = tid & 31;
    int grp = lane >> 2, tig = lane & 3;
    int wm = (warp >> 2) * 64, wn = (warp & 3) * 32;
    uint32_t sAu = (uint32_t)__cvta_generic_to_shared(As);
    uint32_t sBu = (uint32_t)__cvta_generic_to_shared(Bs);
    int niter = K >> 5;

    float acc[4][4][4] = {};

    auto loadTile = [&](int it, int buf) {
        int k0 = it * 32;
        #pragma unroll
        for (int i = 0; i < 2; i++) {
            int c = tid + i * 256;
            int row = c >> 2, kq = c & 3;     // 128 rows x 4 16B-chunks
            cpa16(sAu + (uint32_t)(buf*HTILE + row*ASH + kq*8) * 2,
                  A + (size_t)(bm + row) * K + k0 + kq * 8);
            cpa16(sBu + (uint32_t)(buf*HTILE + row*ASH + kq*8) * 2,
                  Bt + (size_t)(bn + row) * K + k0 + kq * 8);
        }
        CP_COMMIT();
    };

    loadTile(0, 0);
    loadTile(1, 1);

    for (int it = 0; it < niter; ++it) {
        CP_WAIT1();
        __syncthreads();
        if (it + 2 < niter) loadTile(it + 2, (it + 2) % 3);
        else CP_COMMIT();   // keep wait-count invariant

        const __half* Ab = As + (it % 3) * HTILE;
        const __half* Bb = Bs + (it % 3) * HTILE;
        #pragma unroll
        for (int ks = 0; ks < 32; ks += 16) {
            uint32_t af[4][4], bf[4][2];
            #pragma unroll
            for (int mf = 0; mf < 4; mf++) {
                const __half* p = Ab + (wm + mf*16 + grp) * ASH + ks;
                af[mf][0] = *(const uint32_t*)(p + tig*2);
                af[mf][1] = *(const uint32_t*)(p + 8*ASH + tig*2);
                af[mf][2] = *(const uint32_t*)(p + tig*2 + 8);
                af[mf][3] = *(const uint32_t*)(p + 8*ASH + tig*2 + 8);
            }
            #pragma unroll
            for (int nf = 0; nf < 4; nf++) {
                const __half* p = Bb + (wn + nf*8 + grp) * ASH + ks;
                bf[nf][0] = *(const uint32_t*)(p + tig*2);
                bf[nf][1] = *(const uint32_t*)(p + tig*2 + 8);
            }
            #pragma unroll
            for (int mf = 0; mf < 4; mf++)
                #pragma unroll
                for (int nf = 0; nf < 4; nf++)
                    mma_f16(acc[mf][nf], af[mf][0], af[mf][1], af[mf][2], af[mf][3],
                            bf[nf][0], bf[nf][1]);
        }
    }

    // epilogue
    #pragma unroll
    for (int mf = 0; mf < 4; mf++) {
        #pragma unroll
        for (int nf = 0; nf < 4; nf++) {
            int r = bm + wm + mf*16 + grp;
            int c = bn + wn + nf*8 + tig*2;
            float2 v0 = make_float2(acc[mf][nf][0], acc[mf][nf][1]);
            float2 v1 = make_float2(acc[mf][nf][2], acc[mf][nf][3]);
            if (bias) {
                float2 bb = *(const float2*)(bias + c);
                v0.x += bb.x; v0.y += bb.y; v1.x += bb.x; v1.y += bb.y;
            }
            if (res) {
                float2 r0 = *(const float2*)(res + (size_t)r * N + c);
                float2 r1 = *(const float2*)(res + (size_t)(r+8) * N + c);
                v0.x += r0.x; v0.y += r0.y; v1.x += r1.x; v1.y += r1.y;
            }
            if (HOUT) {
                __half* C = (__half*)Cv;
                *(__half2*)(C + (size_t)r * N + c)     = __floats2half2_rn(v0.x, v0.y);
                *(__half2*)(C + (size_t)(r+8) * N + c) = __floats2half2_rn(v1.x, v1.y);
            } else {
                float* C = (float*)Cv;
                *(float2*)(C + (size_t)r * N + c)     = v0;
                *(float2*)(C + (size_t)(r+8) * N + c) = v1;
            }
        }
    }
}

// ================= fp16 flash attention (self-attn, DH=64, 128x128) =========
#define QSH 72
#define VSH 136
#define PSH 136
#define FLH_SMEM ((2*128*QSH + 64*VSH + 128*PSH)*2)

__global__ __launch_bounds__(256, 2)
void flash_h(const __half* __restrict__ q, const __half* __restrict__ k,
             const __half* __restrict__ v, __half* __restrict__ o) {
    extern __shared__ __half smf[];
    __half* Qs = smf;                        // [128][QSH]
    __half* Ks = Qs + 128*QSH;               // [128][QSH]
    __half* Vt = Ks + 128*QSH;               // [64][VSH] (transposed: [dh][kv])
    __half* Ps = Vt + 64*VSH;                // [128][PSH]

    int qt = blockIdx.x, bh = blockIdx.y;
    int b = bh >> 4, h = bh & 15;
    int tid = threadIdx.x, warp = tid >> 5, lane = tid & 31;
    int grp = lane >> 2, tig = lane & 3;

    const __half* qb = q + ((size_t)b*SEQ + qt*128) * Dm + h*DHd;
    const __half* kb = k + (size_t)b*SEQ*Dm + h*DHd;
    const __half* vb = v + (size_t)b*SEQ*Dm + h*DHd;

    // load Q tile
    {
        int row = tid >> 1, part = tid & 1;
        const float4* s4 = (const float4*)(qb + (size_t)row * Dm + part*32);
        float4* d4 = (float4*)(Qs + row*QSH + part*32);
        #pragma unroll
        for (int i = 0; i < 4; i++) d4[i] = s4[i];
    }
    __syncthreads();

    // Q fragments in registers (4 ksteps of k16 over DH=64)
    uint32_t qf[4][4];
    {
        const __half* p = Qs + (warp*16 + grp) * QSH;
        #pragma unroll
        for (int ksi = 0; ksi < 4; ksi++) {
            qf[ksi][0] = *(const uint32_t*)(p + ksi*16 + tig*2);
            qf[ksi][1] = *(const uint32_t*)(p + 8*QSH + ksi*16 + tig*2);
            qf[ksi][2] = *(const uint32_t*)(p + ksi*16 + tig*2 + 8);
            qf[ksi][3] = *(const uint32_t*)(p + 8*QSH + ksi*16 + tig*2 + 8);
        }
    }

    float oacc[8][4] = {};
    float m0 = -1e30f, m1 = -1e30f, l0 = 0.f, l1 = 0.f;
    const float Csc = SCALE_ATTN * 1.4426950408889634f;
    int prow = warp*16 + grp;

    for (int kv0 = 0; kv0 < SEQ; kv0 += 128) {
        // load K tile
        {
            int row = tid >> 1, part = tid & 1;
            const float4* s4 = (const float4*)(kb + (size_t)(kv0+row) * Dm + part*32);
            float4* d4 = (float4*)(Ks + row*QSH + part*32);
            #pragma unroll
            for (int i = 0; i < 4; i++) d4[i] = s4[i];
        }
        // load V tile transposed: Vt[d][kv]
        {
            int d = tid & 63;
            #pragma unroll
            for (int kvp = tid >> 6; kvp < 64; kvp += 4) {
                int kv = kvp * 2;
                __half v0 = vb[(size_t)(kv0 + kv)     * Dm + d];
                __half v1 = vb[(size_t)(kv0 + kv + 1) * Dm + d];
                *(__half2*)(Vt + d*VSH + kv) = __halves2half2(v0, v1);
            }
        }
        __syncthreads();

        // S = Q K^T (16x128 per warp)
        float sacc[16][4] = {};
        #pragma unroll
        for (int ksi = 0; ksi < 4; ksi++) {
            #pragma unroll
            for (int nf = 0; nf < 16; nf++) {
                const __half* kp = Ks + (nf*8 + grp) * QSH + ksi*16;
                uint32_t b0 = *(const uint32_t*)(kp + tig*2);
                uint32_t b1 = *(const uint32_t*)(kp + tig*2 + 8);
                mma_f16(sacc[nf], qf[ksi][0], qf[ksi][1], qf[ksi][2], qf[ksi][3], b0, b1);
            }
        }
        // online softmax (log2 domain)
        float mx0 = -1e30f, mx1 = -1e30f;
        #pragma unroll
        for (int nf = 0; nf < 16; nf++) {
            sacc[nf][0] *= Csc; sacc[nf][1] *= Csc; sacc[nf][2] *= Csc; sacc[nf][3] *= Csc;
            mx0 = fmaxf(mx0, fmaxf(sacc[nf][0], sacc[nf][1]));
            mx1 = fmaxf(mx1, fmaxf(sacc[nf][2], sacc[nf][3]));
        }
        mx0 = fmaxf(mx0, __shfl_xor_sync(0xffffffffu, mx0, 1));
        mx0 = fmaxf(mx0, __shfl_xor_sync(0xffffffffu, mx0, 2));
        mx1 = fmaxf(mx1, __shfl_xor_sync(0xffffffffu, mx1, 1));
        mx1 = fmaxf(mx1, __shfl_xor_sync(0xffffffffu, mx1, 2));
        float mn0 = fmaxf(m0, mx0), mn1 = fmaxf(m1, mx1);
        float sc0 = ex2f(m0 - mn0), sc1 = ex2f(m1 - mn1);
        float sum0 = 0.f, sum1 = 0.f;
        #pragma unroll
        for (int nf = 0; nf < 16; nf++) {
            float p0 = ex2f(sacc[nf][0] - mn0);
            float p1 = ex2f(sacc[nf][1] - mn0);
            float p2 = ex2f(sacc[nf][2] - mn1);
            float p3 = ex2f(sacc[nf][3] - mn1);
            sum0 += p0 + p1; sum1 += p2 + p3;
            int pc = nf*8 + tig*2;
            *(__half2*)(Ps + prow*PSH + pc)     = __floats2half2_rn(p0, p1);
            *(__half2*)(Ps + (prow+8)*PSH + pc) = __floats2half2_rn(p2, p3);
        }
        sum0 += __shfl_xor_sync(0xffffffffu, sum0, 1);
        sum0 += __shfl_xor_sync(0xffffffffu, sum0, 2);
        sum1 += __shfl_xor_sync(0xffffffffu, sum1, 1);
        sum1 += __shfl_xor_sync(0xffffffffu, sum1, 2);
        l0 = l0 * sc0 + sum0;  l1 = l1 * sc1 + sum1;
        m0 = mn0;  m1 = mn1;
        #pragma unroll
        for (int nf = 0; nf < 8; nf++) {
            oacc[nf][0] *= sc0; oacc[nf][1] *= sc0;
            oacc[nf][2] *= sc1; oacc[nf][3] *= sc1;
        }
        __syncwarp();

        // O += P V   (8 ksteps of k16 over kv=128, nf over dh=64)
        #pragma unroll
        for (int ks = 0; ks < 8; ks++) {
            const __half* pp = Ps + prow*PSH + ks*16;
            uint32_t a0 = *(const uint32_t*)(pp + tig*2);
            uint32_t a1 = *(const uint32_t*)(pp + 8*PSH + tig*2);
            uint32_t a2 = *(const uint32_t*)(pp + tig*2 + 8);
            uint32_t a3 = *(const uint32_t*)(pp + 8*PSH + tig*2 + 8);
            #pragma unroll
            for (int nf = 0; nf < 8; nf++) {
                const __half* vp = Vt + (nf*8 + grp) * VSH + ks*16;
                uint32_t b0 = *(const uint32_t*)(vp + tig*2);
                uint32_t b1 = *(const uint32_t*)(vp + tig*2 + 8);
                mma_f16(oacc[nf], a0, a1, a2, a3, b0, b1);
            }
        }
        __syncthreads();
    }

    float i0 = 1.f / l0, i1 = 1.f / l1;
    __half* ob = o + ((size_t)b*SEQ + qt*128 + warp*16) * Dm + h*DHd;
    #pragma unroll
    for (int nf = 0; nf < 8; nf++) {
        int c = nf*8 + tig*2;
        *(__half2*)(ob + (size_t)grp * Dm + c) =
            __floats2half2_rn(oacc[nf][0]*i0, oacc[nf][1]*i0);
        *(__half2*)(ob + (size_t)(grp+8) * Dm + c) =
            __floats2half2_rn(oacc[nf][2]*i1, oacc[nf][3]*i1);
    }
}

// ================= batched tf32 mma GEMM (cross-attn only) ==================
#define SM_STRIDE 136
template<bool TRANSB>
__global__ __launch_bounds__(256)
void mma_gemm(const float* __restrict__ A, const float* __restrict__ B,
              const float* __restrict__ bias, const float* __restrict__ res,
              float* __restrict__ C,
              int M, int N, int K, int lda, int ldb, int ldc,
              long sAb, long sAh, long sBb, long sBh, long sCb, long sCh,
              int zdiv, float scale) {
    __shared__ uint32_t As[32][SM_STRIDE];
    __shared__ uint32_t Bs[32][SM_STRIDE];
    int z = blockIdx.z;
    const float* Ab = A + (size_t)(z / zdiv) * sAb + (size_t)(z % zdiv) * sAh;
    const float* Bb = B + (size_t)(z / zdiv) * sBb + (size_t)(z % zdiv) * sBh;
    float*       Cb = C + (size_t)(z / zdiv) * sCb + (size_t)(z % zdiv) * sCh;
    int bm = blockIdx.y * 128, bn = blockIdx.x * 128;
    int tid = threadIdx.x;
    int warp = tid >> 5, lane = tid & 31;
    int grp = lane >> 2, tig = lane & 3;
    int wm = (warp >> 2) * 64;
    int wn = (warp & 3) * 32;
    float acc[4][4][4] = {};
    bool ldaVec = ((lda & 3) == 0);
    bool ldbVec = ((ldb & 3) == 0);
    for (int k0 = 0; k0 < K; k0 += 32) {
        if (k0 + 32 <= K && ldaVec) {
            int kq = tid & 7, r0 = tid >> 3;
            #pragma unroll
            for (int stp = 0; stp < 4; stp++) {
                int row = r0 + stp * 32;
                float4 v = make_float4(0.f, 0.f, 0.f, 0.f);
                if (bm + row < M)
                    v = *reinterpret_cast<const float4*>(Ab + (size_t)(bm + row) * lda + k0 + kq * 4);
                As[kq*4+0][row] = f2tf32(v.x);
                As[kq*4+1][row] = f2tf32(v.y);
                As[kq*4+2][row] = f2tf32(v.z);
                As[kq*4+3][row] = f2tf32(v.w);
            }
        } else {
            for (int idx = tid; idx < 128 * 32; idx += 256) {
                int m = idx >> 5, kk = idx & 31;
                float v = (bm + m < M && k0 + kk < K)
                          ? Ab[(size_t)(bm + m) * lda + k0 + kk] : 0.f;
                As[kk][m] = f2tf32(v);
            }
        }
        if (TRANSB) {
            if (k0 + 32 <= K && ldbVec) {
                int kq = tid & 7, n0 = tid >> 3;
                #pragma unroll
                for (int stp = 0; stp < 4; stp++) {
                    int n = n0 + stp * 32;
                    float4 v = make_float4(0.f, 0.f, 0.f, 0.f);
                    if (bn + n < N)
                        v = *reinterpret_cast<const float4*>(Bb + (size_t)(bn + n) * ldb + k0 + kq * 4);
                    Bs[kq*4+0][n] = f2tf32(v.x);
                    Bs[kq*4+1][n] = f2tf32(v.y);
                    Bs[kq*4+2][n] = f2tf32(v.z);
                    Bs[kq*4+3][n] = f2tf32(v.w);
                }
            } else {
                for (int idx = tid; idx < 128 * 32; idx += 256) {
                    int kk = idx & 31, n = idx >> 5;
                    float v = (bn + n < N && k0 + kk < K)
                              ? Bb[(size_t)(bn + n) * ldb + k0 + kk] : 0.f;
                    Bs[kk][n] = f2tf32(v);
                }
            }
        } else {
            if (k0 + 32 <= K && bn + 128 <= N && ldbVec) {
                int n4 = tid & 31, kr0 = tid >> 5;
                #pragma unroll
                for (int stp = 0; stp < 4; stp++) {
                    int kk = kr0 + stp * 8;
                    float4 v = *reinterpret_cast<const float4*>(Bb + (size_t)(k0 + kk) * ldb + bn + n4 * 4);
                    Bs[kk][n4*4+0] = f2tf32(v.x);
                    Bs[kk][n4*4+1] = f2tf32(v.y);
                    Bs[kk][n4*4+2] = f2tf32(v.z);
                    Bs[kk][n4*4+3] = f2tf32(v.w);
                }
            } else {
                for (int idx = tid; idx < 128 * 32; idx += 256) {
                    int n = idx & 127, kk = idx >> 7;
                    float v = (k0 + kk < K && bn + n < N)
                              ? Bb[(size_t)(k0 + kk) * ldb + bn + n] : 0.f;
                    Bs[kk][n] = f2tf32(v);
                }
            }
        }
        __syncthreads();
        #pragma unroll
        for (int ks = 0; ks < 32; ks += 8) {
            uint32_t a[4][4], b[4][2];
            #pragma unroll
            for (int mf = 0; mf < 4; mf++) {
                int m = wm + mf * 16 + grp;
                a[mf][0] = As[ks + tig    ][m];
                a[mf][1] = As[ks + tig    ][m + 8];
                a[mf][2] = As[ks + tig + 4][m];
                a[mf][3] = As[ks + tig + 4][m + 8];
            }
            #pragma unroll
            for (int nf = 0; nf < 4; nf++) {
                int n = wn + nf * 8 + grp;
                b[nf][0] = Bs[ks + tig    ][n];
                b[nf][1] = Bs[ks + tig + 4][n];
            }
            #pragma unroll
            for (int mf = 0; mf < 4; mf++)
                #pragma unroll
                for (int nf = 0; nf < 4; nf++)
                    mma_tf32(acc[mf][nf], a[mf][0], a[mf][1], a[mf][2], a[mf][3],
                             b[nf][0], b[nf][1]);
        }
        __syncthreads();
    }
    #pragma unroll
    for (int mf = 0; mf < 4; mf++) {
        #pragma unroll
        for (int nf = 0; nf < 4; nf++) {
            int r0 = bm + wm + mf * 16 + grp;
            int c0 = bn + wn + nf * 8 + tig * 2;
            #pragma unroll
            for (int e = 0; e < 4; e++) {
                int r = r0 + (e >> 1) * 8;
                int c = c0 + (e & 1);
                if (r < M && c < N) {
                    float v = acc[mf][nf][e] * scale;
                    if (bias) v += bias[c];
                    if (res)  v += res[(size_t)r * ldc + c];
                    Cb[(size_t)r * ldc + c] = v;
                }
            }
        }
    }
}

// ---------------- elementwise ----------------
__global__ void copy_kernel(const float* __restrict__ src, float* __restrict__ dst, int n4) {
    int i = blockIdx.x * blockDim.x + threadIdx.x;
    if (i < n4)
        reinterpret_cast<float4*>(dst)[i] = reinterpret_cast<const float4*>(src)[i];
}
__global__ void f2h_kernel(const float* __restrict__ src, __half* __restrict__ dst, int n2) {
    int i = blockIdx.x * blockDim.x + threadIdx.x;
    if (i < n2) {
        float2 v = reinterpret_cast<const float2*>(src)[i];
        reinterpret_cast<__half2*>(dst)[i] = __floats2half2_rn(v.x, v.y);
    }
}

// ---------------- layernorm (half out) ----------------
__global__ void ln_kernel(const float* __restrict__ x, const float* __restrict__ g,
                          const float* __restrict__ b, __half* __restrict__ out) {
    int row = blockIdx.x;
    const float* xr = x + (size_t)row * Dm;
    float s = 0.f, ss = 0.f;
    for (int i = threadIdx.x; i < Dm; i += 256) {
        float v = xr[i];
        s += v; ss += v * v;
    }
    __shared__ float rs[256], rss[256];
    rs[threadIdx.x] = s; rss[threadIdx.x] = ss;
    __syncthreads();
    for (int st = 128; st > 0; st >>= 1) {
        if (threadIdx.x < st) { rs[threadIdx.x] += rs[threadIdx.x+st]; rss[threadIdx.x] += rss[threadIdx.x+st]; }
        __syncthreads();
    }
    float mu  = rs[0] * (1.0f / Dm);
    float var = rss[0] * (1.0f / Dm) - mu * mu;
    float inv = rsqrtf(var + EPS_LN);
    __half* orow = out + (size_t)row * Dm;
    for (int i = threadIdx.x; i < Dm; i += 256)
        orow[i] = __float2half((xr[i] - mu) * inv * g[i] + b[i]);
}

// ---------------- fp32 fallback GEMM (tiny cross-KV proj) ----------------
__global__ void gemm_kernel(const float* __restrict__ A, const float* __restrict__ Bm,
                            const float* __restrict__ bias, const float* __restrict__ res,
                            float* __restrict__ C, int M, int K, int Nn) {
    __shared__ float As[64][17];
    __shared__ float Bs[16][64];
    int bm = blockIdx.y * 64, bn = blockIdx.x * 64;
    int tx = threadIdx.x & 15, ty = threadIdx.x >> 4;
    float acc[4][4] = {};
    for (int k0 = 0; k0 < K; k0 += 16) {
        #pragma unroll
        for (int i = 0; i < 4; i++) {
            int idx = threadIdx.x + i * 256;
            int r = idx >> 4, kk = idx & 15;
            int gr = bm + r;
            As[r][kk] = (gr < M) ? A[(size_t)gr * K + k0 + kk] : 0.f;
            int kb = idx >> 6, c = idx & 63;
            int gc = bn + c;
            Bs[kb][c] = (gc < Nn) ? Bm[(size_t)(k0 + kb) * Nn + gc] : 0.f;
        }
        __syncthreads();
        #pragma unroll
        for (int kk = 0; kk < 16; kk++) {
            float a[4], bb[4];
            #pragma unroll
            for (int i = 0; i < 4; i++) a[i]  = As[ty*4+i][kk];
            #pragma unroll
            for (int j = 0; j < 4; j++) bb[j] = Bs[kk][tx*4+j];
            #pragma unroll
            for (int i = 0; i < 4; i++)
                #pragma unroll
                for (int j = 0; j < 4; j++)
                    acc[i][j] += a[i] * bb[j];
        }
        __syncthreads();
    }
    #pragma unroll
    for (int i = 0; i < 4; i++) {
        int gr = bm + ty*4 + i;
        if (gr >= M) continue;
        #pragma unroll
        for (int j = 0; j < 4; j++) {
            int gc = bn + tx*4 + j;
            if (gc >= Nn) continue;
            float v = acc[i][j];
            if (bias) v += bias[gc];
            if (res)  v += res[(size_t)gr * Nn + gc];
            C[(size_t)gr * Nn + gc] = v;
        }
    }
}

// ---------------- row softmax ----------------
__global__ void softmax_kernel(float* __restrict__ s, int len) {
    float* r = s + (size_t)blockIdx.x * len;
    __shared__ float red[256];
    float mx = -3.4e38f;
    for (int i = threadIdx.x; i < len; i += 256) mx = fmaxf(mx, r[i]);
    red[threadIdx.x] = mx; __syncthreads();
    for (int st = 128; st > 0; st >>= 1) {
        if (threadIdx.x < st) red[threadIdx.x] = fmaxf(red[threadIdx.x], red[threadIdx.x+st]);
        __syncthreads();
    }
    mx = red[0];
    __syncthreads();
    float sum = 0.f;
    for (int i = threadIdx.x; i < len; i += 256) {
        float e = expf(r[i] - mx);
        r[i] = e;
        sum += e;
    }
    red[threadIdx.x] = sum; __syncthreads();
    for (int st = 128; st > 0; st >>= 1) {
        if (threadIdx.x < st) red[threadIdx.x] += red[threadIdx.x+st];
        __syncthreads();
    }
    float inv = 1.f / red[0];
    for (int i = threadIdx.x; i < len; i += 256) r[i] *= inv;
}

// ---------------- GEGLU (half in, half out) ----------------
__global__ void geglu_h(const __half* __restrict__ p, __half* __restrict__ t) {
    size_t idx = (size_t)blockIdx.x * blockDim.x + threadIdx.x;
    if (idx < (size_t)MROWS * FFd) {
        size_t row = idx / FFd, col = idx % FFd;
        float val  = __half2float(p[row * (2*FFd) + col]);
        float gate = __half2float(p[row * (2*FFd) + FFd + col]);
        float ge = 0.5f * gate * (1.f + erff(gate * 0.70710678118654752f));
        t[idx] = __float2half(val * ge);
    }
}

// ---------------- launch ----------------
extern "C" void kernel_launch(void* const* d_in, const int* in_sizes, int n_in,
                              void* d_out, int out_size) {
    const float* x      = (const float*)d_in[0];
    const float* ctx    = (const float*)d_in[1];
    const float* w1_q   = (const float*)d_in[2];
    const float* w1_k   = (const float*)d_in[3];
    const float* w1_v   = (const float*)d_in[4];
    const float* w1_o   = (const float*)d_in[5];
    const float* b1_o   = (const float*)d_in[6];
    const float* w2_q   = (const float*)d_in[7];
    const float* w2_k   = (const float*)d_in[8];
    const float* w2_v   = (const float*)d_in[9];
    const float* w2_o   = (const float*)d_in[10];
    const float* b2_o   = (const float*)d_in[11];
    const float* ln1_g  = (const float*)d_in[12];
    const float* ln1_b  = (const float*)d_in[13];
    const float* ln2_g  = (const float*)d_in[14];
    const float* ln2_b  = (const float*)d_in[15];
    const float* ln3_g  = (const float*)d_in[16];
    const float* ln3_b  = (const float*)d_in[17];
    const float* ff_w1  = (const float*)d_in[18];
    const float* ff_b1  = (const float*)d_in[19];
    const float* ff_w2  = (const float*)d_in[20];
    const float* ff_b2  = (const float*)d_in[21];
    float* xbuf = (float*)d_out;

    __half *hh, *qh, *kh, *vh, *atth, *ph, *th, *wh;
    float *qB, *kB, *vB, *attB, *sB;
    cudaGetSymbolAddress((void**)&hh,   g_hh);
    cudaGetSymbolAddress((void**)&qh,   g_qh);
    cudaGetSymbolAddress((void**)&kh,   g_kh);
    cudaGetSymbolAddress((void**)&vh,   g_vh);
    cudaGetSymbolAddress((void**)&atth, g_atth);
    cudaGetSymbolAddress((void**)&ph,   g_ph);
    cudaGetSymbolAddress((void**)&th,   g_th);
    cudaGetSymbolAddress((void**)&wh,   g_wh);
    cudaGetSymbolAddress((void**)&qB,   g_q);
    cudaGetSymbolAddress((void**)&kB,   g_k);
    cudaGetSymbolAddress((void**)&vB,   g_v);
    cudaGetSymbolAddress((void**)&attB, g_att);
    cudaGetSymbolAddress((void**)&sB,   g_s);

    cudaFuncSetAttribute(gemm_h<true>,  cudaFuncAttributeMaxDynamicSharedMemorySize, GH_SMEM);
    cudaFuncSetAttribute(gemm_h<false>, cudaFuncAttributeMaxDynamicSharedMemorySize, GH_SMEM);
    cudaFuncSetAttribute(flash_h,       cudaFuncAttributeMaxDynamicSharedMemorySize, FLH_SMEM);

    dim3 gD(Dm/128, MROWS/128);             // 8 x 32
    dim3 gFF1(2*FFd/128, MROWS/128);        // 64 x 32
    dim3 gFlash(SEQ/128, Bq*Hh);            // 16 x 32
    dim3 gScoresCross(1, SEQ/128, Bq*Hh);
    dim3 gAVc(1, SEQ/128, Bq*Hh);
    dim3 tpb(32, 8);

    // weight transpose+convert to half [N,K] (once per launch)
    transpose_half<<<dim3(Dm/32,   Dm/32),  tpb>>>(w1_q,  wh+OW1Q, Dm,  Dm);
    transpose_half<<<dim3(Dm/32,   Dm/32),  tpb>>>(w1_k,  wh+OW1K, Dm,  Dm);
    transpose_half<<<dim3(Dm/32,   Dm/32),  tpb>>>(w1_v,  wh+OW1V, Dm,  Dm);
    transpose_half<<<dim3(Dm/32,   Dm/32),  tpb>>>(w1_o,  wh+OW1O, Dm,  Dm);
    transpose_half<<<dim3(Dm/32,   Dm/32),  tpb>>>(w2_q,  wh+OW2Q, Dm,  Dm);
    transpose_half<<<dim3(Dm/32,   Dm/32),  tpb>>>(w2_o,  wh+OW2O, Dm,  Dm);
    transpose_half<<<dim3(2*FFd/32, Dm/32), tpb>>>(ff_w1, wh+OFW1, Dm,  2*FFd);
    transpose_half<<<dim3(Dm/32,  FFd/32),  tpb>>>(ff_w2, wh+OFW2, FFd, Dm);

    copy_kernel<<<(MROWS*Dm/4 + 255)/256, 256>>>(x, xbuf, MROWS*Dm/4);

    // ---- self attention (fp16 flash) ----
    ln_kernel<<<MROWS, 256>>>(xbuf, ln1_g, ln1_b, hh);
    gemm_h<true><<<gD, 256, GH_SMEM>>>(hh, wh+OW1Q, nullptr, nullptr, qh, MROWS, Dm, Dm);
    gemm_h<true><<<gD, 256, GH_SMEM>>>(hh, wh+OW1K, nullptr, nullptr, kh, MROWS, Dm, Dm);
    gemm_h<true><<<gD, 256, GH_SMEM>>>(hh, wh+OW1V, nullptr, nullptr, vh, MROWS, Dm, Dm);
    flash_h<<<gFlash, 256, FLH_SMEM>>>(qh, kh, vh, atth);
    gemm_h<false><<<gD, 256, GH_SMEM>>>(atth, wh+OW1O, b1_o, xbuf, xbuf, MROWS, Dm, Dm);

    // ---- cross attention (fp32/tf32 path; nk=77 tiny) ----
    ln_kernel<<<MROWS, 256>>>(xbuf, ln2_g, ln2_b, hh);
    gemm_h<false><<<gD, 256, GH_SMEM>>>(hh, wh+OW2Q, nullptr, nullptr, qB, MROWS, Dm, Dm);
    dim3 gKV(Dm/64, (CROWS+63)/64);
    gemm_kernel<<<gKV, 256>>>(ctx, w2_k, nullptr, nullptr, kB, CROWS, DCx, Dm);
    gemm_kernel<<<gKV, 256>>>(ctx, w2_v, nullptr, nullptr, vB, CROWS, DCx, Dm);
    mma_gemm<true><<<gScoresCross, 256>>>(qB, kB, nullptr, nullptr, sB,
                                 SEQ, NCx, DHd, Dm, Dm, NCx,
                                 (long)SEQ*Dm, DHd, (long)NCx*Dm, DHd,
                                 (long)Hh*SEQ*NCx, (long)SEQ*NCx, Hh, SCALE_ATTN);
    softmax_kernel<<<Bq*Hh*SEQ, 256>>>(sB, NCx);
    mma_gemm<false><<<gAVc, 256>>>(sB, vB, nullptr, nullptr, attB,
                                 SEQ, DHd, NCx, NCx, Dm, Dm,
                                 (long)Hh*SEQ*NCx, (long)SEQ*NCx, (long)NCx*Dm, DHd,
                                 (long)SEQ*Dm, DHd, Hh, 1.f);
    f2h_kernel<<<(MROWS*Dm/2 + 255)/256, 256>>>(attB, atth, MROWS*Dm/2);
    gemm_h<false><<<gD, 256, GH_SMEM>>>(atth, wh+OW2O, b2_o, xbuf, xbuf, MROWS, Dm, Dm);

    // ---- GEGLU FFN ----
    ln_kernel<<<MROWS, 256>>>(xbuf, ln3_g, ln3_b, hh);
    gemm_h<true><<<gFF1, 256, GH_SMEM>>>(hh, wh+OFW1, ff_b1, nullptr, ph, MROWS, 2*FFd, Dm);
    geglu_h<<<((size_t)MROWS*FFd + 255)/256, 256>>>(ph, th);
    gemm_h<false><<<gD, 256, GH_SMEM>>>(th, wh+OFW2, ff_b2, xbuf, xbuf, MROWS, Dm, FFd);
}

// round 7
// speedup vs baseline: 1.9884x; 1.1870x over previous
#include <cuda_runtime.h>
#include <cuda_fp16.h>
#include <math.h>
#include <stdint.h>

#define Bq 2
#define SEQ 2048
#define Dm 1024
#define NCx 77
#define DCx 768
#define Hh 16
#define DHd 64
#define FFd 4096
#define SCALE_ATTN 0.125f
#define EPS_LN 1e-5f
#define MROWS (Bq*SEQ)          // 4096
#define CROWS (Bq*NCx)          // 154

// ---------------- scratch ----------------
__device__ __half g_hh[(size_t)MROWS*Dm];
__device__ __half g_qkv[(size_t)MROWS*3*Dm];
__device__ __half g_kh[(size_t)CROWS*Dm + 1024];
__device__ __half g_vh[(size_t)CROWS*Dm + 1024];
__device__ __half g_atth[(size_t)MROWS*Dm];
__device__ __half g_th[(size_t)MROWS*FFd];
__device__ __half g_wh[(size_t)18874368];        // transposed half weights [N,K]

// offsets (element counts) into g_wh
#define OWQKV 0
#define OW1O 3145728
#define OW2Q 4194304
#define OW2O 5242880
#define OFW1 6291456
#define OFW2 14680064

// ---------------- helpers ----------------
__device__ __forceinline__ float ex2f(float x) {
    float y;
    asm("ex2.approx.f32 %0, %1;" : "=f"(y) : "f"(x));
    return y;
}
__device__ __forceinline__ void mma_f16(float c[4],
                                        uint32_t a0, uint32_t a1, uint32_t a2, uint32_t a3,
                                        uint32_t b0, uint32_t b1) {
    asm volatile(
        "mma.sync.aligned.m16n8k16.row.col.f32.f16.f16.f32 "
        "{%0,%1,%2,%3}, {%4,%5,%6,%7}, {%8,%9}, {%0,%1,%2,%3};"
        : "+f"(c[0]), "+f"(c[1]), "+f"(c[2]), "+f"(c[3])
        : "r"(a0), "r"(a1), "r"(a2), "r"(a3), "r"(b0), "r"(b1));
}
__device__ __forceinline__ void cpa16(uint32_t dst, const void* src) {
    asm volatile("cp.async.cg.shared.global [%0], [%1], 16;" :: "r"(dst), "l"(src));
}
#define CP_COMMIT() asm volatile("cp.async.commit_group;")
#define CP_WAIT1()  asm volatile("cp.async.wait_group 1;")

// ---------------- weight transpose + fp16 convert: dst[N,K] = h(src[K,N]^T) ----
__global__ void transpose_half(const float* __restrict__ src, __half* __restrict__ dst,
                               int K, int N) {
    __shared__ float t[32][33];
    int bx = blockIdx.x * 32;   // N block
    int by = blockIdx.y * 32;   // K block
    int x = bx + threadIdx.x;
    #pragma unroll
    for (int i = 0; i < 32; i += 8) {
        int y = by + threadIdx.y + i;
        t[threadIdx.y + i][threadIdx.x] = src[(size_t)y * N + x];
    }
    __syncthreads();
    int kx = by + threadIdx.x;
    #pragma unroll
    for (int i = 0; i < 32; i += 8) {
        int ny = bx + threadIdx.y + i;
        dst[(size_t)ny * K + kx] = __float2half(t[threadIdx.x][threadIdx.y + i]);
    }
}
// GEGLU interleave: output row for original col n: n<FF ? 2n : 2(n-FF)+1
__global__ void transpose_geglu(const float* __restrict__ src, __half* __restrict__ dst,
                                int K, int N) {
    __shared__ float t[32][33];
    int bx = blockIdx.x * 32;
    int by = blockIdx.y * 32;
    int x = bx + threadIdx.x;
    #pragma unroll
    for (int i = 0; i < 32; i += 8) {
        int y = by + threadIdx.y + i;
        t[threadIdx.y + i][threadIdx.x] = src[(size_t)y * N + x];
    }
    __syncthreads();
    int kx = by + threadIdx.x;
    #pragma unroll
    for (int i = 0; i < 32; i += 8) {
        int ny = bx + threadIdx.y + i;
        int iny = (ny < FFd) ? (2*ny) : (2*(ny - FFd) + 1);
        dst[(size_t)iny * K + kx] = __float2half(t[threadIdx.x][threadIdx.y + i]);
    }
}

// ================= fp16 dense GEMM ==========================================
// MODE 0: fp32 out (+bias +res); MODE 1: half out (+bias); MODE 2: GEGLU fused
// (weights interleaved val/gate; writes half [M, N/2], bias = full ff_b1).
#define ASH 40
#define HTILE (128*ASH)
#define GH_SMEM (3*2*HTILE*2)

template<int MODE>
__global__ __launch_bounds__(256, 2)
void gemm_h(const __half* __restrict__ A, const __half* __restrict__ Bt,
            const float* __restrict__ bias, const float* __restrict__ res,
            void* __restrict__ Cv, int M, int N, int K) {
    extern __shared__ __half smh[];
    __half* As = smh;
    __half* Bs = smh + 3*HTILE;
    int bm = blockIdx.y * 128, bn = blockIdx.x * 128;
    int tid = threadIdx.x, warp = tid >> 5, lane = tid & 31;
    int grp = lane >> 2, tig = lane & 3;
    int wm = (warp >> 2) * 64, wn = (warp & 3) * 32;
    uint32_t sAu = (uint32_t)__cvta_generic_to_shared(As);
    uint32_t sBu = (uint32_t)__cvta_generic_to_shared(Bs);
    int niter = K >> 5;

    float acc[4][4][4] = {};

    auto loadTile = [&](int it, int buf) {
        int k0 = it * 32;
        #pragma unroll
        for (int i = 0; i < 2; i++) {
            int c = tid + i * 256;
            int row = c >> 2, kq = c & 3;
            cpa16(sAu + (uint32_t)(buf*HTILE + row*ASH + kq*8) * 2,
                  A + (size_t)(bm + row) * K + k0 + kq * 8);
            cpa16(sBu + (uint32_t)(buf*HTILE + row*ASH + kq*8) * 2,
                  Bt + (size_t)(bn + row) * K + k0 + kq * 8);
        }
        CP_COMMIT();
    };

    loadTile(0, 0);
    loadTile(1, 1);

    for (int it = 0; it < niter; ++it) {
        CP_WAIT1();
        __syncthreads();
        if (it + 2 < niter) loadTile(it + 2, (it + 2) % 3);
        else CP_COMMIT();

        const __half* Ab = As + (it % 3) * HTILE;
        const __half* Bb = Bs + (it % 3) * HTILE;
        #pragma unroll
        for (int ks = 0; ks < 32; ks += 16) {
            uint32_t af[4][4], bf[4][2];
            #pragma unroll
            for (int mf = 0; mf < 4; mf++) {
                const __half* p = Ab + (wm + mf*16 + grp) * ASH + ks;
                af[mf][0] = *(const uint32_t*)(p + tig*2);
                af[mf][1] = *(const uint32_t*)(p + 8*ASH + tig*2);
                af[mf][2] = *(const uint32_t*)(p + tig*2 + 8);
                af[mf][3] = *(const uint32_t*)(p + 8*ASH + tig*2 + 8);
            }
            #pragma unroll
            for (int nf = 0; nf < 4; nf++) {
                const __half* p = Bb + (wn + nf*8 + grp) * ASH + ks;
                bf[nf][0] = *(const uint32_t*)(p + tig*2);
                bf[nf][1] = *(const uint32_t*)(p + tig*2 + 8);
            }
            #pragma unroll
            for (int mf = 0; mf < 4; mf++)
                #pragma unroll
                for (int nf = 0; nf < 4; nf++)
                    mma_f16(acc[mf][nf], af[mf][0], af[mf][1], af[mf][2], af[mf][3],
                            bf[nf][0], bf[nf][1]);
        }
    }

    #pragma unroll
    for (int mf = 0; mf < 4; mf++) {
        #pragma unroll
        for (int nf = 0; nf < 4; nf++) {
            int r = bm + wm + mf*16 + grp;
            int c = bn + wn + nf*8 + tig*2;
            float2 v0 = make_float2(acc[mf][nf][0], acc[mf][nf][1]);
            float2 v1 = make_float2(acc[mf][nf][2], acc[mf][nf][3]);
            if (MODE == 2) {
                // interleaved (val, gate) pair; j = c/2
                int j = c >> 1;
                float bv = bias[j], bg = bias[FFd + j];
                float val0 = v0.x + bv, gat0 = v0.y + bg;
                float val1 = v1.x + bv, gat1 = v1.y + bg;
                float o0 = val0 * (0.5f * gat0 * (1.f + erff(gat0 * 0.70710678118654752f)));
                float o1 = val1 * (0.5f * gat1 * (1.f + erff(gat1 * 0.70710678118654752f)));
                __half* C = (__half*)Cv;
                C[(size_t)r * FFd + j]     = __float2half(o0);
                C[(size_t)(r+8) * FFd + j] = __float2half(o1);
            } else {
                if (bias) {
                    float2 bb = *(const float2*)(bias + c);
                    v0.x += bb.x; v0.y += bb.y; v1.x += bb.x; v1.y += bb.y;
                }
                if (MODE == 0 && res) {
                    float2 r0 = *(const float2*)(res + (size_t)r * N + c);
                    float2 r1 = *(const float2*)(res + (size_t)(r+8) * N + c);
                    v0.x += r0.x; v0.y += r0.y; v1.x += r1.x; v1.y += r1.y;
                }
                if (MODE == 1) {
                    __half* C = (__half*)Cv;
                    *(__half2*)(C + (size_t)r * N + c)     = __floats2half2_rn(v0.x, v0.y);
                    *(__half2*)(C + (size_t)(r+8) * N + c) = __floats2half2_rn(v1.x, v1.y);
                } else {
                    float* C = (float*)Cv;
                    *(float2*)(C + (size_t)r * N + c)     = v0;
                    *(float2*)(C + (size_t)(r+8) * N + c) = v1;
                }
            }
        }
    }
}

// ================= fp16 flash attention (self-attn, strided QKV) ============
#define QSH 72
#define VSH 136
#define PSH 136
#define FLH_SMEM ((2*128*QSH + 64*VSH + 128*PSH)*2)

__global__ __launch_bounds__(256, 2)
void flash_h(const __half* __restrict__ qkv, __half* __restrict__ o) {
    extern __shared__ __half smf[];
    __half* Qs = smf;
    __half* Ks = Qs + 128*QSH;
    __half* Vt = Ks + 128*QSH;
    __half* Ps = Vt + 64*VSH;

    const int ldq = 3*Dm;
    int qt = blockIdx.x, bh = blockIdx.y;
    int b = bh >> 4, h = bh & 15;
    int tid = threadIdx.x, warp = tid >> 5, lane = tid & 31;
    int grp = lane >> 2, tig = lane & 3;

    const __half* qb = qkv + ((size_t)b*SEQ + qt*128) * ldq + h*DHd;
    const __half* kb = qkv + (size_t)b*SEQ*ldq + Dm + h*DHd;
    const __half* vb = qkv + (size_t)b*SEQ*ldq + 2*Dm + h*DHd;

    {
        int row = tid >> 1, part = tid & 1;
        const float4* s4 = (const float4*)(qb + (size_t)row * ldq + part*32);
        float4* d4 = (float4*)(Qs + row*QSH + part*32);
        #pragma unroll
        for (int i = 0; i < 4; i++) d4[i] = s4[i];
    }
    __syncthreads();

    uint32_t qf[4][4];
    {
        const __half* p = Qs + (warp*16 + grp) * QSH;
        #pragma unroll
        for (int ksi = 0; ksi < 4; ksi++) {
            qf[ksi][0] = *(const uint32_t*)(p + ksi*16 + tig*2);
            qf[ksi][1] = *(const uint32_t*)(p + 8*QSH + ksi*16 + tig*2);
            qf[ksi][2] = *(const uint32_t*)(p + ksi*16 + tig*2 + 8);
            qf[ksi][3] = *(const uint32_t*)(p + 8*QSH + ksi*16 + tig*2 + 8);
        }
    }

    float oacc[8][4] = {};
    float m0 = -1e30f, m1 = -1e30f, l0 = 0.f, l1 = 0.f;
    const float Csc = SCALE_ATTN * 1.4426950408889634f;
    int prow = warp*16 + grp;

    for (int kv0 = 0; kv0 < SEQ; kv0 += 128) {
        {
            int row = tid >> 1, part = tid & 1;
            const float4* s4 = (const float4*)(kb + (size_t)(kv0+row) * ldq + part*32);
            float4* d4 = (float4*)(Ks + row*QSH + part*32);
            #pragma unroll
            for (int i = 0; i < 4; i++) d4[i] = s4[i];
        }
        {
            int d = tid & 63;
            #pragma unroll
            for (int kvp = tid >> 6; kvp < 64; kvp += 4) {
                int kv = kvp * 2;
                __half v0 = vb[(size_t)(kv0 + kv)     * ldq + d];
                __half v1 = vb[(size_t)(kv0 + kv + 1) * ldq + d];
                *(__half2*)(Vt + d*VSH + kv) = __halves2half2(v0, v1);
            }
        }
        __syncthreads();

        float sacc[16][4] = {};
        #pragma unroll
        for (int ksi = 0; ksi < 4; ksi++) {
            #pragma unroll
            for (int nf = 0; nf < 16; nf++) {
                const __half* kp = Ks + (nf*8 + grp) * QSH + ksi*16;
                uint32_t b0 = *(const uint32_t*)(kp + tig*2);
                uint32_t b1 = *(const uint32_t*)(kp + tig*2 + 8);
                mma_f16(sacc[nf], qf[ksi][0], qf[ksi][1], qf[ksi][2], qf[ksi][3], b0, b1);
            }
        }
        float mx0 = -1e30f, mx1 = -1e30f;
        #pragma unroll
        for (int nf = 0; nf < 16; nf++) {
            sacc[nf][0] *= Csc; sacc[nf][1] *= Csc; sacc[nf][2] *= Csc; sacc[nf][3] *= Csc;
            mx0 = fmaxf(mx0, fmaxf(sacc[nf][0], sacc[nf][1]));
            mx1 = fmaxf(mx1, fmaxf(sacc[nf][2], sacc[nf][3]));
        }
        mx0 = fmaxf(mx0, __shfl_xor_sync(0xffffffffu, mx0, 1));
        mx0 = fmaxf(mx0, __shfl_xor_sync(0xffffffffu, mx0, 2));
        mx1 = fmaxf(mx1, __shfl_xor_sync(0xffffffffu, mx1, 1));
        mx1 = fmaxf(mx1, __shfl_xor_sync(0xffffffffu, mx1, 2));
        float mn0 = fmaxf(m0, mx0), mn1 = fmaxf(m1, mx1);
        float sc0 = ex2f(m0 - mn0), sc1 = ex2f(m1 - mn1);
        float sum0 = 0.f, sum1 = 0.f;
        #pragma unroll
        for (int nf = 0; nf < 16; nf++) {
            float p0 = ex2f(sacc[nf][0] - mn0);
            float p1 = ex2f(sacc[nf][1] - mn0);
            float p2 = ex2f(sacc[nf][2] - mn1);
            float p3 = ex2f(sacc[nf][3] - mn1);
            sum0 += p0 + p1; sum1 += p2 + p3;
            int pc = nf*8 + tig*2;
            *(__half2*)(Ps + prow*PSH + pc)     = __floats2half2_rn(p0, p1);
            *(__half2*)(Ps + (prow+8)*PSH + pc) = __floats2half2_rn(p2, p3);
        }
        sum0 += __shfl_xor_sync(0xffffffffu, sum0, 1);
        sum0 += __shfl_xor_sync(0xffffffffu, sum0, 2);
        sum1 += __shfl_xor_sync(0xffffffffu, sum1, 1);
        sum1 += __shfl_xor_sync(0xffffffffu, sum1, 2);
        l0 = l0 * sc0 + sum0;  l1 = l1 * sc1 + sum1;
        m0 = mn0;  m1 = mn1;
        #pragma unroll
        for (int nf = 0; nf < 8; nf++) {
            oacc[nf][0] *= sc0; oacc[nf][1] *= sc0;
            oacc[nf][2] *= sc1; oacc[nf][3] *= sc1;
        }
        __syncwarp();

        #pragma unroll
        for (int ks = 0; ks < 8; ks++) {
            const __half* pp = Ps + prow*PSH + ks*16;
            uint32_t a0 = *(const uint32_t*)(pp + tig*2);
            uint32_t a1 = *(const uint32_t*)(pp + 8*PSH + tig*2);
            uint32_t a2 = *(const uint32_t*)(pp + tig*2 + 8);
            uint32_t a3 = *(const uint32_t*)(pp + 8*PSH + tig*2 + 8);
            #pragma unroll
            for (int nf = 0; nf < 8; nf++) {
                const __half* vp = Vt + (nf*8 + grp) * VSH + ks*16;
                uint32_t b0 = *(const uint32_t*)(vp + tig*2);
                uint32_t b1 = *(const uint32_t*)(vp + tig*2 + 8);
                mma_f16(oacc[nf], a0, a1, a2, a3, b0, b1);
            }
        }
        __syncthreads();
    }

    float i0 = 1.f / l0, i1 = 1.f / l1;
    __half* ob = o + ((size_t)b*SEQ + qt*128 + warp*16) * Dm + h*DHd;
    #pragma unroll
    for (int nf = 0; nf < 8; nf++) {
        int c = nf*8 + tig*2;
        *(__half2*)(ob + (size_t)grp * Dm + c) =
            __floats2half2_rn(oacc[nf][0]*i0, oacc[nf][1]*i0);
        *(__half2*)(ob + (size_t)(grp+8) * Dm + c) =
            __floats2half2_rn(oacc[nf][2]*i1, oacc[nf][3]*i1);
    }
}

// ================= fp16 cross-attention (single KV tile, nk=77) =============
#define CKROWS 80
#define CVSH 88
#define CPSH 88
#define FLC_SMEM ((128*QSH + CKROWS*QSH + 64*CVSH + 128*CPSH)*2)

__global__ __launch_bounds__(256, 2)
void flash_cross(const __half* __restrict__ q, const __half* __restrict__ k,
                 const __half* __restrict__ v, __half* __restrict__ o) {
    extern __shared__ __half smc[];
    __half* Qs = smc;                       // [128][QSH]
    __half* Ks = Qs + 128*QSH;              // [80][QSH]
    __half* Vt = Ks + CKROWS*QSH;           // [64][CVSH]
    __half* Ps = Vt + 64*CVSH;              // [128][CPSH]

    int qt = blockIdx.x, bh = blockIdx.y;
    int b = bh >> 4, h = bh & 15;
    int tid = threadIdx.x, warp = tid >> 5, lane = tid & 31;
    int grp = lane >> 2, tig = lane & 3;

    const __half* qb = q + ((size_t)b*SEQ + qt*128) * Dm + h*DHd;
    const __half* kb = k + (size_t)b*NCx*Dm + h*DHd;
    const __half* vb = v + (size_t)b*NCx*Dm + h*DHd;

    // Q tile
    {
        int row = tid >> 1, part = tid & 1;
        const float4* s4 = (const float4*)(qb + (size_t)row * Dm + part*32);
        float4* d4 = (float4*)(Qs + row*QSH + part*32);
        #pragma unroll
        for (int i = 0; i < 4; i++) d4[i] = s4[i];
    }
    // K tile (80 rows, zero-pad >=77)
    for (int rr = tid; rr < CKROWS*2; rr += 256) {
        int row = rr >> 1, part = rr & 1;
        float4* d4 = (float4*)(Ks + row*QSH + part*32);
        if (row < NCx) {
            const float4* s4 = (const float4*)(kb + (size_t)row * Dm + part*32);
            #pragma unroll
            for (int i = 0; i < 4; i++) d4[i] = s4[i];
        } else {
            float4 z = make_float4(0.f,0.f,0.f,0.f);
            #pragma unroll
            for (int i = 0; i < 4; i++) d4[i] = z;
        }
    }
    // V transposed [d][kv], zero-pad kv>=77
    {
        int d = tid & 63;
        for (int kvp = tid >> 6; kvp < CKROWS/2; kvp += 4) {
            int kv = kvp * 2;
            __half v0 = (kv   < NCx) ? vb[(size_t)kv     * Dm + d] : __half(0.f);
            __half v1 = (kv+1 < NCx) ? vb[(size_t)(kv+1) * Dm + d] : __half(0.f);
            *(__half2*)(Vt + d*CVSH + kv) = __halves2half2(v0, v1);
        }
    }
    __syncthreads();

    uint32_t qf[4][4];
    {
        const __half* p = Qs + (warp*16 + grp) * QSH;
        #pragma unroll
        for (int ksi = 0; ksi < 4; ksi++) {
            qf[ksi][0] = *(const uint32_t*)(p + ksi*16 + tig*2);
            qf[ksi][1] = *(const uint32_t*)(p + 8*QSH + ksi*16 + tig*2);
            qf[ksi][2] = *(const uint32_t*)(p + ksi*16 + tig*2 + 8);
            qf[ksi][3] = *(const uint32_t*)(p + 8*QSH + ksi*16 + tig*2 + 8);
        }
    }

    const float Csc = SCALE_ATTN * 1.4426950408889634f;
    int prow = warp*16 + grp;

    // S = Q K^T over 80 cols (10 nf groups)
    float sacc[10][4] = {};
    #pragma unroll
    for (int ksi = 0; ksi < 4; ksi++) {
        #pragma unroll
        for (int nf = 0; nf < 10; nf++) {
            const __half* kp = Ks + (nf*8 + grp) * QSH + ksi*16;
            uint32_t b0 = *(const uint32_t*)(kp + tig*2);
            uint32_t b1 = *(const uint32_t*)(kp + tig*2 + 8);
            mma_f16(sacc[nf], qf[ksi][0], qf[ksi][1], qf[ksi][2], qf[ksi][3], b0, b1);
        }
    }
    // scale + mask cols >= 77
    float mx0 = -1e30f, mx1 = -1e30f;
    #pragma unroll
    for (int nf = 0; nf < 10; nf++) {
        int c0 = nf*8 + tig*2, c1 = c0 + 1;
        sacc[nf][0] = (c0 < NCx) ? sacc[nf][0]*Csc : -1e30f;
        sacc[nf][1] = (c1 < NCx) ? sacc[nf][1]*Csc : -1e30f;
        sacc[nf][2] = (c0 < NCx) ? sacc[nf][2]*Csc : -1e30f;
        sacc[nf][3] = (c1 < NCx) ? sacc[nf][3]*Csc : -1e30f;
        mx0 = fmaxf(mx0, fmaxf(sacc[nf][0], sacc[nf][1]));
        mx1 = fmaxf(mx1, fmaxf(sacc[nf][2], sacc[nf][3]));
    }
    mx0 = fmaxf(mx0, __shfl_xor_sync(0xffffffffu, mx0, 1));
    mx0 = fmaxf(mx0, __shfl_xor_sync(0xffffffffu, mx0, 2));
    mx1 = fmaxf(mx1, __shfl_xor_sync(0xffffffffu, mx1, 1));
    mx1 = fmaxf(mx1, __shfl_xor_sync(0xffffffffu, mx1, 2));

    float sum0 = 0.f, sum1 = 0.f;
    #pragma unroll
    for (int nf = 0; nf < 10; nf++) {
        float p0 = ex2f(sacc[nf][0] - mx0);
        float p1 = ex2f(sacc[nf][1] - mx0);
        float p2 = ex2f(sacc[nf][2] - mx1);
        float p3 = ex2f(sacc[nf][3] - mx1);
        sum0 += p0 + p1; sum1 += p2 + p3;
        int pc = nf*8 + tig*2;
        *(__half2*)(Ps + prow*CPSH + pc)     = __floats2half2_rn(p0, p1);
        *(__half2*)(Ps + (prow+8)*CPSH + pc) = __floats2half2_rn(p2, p3);
    }
    sum0 += __shfl_xor_sync(0xffffffffu, sum0, 1);
    sum0 += __shfl_xor_sync(0xffffffffu, sum0, 2);
    sum1 += __shfl_xor_sync(0xffffffffu, sum1, 1);
    sum1 += __shfl_xor_sync(0xffffffffu, sum1, 2);
    __syncwarp();

    // O = P V (5 ksteps of 16 over 80 kv)
    float oacc[8][4] = {};
    #pragma unroll
    for (int ks = 0; ks < 5; ks++) {
        const __half* pp = Ps + prow*CPSH + ks*16;
        uint32_t a0 = *(const uint32_t*)(pp + tig*2);
        uint32_t a1 = *(const uint32_t*)(pp + 8*CPSH + tig*2);
        uint32_t a2 = *(const uint32_t*)(pp + tig*2 + 8);
        uint32_t a3 = *(const uint32_t*)(pp + 8*CPSH + tig*2 + 8);
        #pragma unroll
        for (int nf = 0; nf < 8; nf++) {
            const __half* vp = Vt + (nf*8 + grp) * CVSH + ks*16;
            uint32_t b0 = *(const uint32_t*)(vp + tig*2);
            uint32_t b1 = *(const uint32_t*)(vp + tig*2 + 8);
            mma_f16(oacc[nf], a0, a1, a2, a3, b0, b1);
        }
    }

    float i0 = 1.f / sum0, i1 = 1.f / sum1;
    __half* ob = o + ((size_t)b*SEQ + qt*128 + warp*16) * Dm + h*DHd;
    #pragma unroll
    for (int nf = 0; nf < 8; nf++) {
        int c = nf*8 + tig*2;
        *(__half2*)(ob + (size_t)grp * Dm + c) =
            __floats2half2_rn(oacc[nf][0]*i0, oacc[nf][1]*i0);
        *(__half2*)(ob + (size_t)(grp+8) * Dm + c) =
            __floats2half2_rn(oacc[nf][2]*i1, oacc[nf][3]*i1);
    }
}

// ---------------- elementwise / small kernels ----------------
__global__ void copy_kernel(const float* __restrict__ src, float* __restrict__ dst, int n4) {
    int i = blockIdx.x * blockDim.x + threadIdx.x;
    if (i < n4)
        reinterpret_cast<float4*>(dst)[i] = reinterpret_cast<const float4*>(src)[i];
}

__global__ void ln_kernel(const float* __restrict__ x, const float* __restrict__ g,
                          const float* __restrict__ b, __half* __restrict__ out) {
    int row = blockIdx.x;
    const float* xr = x + (size_t)row * Dm;
    float s = 0.f, ss = 0.f;
    for (int i = threadIdx.x; i < Dm; i += 256) {
        float v = xr[i];
        s += v; ss += v * v;
    }
    __shared__ float rs[256], rss[256];
    rs[threadIdx.x] = s; rss[threadIdx.x] = ss;
    __syncthreads();
    for (int st = 128; st > 0; st >>= 1) {
        if (threadIdx.x < st) { rs[threadIdx.x] += rs[threadIdx.x+st]; rss[threadIdx.x] += rss[threadIdx.x+st]; }
        __syncthreads();
    }
    float mu  = rs[0] * (1.0f / Dm);
    float var = rss[0] * (1.0f / Dm) - mu * mu;
    float inv = rsqrtf(var + EPS_LN);
    __half* orow = out + (size_t)row * Dm;
    for (int i = threadIdx.x; i < Dm; i += 256)
        orow[i] = __float2half((xr[i] - mu) * inv * g[i] + b[i]);
}

// fp32 in, half out small GEMM for cross KV projections
__global__ void gemm_kernel_h(const float* __restrict__ A, const float* __restrict__ Bm,
                              __half* __restrict__ C, int M, int K, int Nn) {
    __shared__ float As[64][17];
    __shared__ float Bs[16][64];
    int bm = blockIdx.y * 64, bn = blockIdx.x * 64;
    int tx = threadIdx.x & 15, ty = threadIdx.x >> 4;
    float acc[4][4] = {};
    for (int k0 = 0; k0 < K; k0 += 16) {
        #pragma unroll
        for (int i = 0; i < 4; i++) {
            int idx = threadIdx.x + i * 256;
            int r = idx >> 4, kk = idx & 15;
            int gr = bm + r;
            As[r][kk] = (gr < M) ? A[(size_t)gr * K + k0 + kk] : 0.f;
            int kb = idx >> 6, c = idx & 63;
            int gc = bn + c;
            Bs[kb][c] = (gc < Nn) ? Bm[(size_t)(k0 + kb) * Nn + gc] : 0.f;
        }
        __syncthreads();
        #pragma unroll
        for (int kk = 0; kk < 16; kk++) {
            float a[4], bb[4];
            #pragma unroll
            for (int i = 0; i < 4; i++) a[i]  = As[ty*4+i][kk];
            #pragma unroll
            for (int j = 0; j < 4; j++) bb[j] = Bs[kk][tx*4+j];
            #pragma unroll
            for (int i = 0; i < 4; i++)
                #pragma unroll
                for (int j = 0; j < 4; j++)
                    acc[i][j] += a[i] * bb[j];
        }
        __syncthreads();
    }
    #pragma unroll
    for (int i = 0; i < 4; i++) {
        int gr = bm + ty*4 + i;
        if (gr >= M) continue;
        #pragma unroll
        for (int j = 0; j < 4; j++) {
            int gc = bn + tx*4 + j;
            if (gc >= Nn) continue;
            C[(size_t)gr * Nn + gc] = __float2half(acc[i][j]);
        }
    }
}

// ---------------- launch ----------------
extern "C" void kernel_launch(void* const* d_in, const int* in_sizes, int n_in,
                              void* d_out, int out_size) {
    const float* x      = (const float*)d_in[0];
    const float* ctx    = (const float*)d_in[1];
    const float* w1_q   = (const float*)d_in[2];
    const float* w1_k   = (const float*)d_in[3];
    const float* w1_v   = (const float*)d_in[4];
    const float* w1_o   = (const float*)d_in[5];
    const float* b1_o   = (const float*)d_in[6];
    const float* w2_q   = (const float*)d_in[7];
    const float* w2_k   = (const float*)d_in[8];
    const float* w2_v   = (const float*)d_in[9];
    const float* w2_o   = (const float*)d_in[10];
    const float* b2_o   = (const float*)d_in[11];
    const float* ln1_g  = (const float*)d_in[12];
    const float* ln1_b  = (const float*)d_in[13];
    const float* ln2_g  = (const float*)d_in[14];
    const float* ln2_b  = (const float*)d_in[15];
    const float* ln3_g  = (const float*)d_in[16];
    const float* ln3_b  = (const float*)d_in[17];
    const float* ff_w1  = (const float*)d_in[18];
    const float* ff_b1  = (const float*)d_in[19];
    const float* ff_w2  = (const float*)d_in[20];
    const float* ff_b2  = (const float*)d_in[21];
    float* xbuf = (float*)d_out;

    __half *hh, *qkvh, *kh, *vh, *atth, *th, *wh;
    cudaGetSymbolAddress((void**)&hh,   g_hh);
    cudaGetSymbolAddress((void**)&qkvh, g_qkv);
    cudaGetSymbolAddress((void**)&kh,   g_kh);
    cudaGetSymbolAddress((void**)&vh,   g_vh);
    cudaGetSymbolAddress((void**)&atth, g_atth);
    cudaGetSymbolAddress((void**)&th,   g_th);
    cudaGetSymbolAddress((void**)&wh,   g_wh);

    cudaFuncSetAttribute(gemm_h<0>, cudaFuncAttributeMaxDynamicSharedMemorySize, GH_SMEM);
    cudaFuncSetAttribute(gemm_h<1>, cudaFuncAttributeMaxDynamicSharedMemorySize, GH_SMEM);
    cudaFuncSetAttribute(gemm_h<2>, cudaFuncAttributeMaxDynamicSharedMemorySize, GH_SMEM);
    cudaFuncSetAttribute(flash_h,     cudaFuncAttributeMaxDynamicSharedMemorySize, FLH_SMEM);
    cudaFuncSetAttribute(flash_cross, cudaFuncAttributeMaxDynamicSharedMemorySize, FLC_SMEM);

    dim3 gD(Dm/128, MROWS/128);
    dim3 gQKV(3*Dm/128, MROWS/128);
    dim3 gFF1(2*FFd/128, MROWS/128);
    dim3 gFlash(SEQ/128, Bq*Hh);
    dim3 tpb(32, 8);

    // weight transpose+convert (QKV packed; ff_w1 interleaved for GEGLU)
    transpose_half<<<dim3(Dm/32,   Dm/32),  tpb>>>(w1_q,  wh+OWQKV,             Dm,  Dm);
    transpose_half<<<dim3(Dm/32,   Dm/32),  tpb>>>(w1_k,  wh+OWQKV+1024*1024,   Dm,  Dm);
    transpose_half<<<dim3(Dm/32,   Dm/32),  tpb>>>(w1_v,  wh+OWQKV+2*1024*1024, Dm,  Dm);
    transpose_half<<<dim3(Dm/32,   Dm/32),  tpb>>>(w1_o,  wh+OW1O, Dm,  Dm);
    transpose_half<<<dim3(Dm/32,   Dm/32),  tpb>>>(w2_q,  wh+OW2Q, Dm,  Dm);
    transpose_half<<<dim3(Dm/32,   Dm/32),  tpb>>>(w2_o,  wh+OW2O, Dm,  Dm);
    transpose_geglu<<<dim3(2*FFd/32, Dm/32), tpb>>>(ff_w1, wh+OFW1, Dm,  2*FFd);
    transpose_half<<<dim3(Dm/32,  FFd/32),  tpb>>>(ff_w2, wh+OFW2, FFd, Dm);

    copy_kernel<<<(MROWS*Dm/4 + 255)/256, 256>>>(x, xbuf, MROWS*Dm/4);

    // ---- self attention (fused QKV + flash) ----
    ln_kernel<<<MROWS, 256>>>(xbuf, ln1_g, ln1_b, hh);
    gemm_h<1><<<gQKV, 256, GH_SMEM>>>(hh, wh+OWQKV, nullptr, nullptr, qkvh, MROWS, 3*Dm, Dm);
    flash_h<<<gFlash, 256, FLH_SMEM>>>(qkvh, atth);
    gemm_h<0><<<gD, 256, GH_SMEM>>>(atth, wh+OW1O, b1_o, xbuf, xbuf, MROWS, Dm, Dm);

    // ---- cross attention (fused flash, nk=77) ----
    ln_kernel<<<MROWS, 256>>>(xbuf, ln2_g, ln2_b, hh);
    gemm_h<1><<<gD, 256, GH_SMEM>>>(hh, wh+OW2Q, nullptr, nullptr, atth, MROWS, Dm, Dm);
    dim3 gKV(Dm/64, (CROWS+63)/64);
    gemm_kernel_h<<<gKV, 256>>>(ctx, w2_k, kh, CROWS, DCx, Dm);
    gemm_kernel_h<<<gKV, 256>>>(ctx, w2_v, vh, CROWS, DCx, Dm);
    flash_cross<<<gFlash, 256, FLC_SMEM>>>(atth, kh, vh, qkvh);   // qkvh reused as out
    gemm_h<0><<<gD, 256, GH_SMEM>>>(qkvh, wh+OW2O, b2_o, xbuf, xbuf, MROWS, Dm, Dm);

    // ---- GEGLU FFN (fused epilogue) ----
    ln_kernel<<<MROWS, 256>>>(xbuf, ln3_g, ln3_b, hh);
    gemm_h<2><<<gFF1, 256, GH_SMEM>>>(hh, wh+OFW1, ff_b1, nullptr, th, MROWS, 2*FFd, Dm);
    gemm_h<0><<<gD, 256, GH_SMEM>>>(th, wh+OFW2, ff_b2, xbuf, xbuf, MROWS, Dm, FFd);
}

// round 8
// speedup vs baseline: 2.1844x; 1.0986x over previous
#include <cuda_runtime.h>
#include <cuda_fp16.h>
#include <math.h>
#include <stdint.h>

#define Bq 2
#define SEQ 2048
#define Dm 1024
#define NCx 77
#define DCx 768
#define Hh 16
#define DHd 64
#define FFd 4096
#define SCALE_ATTN 0.125f
#define EPS_LN 1e-5f
#define MROWS (Bq*SEQ)          // 4096
#define CROWS (Bq*NCx)          // 154

// ---------------- scratch ----------------
__device__ __half g_hh[(size_t)MROWS*Dm];
__device__ __half g_qkv[(size_t)MROWS*3*Dm];
__device__ __half g_kh[(size_t)CROWS*Dm + 1024];
__device__ __half g_vh[(size_t)CROWS*Dm + 1024];
__device__ __half g_atth[(size_t)MROWS*Dm];
__device__ __half g_th[(size_t)MROWS*FFd];
__device__ __half g_wh[(size_t)18874368];        // transposed half weights [N,K]

#define OWQKV 0
#define OW1O 3145728
#define OW2Q 4194304
#define OW2O 5242880
#define OFW1 6291456
#define OFW2 14680064

// ---------------- helpers ----------------
__device__ __forceinline__ float ex2f(float x) {
    float y;
    asm("ex2.approx.f32 %0, %1;" : "=f"(y) : "f"(x));
    return y;
}
__device__ __forceinline__ void mma_f16(float c[4],
                                        uint32_t a0, uint32_t a1, uint32_t a2, uint32_t a3,
                                        uint32_t b0, uint32_t b1) {
    asm volatile(
        "mma.sync.aligned.m16n8k16.row.col.f32.f16.f16.f32 "
        "{%0,%1,%2,%3}, {%4,%5,%6,%7}, {%8,%9}, {%0,%1,%2,%3};"
        : "+f"(c[0]), "+f"(c[1]), "+f"(c[2]), "+f"(c[3])
        : "r"(a0), "r"(a1), "r"(a2), "r"(a3), "r"(b0), "r"(b1));
}
__device__ __forceinline__ void ldsm4(uint32_t& r0, uint32_t& r1, uint32_t& r2, uint32_t& r3,
                                      uint32_t addr) {
    asm volatile("ldmatrix.sync.aligned.m8n8.x4.shared.b16 {%0,%1,%2,%3}, [%4];"
                 : "=r"(r0), "=r"(r1), "=r"(r2), "=r"(r3) : "r"(addr));
}
__device__ __forceinline__ void cpa16(uint32_t dst, const void* src) {
    asm volatile("cp.async.cg.shared.global [%0], [%1], 16;" :: "r"(dst), "l"(src));
}
#define CP_COMMIT() asm volatile("cp.async.commit_group;")
#define CP_WAIT1()  asm volatile("cp.async.wait_group 1;")

// ---------------- weight transpose + fp16 convert: dst[N,K] = h(src[K,N]^T) ----
__global__ void transpose_half(const float* __restrict__ src, __half* __restrict__ dst,
                               int K, int N) {
    __shared__ float t[32][33];
    int bx = blockIdx.x * 32;
    int by = blockIdx.y * 32;
    int x = bx + threadIdx.x;
    #pragma unroll
    for (int i = 0; i < 32; i += 8) {
        int y = by + threadIdx.y + i;
        t[threadIdx.y + i][threadIdx.x] = src[(size_t)y * N + x];
    }
    __syncthreads();
    int kx = by + threadIdx.x;
    #pragma unroll
    for (int i = 0; i < 32; i += 8) {
        int ny = bx + threadIdx.y + i;
        dst[(size_t)ny * K + kx] = __float2half(t[threadIdx.x][threadIdx.y + i]);
    }
}
__global__ void transpose_geglu(const float* __restrict__ src, __half* __restrict__ dst,
                                int K, int N) {
    __shared__ float t[32][33];
    int bx = blockIdx.x * 32;
    int by = blockIdx.y * 32;
    int x = bx + threadIdx.x;
    #pragma unroll
    for (int i = 0; i < 32; i += 8) {
        int y = by + threadIdx.y + i;
        t[threadIdx.y + i][threadIdx.x] = src[(size_t)y * N + x];
    }
    __syncthreads();
    int kx = by + threadIdx.x;
    #pragma unroll
    for (int i = 0; i < 32; i += 8) {
        int ny = bx + threadIdx.y + i;
        int iny = (ny < FFd) ? (2*ny) : (2*(ny - FFd) + 1);
        dst[(size_t)iny * K + kx] = __float2half(t[threadIdx.x][threadIdx.y + i]);
    }
}

// ================= fp16 dense GEMM (ldmatrix fragments) =====================
// MODE 0: fp32 out (+bias +res); MODE 1: half out; MODE 2: GEGLU fused.
#define ASH 40
#define HTILE (128*ASH)
#define GH_SMEM (3*2*HTILE*2)

template<int MODE>
__global__ __launch_bounds__(256, 2)
void gemm_h(const __half* __restrict__ A, const __half* __restrict__ Bt,
            const float* __restrict__ bias, const float* __restrict__ res,
            void* __restrict__ Cv, int M, int N, int K) {
    extern __shared__ __half smh[];
    __half* As = smh;
    __half* Bs = smh + 3*HTILE;
    int bm = blockIdx.y * 128, bn = blockIdx.x * 128;
    int tid = threadIdx.x, warp = tid >> 5, lane = tid & 31;
    int grp = lane >> 2, tig = lane & 3;
    int wm = (warp >> 2) * 64, wn = (warp & 3) * 32;
    int sel = lane >> 3, lrow = lane & 7;
    // ldmatrix per-lane quadrant offsets
    int a_r = (sel & 1) * 8 + lrow, a_c = (sel >> 1) * 8;   // A: m+8 if sel odd, k+8 if sel>=2
    int b_r = (sel >> 1) * 8 + lrow, b_c = (sel & 1) * 8;   // B: n+8 if sel>=2, k+8 if sel odd
    uint32_t sAu = (uint32_t)__cvta_generic_to_shared(As);
    uint32_t sBu = (uint32_t)__cvta_generic_to_shared(Bs);
    int niter = K >> 5;

    float acc[4][4][4] = {};

    auto loadTile = [&](int it, int buf) {
        int k0 = it * 32;
        #pragma unroll
        for (int i = 0; i < 2; i++) {
            int c = tid + i * 256;
            int row = c >> 2, kq = c & 3;
            cpa16(sAu + (uint32_t)(buf*HTILE + row*ASH + kq*8) * 2,
                  A + (size_t)(bm + row) * K + k0 + kq * 8);
            cpa16(sBu + (uint32_t)(buf*HTILE + row*ASH + kq*8) * 2,
                  Bt + (size_t)(bn + row) * K + k0 + kq * 8);
        }
        CP_COMMIT();
    };

    loadTile(0, 0);
    loadTile(1, 1);

    for (int it = 0; it < niter; ++it) {
        CP_WAIT1();
        __syncthreads();
        if (it + 2 < niter) loadTile(it + 2, (it + 2) % 3);
        else CP_COMMIT();

        uint32_t Abu = sAu + (uint32_t)((it % 3) * HTILE) * 2;
        uint32_t Bbu = sBu + (uint32_t)((it % 3) * HTILE) * 2;
        #pragma unroll
        for (int ks = 0; ks < 32; ks += 16) {
            uint32_t af[4][4], bf[4][2];
            #pragma unroll
            for (int mf = 0; mf < 4; mf++) {
                uint32_t ad = Abu + (uint32_t)((wm + mf*16 + a_r) * ASH + ks + a_c) * 2;
                ldsm4(af[mf][0], af[mf][1], af[mf][2], af[mf][3], ad);
            }
            #pragma unroll
            for (int np = 0; np < 2; np++) {
                uint32_t bd = Bbu + (uint32_t)((wn + np*16 + b_r) * ASH + ks + b_c) * 2;
                ldsm4(bf[2*np][0], bf[2*np][1], bf[2*np+1][0], bf[2*np+1][1], bd);
            }
            #pragma unroll
            for (int mf = 0; mf < 4; mf++)
                #pragma unroll
                for (int nf = 0; nf < 4; nf++)
                    mma_f16(acc[mf][nf], af[mf][0], af[mf][1], af[mf][2], af[mf][3],
                            bf[nf][0], bf[nf][1]);
        }
    }

    #pragma unroll
    for (int mf = 0; mf < 4; mf++) {
        #pragma unroll
        for (int nf = 0; nf < 4; nf++) {
            int r = bm + wm + mf*16 + grp;
            int c = bn + wn + nf*8 + tig*2;
            float2 v0 = make_float2(acc[mf][nf][0], acc[mf][nf][1]);
            float2 v1 = make_float2(acc[mf][nf][2], acc[mf][nf][3]);
            if (MODE == 2) {
                int j = c >> 1;
                float bv = bias[j], bg = bias[FFd + j];
                float val0 = v0.x + bv, gat0 = v0.y + bg;
                float val1 = v1.x + bv, gat1 = v1.y + bg;
                float o0 = val0 * (0.5f * gat0 * (1.f + erff(gat0 * 0.70710678118654752f)));
                float o1 = val1 * (0.5f * gat1 * (1.f + erff(gat1 * 0.70710678118654752f)));
                __half* C = (__half*)Cv;
                C[(size_t)r * FFd + j]     = __float2half(o0);
                C[(size_t)(r+8) * FFd + j] = __float2half(o1);
            } else {
                if (bias) {
                    float2 bb = *(const float2*)(bias + c);
                    v0.x += bb.x; v0.y += bb.y; v1.x += bb.x; v1.y += bb.y;
                }
                if (MODE == 0 && res) {
                    float2 r0 = *(const float2*)(res + (size_t)r * N + c);
                    float2 r1 = *(const float2*)(res + (size_t)(r+8) * N + c);
                    v0.x += r0.x; v0.y += r0.y; v1.x += r1.x; v1.y += r1.y;
                }
                if (MODE == 1) {
                    __half* C = (__half*)Cv;
                    *(__half2*)(C + (size_t)r * N + c)     = __floats2half2_rn(v0.x, v0.y);
                    *(__half2*)(C + (size_t)(r+8) * N + c) = __floats2half2_rn(v1.x, v1.y);
                } else {
                    float* C = (float*)Cv;
                    *(float2*)(C + (size_t)r * N + c)     = v0;
                    *(float2*)(C + (size_t)(r+8) * N + c) = v1;
                }
            }
        }
    }
}

// ================= fp16 flash attention (self-attn, strided QKV) ============
#define QSH 72
#define VSH 136
#define PSH 136
#define FLH_SMEM ((2*128*QSH + 64*VSH + 128*PSH)*2)

__global__ __launch_bounds__(256, 2)
void flash_h(const __half* __restrict__ qkv, __half* __restrict__ o) {
    extern __shared__ __half smf[];
    __half* Qs = smf;
    __half* Ks = Qs + 128*QSH;
    __half* Vt = Ks + 128*QSH;
    __half* Ps = Vt + 64*VSH;
    uint32_t Ksu = (uint32_t)__cvta_generic_to_shared(Ks);
    uint32_t Vtu = (uint32_t)__cvta_generic_to_shared(Vt);
    uint32_t Psu = (uint32_t)__cvta_generic_to_shared(Ps);

    const int ldq = 3*Dm;
    int qt = blockIdx.x, bh = blockIdx.y;
    int b = bh >> 4, h = bh & 15;
    int tid = threadIdx.x, warp = tid >> 5, lane = tid & 31;
    int grp = lane >> 2, tig = lane & 3;
    int sel = lane >> 3, lrow = lane & 7;
    int a_r = (sel & 1) * 8 + lrow, a_c = (sel >> 1) * 8;
    int b_r = (sel >> 1) * 8 + lrow, b_c = (sel & 1) * 8;

    const __half* qb = qkv + ((size_t)b*SEQ + qt*128) * ldq + h*DHd;
    const __half* kb = qkv + (size_t)b*SEQ*ldq + Dm + h*DHd;
    const __half* vb = qkv + (size_t)b*SEQ*ldq + 2*Dm + h*DHd;

    {
        int row = tid >> 1, part = tid & 1;
        const float4* s4 = (const float4*)(qb + (size_t)row * ldq + part*32);
        float4* d4 = (float4*)(Qs + row*QSH + part*32);
        #pragma unroll
        for (int i = 0; i < 4; i++) d4[i] = s4[i];
    }
    __syncthreads();

    uint32_t qf[4][4];
    {
        const __half* p = Qs + (warp*16 + grp) * QSH;
        #pragma unroll
        for (int ksi = 0; ksi < 4; ksi++) {
            qf[ksi][0] = *(const uint32_t*)(p + ksi*16 + tig*2);
            qf[ksi][1] = *(const uint32_t*)(p + 8*QSH + ksi*16 + tig*2);
            qf[ksi][2] = *(const uint32_t*)(p + ksi*16 + tig*2 + 8);
            qf[ksi][3] = *(const uint32_t*)(p + 8*QSH + ksi*16 + tig*2 + 8);
        }
    }

    float oacc[8][4] = {};
    float m0 = -1e30f, m1 = -1e30f, l0 = 0.f, l1 = 0.f;
    const float Csc = SCALE_ATTN * 1.4426950408889634f;
    int prow = warp*16 + grp;

    for (int kv0 = 0; kv0 < SEQ; kv0 += 128) {
        {
            int row = tid >> 1, part = tid & 1;
            const float4* s4 = (const float4*)(kb + (size_t)(kv0+row) * ldq + part*32);
            float4* d4 = (float4*)(Ks + row*QSH + part*32);
            #pragma unroll
            for (int i = 0; i < 4; i++) d4[i] = s4[i];
        }
        {
            int d = tid & 63;
            #pragma unroll
            for (int kvp = tid >> 6; kvp < 64; kvp += 4) {
                int kv = kvp * 2;
                __half v0 = vb[(size_t)(kv0 + kv)     * ldq + d];
                __half v1 = vb[(size_t)(kv0 + kv + 1) * ldq + d];
                *(__half2*)(Vt + d*VSH + kv) = __halves2half2(v0, v1);
            }
        }
        __syncthreads();

        // S = Q K^T (16x128 per warp) — K fragments via ldmatrix
        float sacc[16][4] = {};
        #pragma unroll
        for (int ksi = 0; ksi < 4; ksi++) {
            #pragma unroll
            for (int np = 0; np < 8; np++) {
                uint32_t kd = Ksu + (uint32_t)((np*16 + b_r) * QSH + ksi*16 + b_c) * 2;
                uint32_t b00, b01, b10, b11;
                ldsm4(b00, b01, b10, b11, kd);
                mma_f16(sacc[2*np],   qf[ksi][0], qf[ksi][1], qf[ksi][2], qf[ksi][3], b00, b01);
                mma_f16(sacc[2*np+1], qf[ksi][0], qf[ksi][1], qf[ksi][2], qf[ksi][3], b10, b11);
            }
        }
        float mx0 = -1e30f, mx1 = -1e30f;
        #pragma unroll
        for (int nf = 0; nf < 16; nf++) {
            sacc[nf][0] *= Csc; sacc[nf][1] *= Csc; sacc[nf][2] *= Csc; sacc[nf][3] *= Csc;
            mx0 = fmaxf(mx0, fmaxf(sacc[nf][0], sacc[nf][1]));
            mx1 = fmaxf(mx1, fmaxf(sacc[nf][2], sacc[nf][3]));
        }
        mx0 = fmaxf(mx0, __shfl_xor_sync(0xffffffffu, mx0, 1));
        mx0 = fmaxf(mx0, __shfl_xor_sync(0xffffffffu, mx0, 2));
        mx1 = fmaxf(mx1, __shfl_xor_sync(0xffffffffu, mx1, 1));
        mx1 = fmaxf(mx1, __shfl_xor_sync(0xffffffffu, mx1, 2));
        float mn0 = fmaxf(m0, mx0), mn1 = fmaxf(m1, mx1);
        float sc0 = ex2f(m0 - mn0), sc1 = ex2f(m1 - mn1);
        float sum0 = 0.f, sum1 = 0.f;
        #pragma unroll
        for (int nf = 0; nf < 16; nf++) {
            float p0 = ex2f(sacc[nf][0] - mn0);
            float p1 = ex2f(sacc[nf][1] - mn0);
            float p2 = ex2f(sacc[nf][2] - mn1);
            float p3 = ex2f(sacc[nf][3] - mn1);
            sum0 += p0 + p1; sum1 += p2 + p3;
            int pc = nf*8 + tig*2;
            *(__half2*)(Ps + prow*PSH + pc)     = __floats2half2_rn(p0, p1);
            *(__half2*)(Ps + (prow+8)*PSH + pc) = __floats2half2_rn(p2, p3);
        }
        sum0 += __shfl_xor_sync(0xffffffffu, sum0, 1);
        sum0 += __shfl_xor_sync(0xffffffffu, sum0, 2);
        sum1 += __shfl_xor_sync(0xffffffffu, sum1, 1);
        sum1 += __shfl_xor_sync(0xffffffffu, sum1, 2);
        l0 = l0 * sc0 + sum0;  l1 = l1 * sc1 + sum1;
        m0 = mn0;  m1 = mn1;
        #pragma unroll
        for (int nf = 0; nf < 8; nf++) {
            oacc[nf][0] *= sc0; oacc[nf][1] *= sc0;
            oacc[nf][2] *= sc1; oacc[nf][3] *= sc1;
        }
        __syncwarp();

        // O += P V — fragments via ldmatrix
        #pragma unroll
        for (int ks = 0; ks < 8; ks++) {
            uint32_t pd = Psu + (uint32_t)((warp*16 + a_r) * PSH + ks*16 + a_c) * 2;
            uint32_t a0, a1, a2, a3;
            ldsm4(a0, a1, a2, a3, pd);
            #pragma unroll
            for (int np = 0; np < 4; np++) {
                uint32_t vd = Vtu + (uint32_t)((np*16 + b_r) * VSH + ks*16 + b_c) * 2;
                uint32_t b00, b01, b10, b11;
                ldsm4(b00, b01, b10, b11, vd);
                mma_f16(oacc[2*np],   a0, a1, a2, a3, b00, b01);
                mma_f16(oacc[2*np+1], a0, a1, a2, a3, b10, b11);
            }
        }
        __syncthreads();
    }

    float i0 = 1.f / l0, i1 = 1.f / l1;
    __half* ob = o + ((size_t)b*SEQ + qt*128 + warp*16) * Dm + h*DHd;
    #pragma unroll
    for (int nf = 0; nf < 8; nf++) {
        int c = nf*8 + tig*2;
        *(__half2*)(ob + (size_t)grp * Dm + c) =
            __floats2half2_rn(oacc[nf][0]*i0, oacc[nf][1]*i0);
        *(__half2*)(ob + (size_t)(grp+8) * Dm + c) =
            __floats2half2_rn(oacc[nf][2]*i1, oacc[nf][3]*i1);
    }
}

// ================= fp16 cross-attention (single KV tile, nk=77) =============
#define CKROWS 80
#define CVSH 88
#define CPSH 88
#define FLC_SMEM ((128*QSH + CKROWS*QSH + 64*CVSH + 128*CPSH)*2)

__global__ __launch_bounds__(256, 2)
void flash_cross(const __half* __restrict__ q, const __half* __restrict__ k,
                 const __half* __restrict__ v, __half* __restrict__ o) {
    extern __shared__ __half smc[];
    __half* Qs = smc;
    __half* Ks = Qs + 128*QSH;
    __half* Vt = Ks + CKROWS*QSH;
    __half* Ps = Vt + 64*CVSH;

    int qt = blockIdx.x, bh = blockIdx.y;
    int b = bh >> 4, h = bh & 15;
    int tid = threadIdx.x, warp = tid >> 5, lane = tid & 31;
    int grp = lane >> 2, tig = lane & 3;

    const __half* qb = q + ((size_t)b*SEQ + qt*128) * Dm + h*DHd;
    const __half* kb = k + (size_t)b*NCx*Dm + h*DHd;
    const __half* vb = v + (size_t)b*NCx*Dm + h*DHd;

    {
        int row = tid >> 1, part = tid & 1;
        const float4* s4 = (const float4*)(qb + (size_t)row * Dm + part*32);
        float4* d4 = (float4*)(Qs + row*QSH + part*32);
        #pragma unroll
        for (int i = 0; i < 4; i++) d4[i] = s4[i];
    }
    for (int rr = tid; rr < CKROWS*2; rr += 256) {
        int row = rr >> 1, part = rr & 1;
        float4* d4 = (float4*)(Ks + row*QSH + part*32);
        if (row < NCx) {
            const float4* s4 = (const float4*)(kb + (size_t)row * Dm + part*32);
            #pragma unroll
            for (int i = 0; i < 4; i++) d4[i] = s4[i];
        } else {
            float4 z = make_float4(0.f,0.f,0.f,0.f);
            #pragma unroll
            for (int i = 0; i < 4; i++) d4[i] = z;
        }
    }
    {
        int d = tid & 63;
        for (int kvp = tid >> 6; kvp < CKROWS/2; kvp += 4) {
            int kv = kvp * 2;
            __half v0 = (kv   < NCx) ? vb[(size_t)kv     * Dm + d] : __half(0.f);
            __half v1 = (kv+1 < NCx) ? vb[(size_t)(kv+1) * Dm + d] : __half(0.f);
            *(__half2*)(Vt + d*CVSH + kv) = __halves2half2(v0, v1);
        }
    }
    __syncthreads();

    uint32_t qf[4][4];
    {
        const __half* p = Qs + (warp*16 + grp) * QSH;
        #pragma unroll
        for (int ksi = 0; ksi < 4; ksi++) {
            qf[ksi][0] = *(const uint32_t*)(p + ksi*16 + tig*2);
            qf[ksi][1] = *(const uint32_t*)(p + 8*QSH + ksi*16 + tig*2);
            qf[ksi][2] = *(const uint32_t*)(p + ksi*16 + tig*2 + 8);
            qf[ksi][3] = *(const uint32_t*)(p + 8*QSH + ksi*16 + tig*2 + 8);
        }
    }

    const float Csc = SCALE_ATTN * 1.4426950408889634f;
    int prow = warp*16 + grp;

    float sacc[10][4] = {};
    #pragma unroll
    for (int ksi = 0; ksi < 4; ksi++) {
        #pragma unroll
        for (int nf = 0; nf < 10; nf++) {
            const __half* kp = Ks + (nf*8 + grp) * QSH + ksi*16;
            uint32_t b0 = *(const uint32_t*)(kp + tig*2);
            uint32_t b1 = *(const uint32_t*)(kp + tig*2 + 8);
            mma_f16(sacc[nf], qf[ksi][0], qf[ksi][1], qf[ksi][2], qf[ksi][3], b0, b1);
        }
    }
    float mx0 = -1e30f, mx1 = -1e30f;
    #pragma unroll
    for (int nf = 0; nf < 10; nf++) {
        int c0 = nf*8 + tig*2, c1 = c0 + 1;
        sacc[nf][0] = (c0 < NCx) ? sacc[nf][0]*Csc : -1e30f;
        sacc[nf][1] = (c1 < NCx) ? sacc[nf][1]*Csc : -1e30f;
        sacc[nf][2] = (c0 < NCx) ? sacc[nf][2]*Csc : -1e30f;
        sacc[nf][3] = (c1 < NCx) ? sacc[nf][3]*Csc : -1e30f;
        mx0 = fmaxf(mx0, fmaxf(sacc[nf][0], sacc[nf][1]));
        mx1 = fmaxf(mx1, fmaxf(sacc[nf][2], sacc[nf][3]));
    }
    mx0 = fmaxf(mx0, __shfl_xor_sync(0xffffffffu, mx0, 1));
    mx0 = fmaxf(mx0, __shfl_xor_sync(0xffffffffu, mx0, 2));
    mx1 = fmaxf(mx1, __shfl_xor_sync(0xffffffffu, mx1, 1));
    mx1 = fmaxf(mx1, __shfl_xor_sync(0xffffffffu, mx1, 2));

    float sum0 = 0.f, sum1 = 0.f;
    #pragma unroll
    for (int nf = 0; nf < 10; nf++) {
        float p0 = ex2f(sacc[nf][0] - mx0);
        float p1 = ex2f(sacc[nf][1] - mx0);
        float p2 = ex2f(sacc[nf][2] - mx1);
        float p3 = ex2f(sacc[nf][3] - mx1);
        sum0 += p0 + p1; sum1 += p2 + p3;
        int pc = nf*8 + tig*2;
        *(__half2*)(Ps + prow*CPSH + pc)     = __floats2half2_rn(p0, p1);
        *(__half2*)(Ps + (prow+8)*CPSH + pc) = __floats2half2_rn(p2, p3);
    }
    sum0 += __shfl_xor_sync(0xffffffffu, sum0, 1);
    sum0 += __shfl_xor_sync(0xffffffffu, sum0, 2);
    sum1 += __shfl_xor_sync(0xffffffffu, sum1, 1);
    sum1 += __shfl_xor_sync(0xffffffffu, sum1, 2);
    __syncwarp();

    float oacc[8][4] = {};
    #pragma unroll
    for (int ks = 0; ks < 5; ks++) {
        const __half* pp = Ps + prow*CPSH + ks*16;
        uint32_t a0 = *(const uint32_t*)(pp + tig*2);
        uint32_t a1 = *(const uint32_t*)(pp + 8*CPSH + tig*2);
        uint32_t a2 = *(const uint32_t*)(pp + tig*2 + 8);
        uint32_t a3 = *(const uint32_t*)(pp + 8*CPSH + tig*2 + 8);
        #pragma unroll
        for (int nf = 0; nf < 8; nf++) {
            const __half* vp = Vt + (nf*8 + grp) * CVSH + ks*16;
            uint32_t b0 = *(const uint32_t*)(vp + tig*2);
            uint32_t b1 = *(const uint32_t*)(vp + tig*2 + 8);
            mma_f16(oacc[nf], a0, a1, a2, a3, b0, b1);
        }
    }

    float i0 = 1.f / sum0, i1 = 1.f / sum1;
    __half* ob = o + ((size_t)b*SEQ + qt*128 + warp*16) * Dm + h*DHd;
    #pragma unroll
    for (int nf = 0; nf < 8; nf++) {
        int c = nf*8 + tig*2;
        *(__half2*)(ob + (size_t)grp * Dm + c) =
            __floats2half2_rn(oacc[nf][0]*i0, oacc[nf][1]*i0);
        *(__half2*)(ob + (size_t)(grp+8) * Dm + c) =
            __floats2half2_rn(oacc[nf][2]*i1, oacc[nf][3]*i1);
    }
}

// ---------------- elementwise / small kernels ----------------
__global__ void copy_kernel(const float* __restrict__ src, float* __restrict__ dst, int n4) {
    int i = blockIdx.x * blockDim.x + threadIdx.x;
    if (i < n4)
        reinterpret_cast<float4*>(dst)[i] = reinterpret_cast<const float4*>(src)[i];
}

__global__ void ln_kernel(const float* __restrict__ x, const float* __restrict__ g,
                          const float* __restrict__ b, __half* __restrict__ out) {
    int row = blockIdx.x;
    const float* xr = x + (size_t)row * Dm;
    float s = 0.f, ss = 0.f;
    for (int i = threadIdx.x; i < Dm; i += 256) {
        float v = xr[i];
        s += v; ss += v * v;
    }
    __shared__ float rs[256], rss[256];
    rs[threadIdx.x] = s; rss[threadIdx.x] = ss;
    __syncthreads();
    for (int st = 128; st > 0; st >>= 1) {
        if (threadIdx.x < st) { rs[threadIdx.x] += rs[threadIdx.x+st]; rss[threadIdx.x] += rss[threadIdx.x+st]; }
        __syncthreads();
    }
    float mu  = rs[0] * (1.0f / Dm);
    float var = rss[0] * (1.0f / Dm) - mu * mu;
    float inv = rsqrtf(var + EPS_LN);
    __half* orow = out + (size_t)row * Dm;
    for (int i = threadIdx.x; i < Dm; i += 256)
        orow[i] = __float2half((xr[i] - mu) * inv * g[i] + b[i]);
}

__global__ void gemm_kernel_h(const float* __restrict__ A, const float* __restrict__ Bm,
                              __half* __restrict__ C, int M, int K, int Nn) {
    __shared__ float As[64][17];
    __shared__ float Bs[16][64];
    int bm = blockIdx.y * 64, bn = blockIdx.x * 64;
    int tx = threadIdx.x & 15, ty = threadIdx.x >> 4;
    float acc[4][4] = {};
    for (int k0 = 0; k0 < K; k0 += 16) {
        #pragma unroll
        for (int i = 0; i < 4; i++) {
            int idx = threadIdx.x + i * 256;
            int r = idx >> 4, kk = idx & 15;
            int gr = bm + r;
            As[r][kk] = (gr < M) ? A[(size_t)gr * K + k0 + kk] : 0.f;
            int kb = idx >> 6, c = idx & 63;
            int gc = bn + c;
            Bs[kb][c] = (gc < Nn) ? Bm[(size_t)(k0 + kb) * Nn + gc] : 0.f;
        }
        __syncthreads();
        #pragma unroll
        for (int kk = 0; kk < 16; kk++) {
            float a[4], bb[4];
            #pragma unroll
            for (int i = 0; i < 4; i++) a[i]  = As[ty*4+i][kk];
            #pragma unroll
            for (int j = 0; j < 4; j++) bb[j] = Bs[kk][tx*4+j];
            #pragma unroll
            for (int i = 0; i < 4; i++)
                #pragma unroll
                for (int j = 0; j < 4; j++)
                    acc[i][j] += a[i] * bb[j];
        }
        __syncthreads();
    }
    #pragma unroll
    for (int i = 0; i < 4; i++) {
        int gr = bm + ty*4 + i;
        if (gr >= M) continue;
        #pragma unroll
        for (int j = 0; j < 4; j++) {
            int gc = bn + tx*4 + j;
            if (gc >= Nn) continue;
            C[(size_t)gr * Nn + gc] = __float2half(acc[i][j]);
        }
    }
}

// ---------------- launch ----------------
extern "C" void kernel_launch(void* const* d_in, const int* in_sizes, int n_in,
                              void* d_out, int out_size) {
    const float* x      = (const float*)d_in[0];
    const float* ctx    = (const float*)d_in[1];
    const float* w1_q   = (const float*)d_in[2];
    const float* w1_k   = (const float*)d_in[3];
    const float* w1_v   = (const float*)d_in[4];
    const float* w1_o   = (const float*)d_in[5];
    const float* b1_o   = (const float*)d_in[6];
    const float* w2_q   = (const float*)d_in[7];
    const float* w2_k   = (const float*)d_in[8];
    const float* w2_v   = (const float*)d_in[9];
    const float* w2_o   = (const float*)d_in[10];
    const float* b2_o   = (const float*)d_in[11];
    const float* ln1_g  = (const float*)d_in[12];
    const float* ln1_b  = (const float*)d_in[13];
    const float* ln2_g  = (const float*)d_in[14];
    const float* ln2_b  = (const float*)d_in[15];
    const float* ln3_g  = (const float*)d_in[16];
    const float* ln3_b  = (const float*)d_in[17];
    const float* ff_w1  = (const float*)d_in[18];
    const float* ff_b1  = (const float*)d_in[19];
    const float* ff_w2  = (const float*)d_in[20];
    const float* ff_b2  = (const float*)d_in[21];
    float* xbuf = (float*)d_out;

    __half *hh, *qkvh, *kh, *vh, *atth, *th, *wh;
    cudaGetSymbolAddress((void**)&hh,   g_hh);
    cudaGetSymbolAddress((void**)&qkvh, g_qkv);
    cudaGetSymbolAddress((void**)&kh,   g_kh);
    cudaGetSymbolAddress((void**)&vh,   g_vh);
    cudaGetSymbolAddress((void**)&atth, g_atth);
    cudaGetSymbolAddress((void**)&th,   g_th);
    cudaGetSymbolAddress((void**)&wh,   g_wh);

    cudaFuncSetAttribute(gemm_h<0>, cudaFuncAttributeMaxDynamicSharedMemorySize, GH_SMEM);
    cudaFuncSetAttribute(gemm_h<1>, cudaFuncAttributeMaxDynamicSharedMemorySize, GH_SMEM);
    cudaFuncSetAttribute(gemm_h<2>, cudaFuncAttributeMaxDynamicSharedMemorySize, GH_SMEM);
    cudaFuncSetAttribute(flash_h,     cudaFuncAttributeMaxDynamicSharedMemorySize, FLH_SMEM);
    cudaFuncSetAttribute(flash_cross, cudaFuncAttributeMaxDynamicSharedMemorySize, FLC_SMEM);

    dim3 gD(Dm/128, MROWS/128);
    dim3 gQKV(3*Dm/128, MROWS/128);
    dim3 gFF1(2*FFd/128, MROWS/128);
    dim3 gFlash(SEQ/128, Bq*Hh);
    dim3 tpb(32, 8);

    transpose_half<<<dim3(Dm/32,   Dm/32),  tpb>>>(w1_q,  wh+OWQKV,             Dm,  Dm);
    transpose_half<<<dim3(Dm/32,   Dm/32),  tpb>>>(w1_k,  wh+OWQKV+1024*1024,   Dm,  Dm);
    transpose_half<<<dim3(Dm/32,   Dm/32),  tpb>>>(w1_v,  wh+OWQKV+2*1024*1024, Dm,  Dm);
    transpose_half<<<dim3(Dm/32,   Dm/32),  tpb>>>(w1_o,  wh+OW1O, Dm,  Dm);
    transpose_half<<<dim3(Dm/32,   Dm/32),  tpb>>>(w2_q,  wh+OW2Q, Dm,  Dm);
    transpose_half<<<dim3(Dm/32,   Dm/32),  tpb>>>(w2_o,  wh+OW2O, Dm,  Dm);
    transpose_geglu<<<dim3(2*FFd/32, Dm/32), tpb>>>(ff_w1, wh+OFW1, Dm,  2*FFd);
    transpose_half<<<dim3(Dm/32,  FFd/32),  tpb>>>(ff_w2, wh+OFW2, FFd, Dm);

    copy_kernel<<<(MROWS*Dm/4 + 255)/256, 256>>>(x, xbuf, MROWS*Dm/4);

    // ---- self attention ----
    ln_kernel<<<MROWS, 256>>>(xbuf, ln1_g, ln1_b, hh);
    gemm_h<1><<<gQKV, 256, GH_SMEM>>>(hh, wh+OWQKV, nullptr, nullptr, qkvh, MROWS, 3*Dm, Dm);
    flash_h<<<gFlash, 256, FLH_SMEM>>>(qkvh, atth);
    gemm_h<0><<<gD, 256, GH_SMEM>>>(atth, wh+OW1O, b1_o, xbuf, xbuf, MROWS, Dm, Dm);

    // ---- cross attention ----
    ln_kernel<<<MROWS, 256>>>(xbuf, ln2_g, ln2_b, hh);
    gemm_h<1><<<gD, 256, GH_SMEM>>>(hh, wh+OW2Q, nullptr, nullptr, atth, MROWS, Dm, Dm);
    dim3 gKV(Dm/64, (CROWS+63)/64);
    gemm_kernel_h<<<gKV, 256>>>(ctx, w2_k, kh, CROWS, DCx, Dm);
    gemm_kernel_h<<<gKV, 256>>>(ctx, w2_v, vh, CROWS, DCx, Dm);
    flash_cross<<<gFlash, 256, FLC_SMEM>>>(atth, kh, vh, qkvh);
    gemm_h<0><<<gD, 256, GH_SMEM>>>(qkvh, wh+OW2O, b2_o, xbuf, xbuf, MROWS, Dm, Dm);

    // ---- GEGLU FFN ----
    ln_kernel<<<MROWS, 256>>>(xbuf, ln3_g, ln3_b, hh);
    gemm_h<2><<<gFF1, 256, GH_SMEM>>>(hh, wh+OFW1, ff_b1, nullptr, th, MROWS, 2*FFd, Dm);
    gemm_h<0><<<gD, 256, GH_SMEM>>>(th, wh+OFW2, ff_b2, xbuf, xbuf, MROWS, Dm, FFd);
}

// round 9
// speedup vs baseline: 2.4505x; 1.1218x over previous
#include <cuda_runtime.h>
#include <cuda_fp16.h>
#include <math.h>
#include <stdint.h>

#define Bq 2
#define SEQ 2048
#define Dm 1024
#define NCx 77
#define DCx 768
#define Hh 16
#define DHd 64
#define FFd 4096
#define SCALE_ATTN 0.125f
#define EPS_LN 1e-5f
#define MROWS (Bq*SEQ)          // 4096
#define CROWS (Bq*NCx)          // 154

// ---------------- scratch ----------------
__device__ __half g_hh[(size_t)MROWS*Dm];
__device__ __half g_qkv[(size_t)MROWS*3*Dm];
__device__ __half g_kh[(size_t)CROWS*Dm + 1024];
__device__ __half g_vh[(size_t)CROWS*Dm + 1024];
__device__ __half g_atth[(size_t)MROWS*Dm];
__device__ __half g_th[(size_t)MROWS*FFd];
__device__ __half g_wh[(size_t)18874368];        // transposed half weights [N,K]

#define OWQKV 0
#define OW1O 3145728
#define OW2Q 4194304
#define OW2O 5242880
#define OFW1 6291456
#define OFW2 14680064

// ---------------- helpers ----------------
__device__ __forceinline__ float ex2f(float x) {
    float y;
    asm("ex2.approx.f32 %0, %1;" : "=f"(y) : "f"(x));
    return y;
}
__device__ __forceinline__ void mma_f16(float c[4],
                                        uint32_t a0, uint32_t a1, uint32_t a2, uint32_t a3,
                                        uint32_t b0, uint32_t b1) {
    asm volatile(
        "mma.sync.aligned.m16n8k16.row.col.f32.f16.f16.f32 "
        "{%0,%1,%2,%3}, {%4,%5,%6,%7}, {%8,%9}, {%0,%1,%2,%3};"
        : "+f"(c[0]), "+f"(c[1]), "+f"(c[2]), "+f"(c[3])
        : "r"(a0), "r"(a1), "r"(a2), "r"(a3), "r"(b0), "r"(b1));
}
__device__ __forceinline__ void ldsm4(uint32_t& r0, uint32_t& r1, uint32_t& r2, uint32_t& r3,
                                      uint32_t addr) {
    asm volatile("ldmatrix.sync.aligned.m8n8.x4.shared.b16 {%0,%1,%2,%3}, [%4];"
                 : "=r"(r0), "=r"(r1), "=r"(r2), "=r"(r3) : "r"(addr));
}
__device__ __forceinline__ void cpa16(uint32_t dst, const void* src) {
    asm volatile("cp.async.cg.shared.global [%0], [%1], 16;" :: "r"(dst), "l"(src));
}
#define CP_COMMIT() asm volatile("cp.async.commit_group;")
#define CP_WAIT1()  asm volatile("cp.async.wait_group 1;")

// ---------------- weight transpose + fp16 convert ----------------
__global__ void transpose_half(const float* __restrict__ src, __half* __restrict__ dst,
                               int K, int N) {
    __shared__ float t[32][33];
    int bx = blockIdx.x * 32;
    int by = blockIdx.y * 32;
    int x = bx + threadIdx.x;
    #pragma unroll
    for (int i = 0; i < 32; i += 8) {
        int y = by + threadIdx.y + i;
        t[threadIdx.y + i][threadIdx.x] = src[(size_t)y * N + x];
    }
    __syncthreads();
    int kx = by + threadIdx.x;
    #pragma unroll
    for (int i = 0; i < 32; i += 8) {
        int ny = bx + threadIdx.y + i;
        dst[(size_t)ny * K + kx] = __float2half(t[threadIdx.x][threadIdx.y + i]);
    }
}
__global__ void transpose_geglu(const float* __restrict__ src, __half* __restrict__ dst,
                                int K, int N) {
    __shared__ float t[32][33];
    int bx = blockIdx.x * 32;
    int by = blockIdx.y * 32;
    int x = bx + threadIdx.x;
    #pragma unroll
    for (int i = 0; i < 32; i += 8) {
        int y = by + threadIdx.y + i;
        t[threadIdx.y + i][threadIdx.x] = src[(size_t)y * N + x];
    }
    __syncthreads();
    int kx = by + threadIdx.x;
    #pragma unroll
    for (int i = 0; i < 32; i += 8) {
        int ny = bx + threadIdx.y + i;
        int iny = (ny < FFd) ? (2*ny) : (2*(ny - FFd) + 1);
        dst[(size_t)iny * K + kx] = __float2half(t[threadIdx.x][threadIdx.y + i]);
    }
}

// ================= fp16 dense GEMM (ldmatrix, BK=64, 3-stage) ===============
// MODE 0: fp32 out (+bias +res); MODE 1: half out; MODE 2: GEGLU fused.
#define ASH 72
#define HTILE (128*ASH)
#define GH_SMEM (3*2*HTILE*2)

template<int MODE>
__global__ __launch_bounds__(256, 2)
void gemm_h(const __half* __restrict__ A, const __half* __restrict__ Bt,
            const float* __restrict__ bias, const float* __restrict__ res,
            void* __restrict__ Cv, int M, int N, int K) {
    extern __shared__ __half smh[];
    __half* As = smh;
    __half* Bs = smh + 3*HTILE;
    int bm = blockIdx.y * 128, bn = blockIdx.x * 128;
    int tid = threadIdx.x, warp = tid >> 5, lane = tid & 31;
    int grp = lane >> 2, tig = lane & 3;
    int wm = (warp >> 2) * 64, wn = (warp & 3) * 32;
    int sel = lane >> 3, lrow = lane & 7;
    int a_r = (sel & 1) * 8 + lrow, a_c = (sel >> 1) * 8;
    int b_r = (sel >> 1) * 8 + lrow, b_c = (sel & 1) * 8;
    uint32_t sAu = (uint32_t)__cvta_generic_to_shared(As);
    uint32_t sBu = (uint32_t)__cvta_generic_to_shared(Bs);
    int niter = K >> 6;

    float acc[4][4][4] = {};

    auto loadTile = [&](int it, int buf) {
        int k0 = it * 64;
        #pragma unroll
        for (int i = 0; i < 4; i++) {
            int c = tid + i * 256;
            int row = c >> 3, kq = c & 7;        // 128 rows x 8 16B-chunks
            cpa16(sAu + (uint32_t)(buf*HTILE + row*ASH + kq*8) * 2,
                  A + (size_t)(bm + row) * K + k0 + kq * 8);
            cpa16(sBu + (uint32_t)(buf*HTILE + row*ASH + kq*8) * 2,
                  Bt + (size_t)(bn + row) * K + k0 + kq * 8);
        }
        CP_COMMIT();
    };

    loadTile(0, 0);
    loadTile(1, 1);

    for (int it = 0; it < niter; ++it) {
        CP_WAIT1();
        __syncthreads();
        if (it + 2 < niter) loadTile(it + 2, (it + 2) % 3);
        else CP_COMMIT();

        uint32_t Abu = sAu + (uint32_t)((it % 3) * HTILE) * 2;
        uint32_t Bbu = sBu + (uint32_t)((it % 3) * HTILE) * 2;
        #pragma unroll
        for (int ks = 0; ks < 64; ks += 16) {
            uint32_t af[4][4], bf[4][2];
            #pragma unroll
            for (int mf = 0; mf < 4; mf++) {
                uint32_t ad = Abu + (uint32_t)((wm + mf*16 + a_r) * ASH + ks + a_c) * 2;
                ldsm4(af[mf][0], af[mf][1], af[mf][2], af[mf][3], ad);
            }
            #pragma unroll
            for (int np = 0; np < 2; np++) {
                uint32_t bd = Bbu + (uint32_t)((wn + np*16 + b_r) * ASH + ks + b_c) * 2;
                ldsm4(bf[2*np][0], bf[2*np][1], bf[2*np+1][0], bf[2*np+1][1], bd);
            }
            #pragma unroll
            for (int mf = 0; mf < 4; mf++)
                #pragma unroll
                for (int nf = 0; nf < 4; nf++)
                    mma_f16(acc[mf][nf], af[mf][0], af[mf][1], af[mf][2], af[mf][3],
                            bf[nf][0], bf[nf][1]);
        }
    }

    #pragma unroll
    for (int mf = 0; mf < 4; mf++) {
        #pragma unroll
        for (int nf = 0; nf < 4; nf++) {
            int r = bm + wm + mf*16 + grp;
            int c = bn + wn + nf*8 + tig*2;
            float2 v0 = make_float2(acc[mf][nf][0], acc[mf][nf][1]);
            float2 v1 = make_float2(acc[mf][nf][2], acc[mf][nf][3]);
            if (MODE == 2) {
                int j = c >> 1;
                float bv = bias[j], bg = bias[FFd + j];
                float val0 = v0.x + bv, gat0 = v0.y + bg;
                float val1 = v1.x + bv, gat1 = v1.y + bg;
                float o0 = val0 * (0.5f * gat0 * (1.f + erff(gat0 * 0.70710678118654752f)));
                float o1 = val1 * (0.5f * gat1 * (1.f + erff(gat1 * 0.70710678118654752f)));
                __half* C = (__half*)Cv;
                C[(size_t)r * FFd + j]     = __float2half(o0);
                C[(size_t)(r+8) * FFd + j] = __float2half(o1);
            } else {
                if (bias) {
                    float2 bb = *(const float2*)(bias + c);
                    v0.x += bb.x; v0.y += bb.y; v1.x += bb.x; v1.y += bb.y;
                }
                if (MODE == 0 && res) {
                    float2 r0 = *(const float2*)(res + (size_t)r * N + c);
                    float2 r1 = *(const float2*)(res + (size_t)(r+8) * N + c);
                    v0.x += r0.x; v0.y += r0.y; v1.x += r1.x; v1.y += r1.y;
                }
                if (MODE == 1) {
                    __half* C = (__half*)Cv;
                    *(__half2*)(C + (size_t)r * N + c)     = __floats2half2_rn(v0.x, v0.y);
                    *(__half2*)(C + (size_t)(r+8) * N + c) = __floats2half2_rn(v1.x, v1.y);
                } else {
                    float* C = (float*)Cv;
                    *(float2*)(C + (size_t)r * N + c)     = v0;
                    *(float2*)(C + (size_t)(r+8) * N + c) = v1;
                }
            }
        }
    }
}

// ================= fp16 flash attention (self-attn, strided QKV) ============
#define QSH 72
#define VSH 136
#define PSH 136
#define FLH_SMEM ((2*128*QSH + 64*VSH + 128*PSH)*2)

__global__ __launch_bounds__(256, 2)
void flash_h(const __half* __restrict__ qkv, __half* __restrict__ o) {
    extern __shared__ __half smf[];
    __half* Qs = smf;
    __half* Ks = Qs + 128*QSH;
    __half* Vt = Ks + 128*QSH;
    __half* Ps = Vt + 64*VSH;
    uint32_t Ksu = (uint32_t)__cvta_generic_to_shared(Ks);
    uint32_t Vtu = (uint32_t)__cvta_generic_to_shared(Vt);
    uint32_t Psu = (uint32_t)__cvta_generic_to_shared(Ps);

    const int ldq = 3*Dm;
    int qt = blockIdx.x, bh = blockIdx.y;
    int b = bh >> 4, h = bh & 15;
    int tid = threadIdx.x, warp = tid >> 5, lane = tid & 31;
    int grp = lane >> 2, tig = lane & 3;
    int sel = lane >> 3, lrow = lane & 7;
    int a_r = (sel & 1) * 8 + lrow, a_c = (sel >> 1) * 8;
    int b_r = (sel >> 1) * 8 + lrow, b_c = (sel & 1) * 8;

    const __half* qb = qkv + ((size_t)b*SEQ + qt*128) * ldq + h*DHd;
    const __half* kb = qkv + (size_t)b*SEQ*ldq + Dm + h*DHd;
    const __half* vb = qkv + (size_t)b*SEQ*ldq + 2*Dm + h*DHd;

    {
        int row = tid >> 1, part = tid & 1;
        const float4* s4 = (const float4*)(qb + (size_t)row * ldq + part*32);
        float4* d4 = (float4*)(Qs + row*QSH + part*32);
        #pragma unroll
        for (int i = 0; i < 4; i++) d4[i] = s4[i];
    }
    __syncthreads();

    uint32_t qf[4][4];
    {
        const __half* p = Qs + (warp*16 + grp) * QSH;
        #pragma unroll
        for (int ksi = 0; ksi < 4; ksi++) {
            qf[ksi][0] = *(const uint32_t*)(p + ksi*16 + tig*2);
            qf[ksi][1] = *(const uint32_t*)(p + 8*QSH + ksi*16 + tig*2);
            qf[ksi][2] = *(const uint32_t*)(p + ksi*16 + tig*2 + 8);
            qf[ksi][3] = *(const uint32_t*)(p + 8*QSH + ksi*16 + tig*2 + 8);
        }
    }

    float oacc[8][4] = {};
    float m0 = -1e30f, m1 = -1e30f, l0 = 0.f, l1 = 0.f;
    const float Csc = SCALE_ATTN * 1.4426950408889634f;
    int prow = warp*16 + grp;

    for (int kv0 = 0; kv0 < SEQ; kv0 += 128) {
        {
            int row = tid >> 1, part = tid & 1;
            const float4* s4 = (const float4*)(kb + (size_t)(kv0+row) * ldq + part*32);
            float4* d4 = (float4*)(Ks + row*QSH + part*32);
            #pragma unroll
            for (int i = 0; i < 4; i++) d4[i] = s4[i];
        }
        {
            int d = tid & 63;
            #pragma unroll
            for (int kvp = tid >> 6; kvp < 64; kvp += 4) {
                int kv = kvp * 2;
                __half v0 = vb[(size_t)(kv0 + kv)     * ldq + d];
                __half v1 = vb[(size_t)(kv0 + kv + 1) * ldq + d];
                *(__half2*)(Vt + d*VSH + kv) = __halves2half2(v0, v1);
            }
        }
        __syncthreads();

        float sacc[16][4] = {};
        #pragma unroll
        for (int ksi = 0; ksi < 4; ksi++) {
            #pragma unroll
            for (int np = 0; np < 8; np++) {
                uint32_t kd = Ksu + (uint32_t)((np*16 + b_r) * QSH + ksi*16 + b_c) * 2;
                uint32_t b00, b01, b10, b11;
                ldsm4(b00, b01, b10, b11, kd);
                mma_f16(sacc[2*np],   qf[ksi][0], qf[ksi][1], qf[ksi][2], qf[ksi][3], b00, b01);
                mma_f16(sacc[2*np+1], qf[ksi][0], qf[ksi][1], qf[ksi][2], qf[ksi][3], b10, b11);
            }
        }
        float mx0 = -1e30f, mx1 = -1e30f;
        #pragma unroll
        for (int nf = 0; nf < 16; nf++) {
            sacc[nf][0] *= Csc; sacc[nf][1] *= Csc; sacc[nf][2] *= Csc; sacc[nf][3] *= Csc;
            mx0 = fmaxf(mx0, fmaxf(sacc[nf][0], sacc[nf][1]));
            mx1 = fmaxf(mx1, fmaxf(sacc[nf][2], sacc[nf][3]));
        }
        mx0 = fmaxf(mx0, __shfl_xor_sync(0xffffffffu, mx0, 1));
        mx0 = fmaxf(mx0, __shfl_xor_sync(0xffffffffu, mx0, 2));
        mx1 = fmaxf(mx1, __shfl_xor_sync(0xffffffffu, mx1, 1));
        mx1 = fmaxf(mx1, __shfl_xor_sync(0xffffffffu, mx1, 2));
        float mn0 = fmaxf(m0, mx0), mn1 = fmaxf(m1, mx1);
        float sc0 = ex2f(m0 - mn0), sc1 = ex2f(m1 - mn1);
        float sum0 = 0.f, sum1 = 0.f;
        #pragma unroll
        for (int nf = 0; nf < 16; nf++) {
            float p0 = ex2f(sacc[nf][0] - mn0);
            float p1 = ex2f(sacc[nf][1] - mn0);
            float p2 = ex2f(sacc[nf][2] - mn1);
            float p3 = ex2f(sacc[nf][3] - mn1);
            sum0 += p0 + p1; sum1 += p2 + p3;
            int pc = nf*8 + tig*2;
            *(__half2*)(Ps + prow*PSH + pc)     = __floats2half2_rn(p0, p1);
            *(__half2*)(Ps + (prow+8)*PSH + pc) = __floats2half2_rn(p2, p3);
        }
        sum0 += __shfl_xor_sync(0xffffffffu, sum0, 1);
        sum0 += __shfl_xor_sync(0xffffffffu, sum0, 2);
        sum1 += __shfl_xor_sync(0xffffffffu, sum1, 1);
        sum1 += __shfl_xor_sync(0xffffffffu, sum1, 2);
        l0 = l0 * sc0 + sum0;  l1 = l1 * sc1 + sum1;
        m0 = mn0;  m1 = mn1;
        #pragma unroll
        for (int nf = 0; nf < 8; nf++) {
            oacc[nf][0] *= sc0; oacc[nf][1] *= sc0;
            oacc[nf][2] *= sc1; oacc[nf][3] *= sc1;
        }
        __syncwarp();

        #pragma unroll
        for (int ks = 0; ks < 8; ks++) {
            uint32_t pd = Psu + (uint32_t)((warp*16 + a_r) * PSH + ks*16 + a_c) * 2;
            uint32_t a0, a1, a2, a3;
            ldsm4(a0, a1, a2, a3, pd);
            #pragma unroll
            for (int np = 0; np < 4; np++) {
                uint32_t vd = Vtu + (uint32_t)((np*16 + b_r) * VSH + ks*16 + b_c) * 2;
                uint32_t b00, b01, b10, b11;
                ldsm4(b00, b01, b10, b11, vd);
                mma_f16(oacc[2*np],   a0, a1, a2, a3, b00, b01);
                mma_f16(oacc[2*np+1], a0, a1, a2, a3, b10, b11);
            }
        }
        __syncthreads();
    }

    float i0 = 1.f / l0, i1 = 1.f / l1;
    __half* ob = o + ((size_t)b*SEQ + qt*128 + warp*16) * Dm + h*DHd;
    #pragma unroll
    for (int nf = 0; nf < 8; nf++) {
        int c = nf*8 + tig*2;
        *(__half2*)(ob + (size_t)grp * Dm + c) =
            __floats2half2_rn(oacc[nf][0]*i0, oacc[nf][1]*i0);
        *(__half2*)(ob + (size_t)(grp+8) * Dm + c) =
            __floats2half2_rn(oacc[nf][2]*i1, oacc[nf][3]*i1);
    }
}

// ================= fp16 cross-attention (single KV tile, nk=77) =============
#define CKROWS 80
#define CVSH 88
#define CPSH 88
#define FLC_SMEM ((128*QSH + CKROWS*QSH + 64*CVSH + 128*CPSH)*2)

__global__ __launch_bounds__(256, 2)
void flash_cross(const __half* __restrict__ q, const __half* __restrict__ k,
                 const __half* __restrict__ v, __half* __restrict__ o) {
    extern __shared__ __half smc[];
    __half* Qs = smc;
    __half* Ks = Qs + 128*QSH;
    __half* Vt = Ks + CKROWS*QSH;
    __half* Ps = Vt + 64*CVSH;

    int qt = blockIdx.x, bh = blockIdx.y;
    int b = bh >> 4, h = bh & 15;
    int tid = threadIdx.x, warp = tid >> 5, lane = tid & 31;
    int grp = lane >> 2, tig = lane & 3;

    const __half* qb = q + ((size_t)b*SEQ + qt*128) * Dm + h*DHd;
    const __half* kb = k + (size_t)b*NCx*Dm + h*DHd;
    const __half* vb = v + (size_t)b*NCx*Dm + h*DHd;

    {
        int row = tid >> 1, part = tid & 1;
        const float4* s4 = (const float4*)(qb + (size_t)row * Dm + part*32);
        float4* d4 = (float4*)(Qs + row*QSH + part*32);
        #pragma unroll
        for (int i = 0; i < 4; i++) d4[i] = s4[i];
    }
    for (int rr = tid; rr < CKROWS*2; rr += 256) {
        int row = rr >> 1, part = rr & 1;
        float4* d4 = (float4*)(Ks + row*QSH + part*32);
        if (row < NCx) {
            const float4* s4 = (const float4*)(kb + (size_t)row * Dm + part*32);
            #pragma unroll
            for (int i = 0; i < 4; i++) d4[i] = s4[i];
        } else {
            float4 z = make_float4(0.f,0.f,0.f,0.f);
            #pragma unroll
            for (int i = 0; i < 4; i++) d4[i] = z;
        }
    }
    {
        int d = tid & 63;
        for (int kvp = tid >> 6; kvp < CKROWS/2; kvp += 4) {
            int kv = kvp * 2;
            __half v0 = (kv   < NCx) ? vb[(size_t)kv     * Dm + d] : __half(0.f);
            __half v1 = (kv+1 < NCx) ? vb[(size_t)(kv+1) * Dm + d] : __half(0.f);
            *(__half2*)(Vt + d*CVSH + kv) = __halves2half2(v0, v1);
        }
    }
    __syncthreads();

    uint32_t qf[4][4];
    {
        const __half* p = Qs + (warp*16 + grp) * QSH;
        #pragma unroll
        for (int ksi = 0; ksi < 4; ksi++) {
            qf[ksi][0] = *(const uint32_t*)(p + ksi*16 + tig*2);
            qf[ksi][1] = *(const uint32_t*)(p + 8*QSH + ksi*16 + tig*2);
            qf[ksi][2] = *(const uint32_t*)(p + ksi*16 + tig*2 + 8);
            qf[ksi][3] = *(const uint32_t*)(p + 8*QSH + ksi*16 + tig*2 + 8);
        }
    }

    const float Csc = SCALE_ATTN * 1.4426950408889634f;
    int prow = warp*16 + grp;

    float sacc[10][4] = {};
    #pragma unroll
    for (int ksi = 0; ksi < 4; ksi++) {
        #pragma unroll
        for (int nf = 0; nf < 10; nf++) {
            const __half* kp = Ks + (nf*8 + grp) * QSH + ksi*16;
            uint32_t b0 = *(const uint32_t*)(kp + tig*2);
            uint32_t b1 = *(const uint32_t*)(kp + tig*2 + 8);
            mma_f16(sacc[nf], qf[ksi][0], qf[ksi][1], qf[ksi][2], qf[ksi][3], b0, b1);
        }
    }
    float mx0 = -1e30f, mx1 = -1e30f;
    #pragma unroll
    for (int nf = 0; nf < 10; nf++) {
        int c0 = nf*8 + tig*2, c1 = c0 + 1;
        sacc[nf][0] = (c0 < NCx) ? sacc[nf][0]*Csc : -1e30f;
        sacc[nf][1] = (c1 < NCx) ? sacc[nf][1]*Csc : -1e30f;
        sacc[nf][2] = (c0 < NCx) ? sacc[nf][2]*Csc : -1e30f;
        sacc[nf][3] = (c1 < NCx) ? sacc[nf][3]*Csc : -1e30f;
        mx0 = fmaxf(mx0, fmaxf(sacc[nf][0], sacc[nf][1]));
        mx1 = fmaxf(mx1, fmaxf(sacc[nf][2], sacc[nf][3]));
    }
    mx0 = fmaxf(mx0, __shfl_xor_sync(0xffffffffu, mx0, 1));
    mx0 = fmaxf(mx0, __shfl_xor_sync(0xffffffffu, mx0, 2));
    mx1 = fmaxf(mx1, __shfl_xor_sync(0xffffffffu, mx1, 1));
    mx1 = fmaxf(mx1, __shfl_xor_sync(0xffffffffu, mx1, 2));

    float sum0 = 0.f, sum1 = 0.f;
    #pragma unroll
    for (int nf = 0; nf < 10; nf++) {
        float p0 = ex2f(sacc[nf][0] - mx0);
        float p1 = ex2f(sacc[nf][1] - mx0);
        float p2 = ex2f(sacc[nf][2] - mx1);
        float p3 = ex2f(sacc[nf][3] - mx1);
        sum0 += p0 + p1; sum1 += p2 + p3;
        int pc = nf*8 + tig*2;
        *(__half2*)(Ps + prow*CPSH + pc)     = __floats2half2_rn(p0, p1);
        *(__half2*)(Ps + (prow+8)*CPSH + pc) = __floats2half2_rn(p2, p3);
    }
    sum0 += __shfl_xor_sync(0xffffffffu, sum0, 1);
    sum0 += __shfl_xor_sync(0xffffffffu, sum0, 2);
    sum1 += __shfl_xor_sync(0xffffffffu, sum1, 1);
    sum1 += __shfl_xor_sync(0xffffffffu, sum1, 2);
    __syncwarp();

    float oacc[8][4] = {};
    #pragma unroll
    for (int ks = 0; ks < 5; ks++) {
        const __half* pp = Ps + prow*CPSH + ks*16;
        uint32_t a0 = *(const uint32_t*)(pp + tig*2);
        uint32_t a1 = *(const uint32_t*)(pp + 8*CPSH + tig*2);
        uint32_t a2 = *(const uint32_t*)(pp + tig*2 + 8);
        uint32_t a3 = *(const uint32_t*)(pp + 8*CPSH + tig*2 + 8);
        #pragma unroll
        for (int nf = 0; nf < 8; nf++) {
            const __half* vp = Vt + (nf*8 + grp) * CVSH + ks*16;
            uint32_t b0 = *(const uint32_t*)(vp + tig*2);
            uint32_t b1 = *(const uint32_t*)(vp + tig*2 + 8);
            mma_f16(oacc[nf], a0, a1, a2, a3, b0, b1);
        }
    }

    float i0 = 1.f / sum0, i1 = 1.f / sum1;
    __half* ob = o + ((size_t)b*SEQ + qt*128 + warp*16) * Dm + h*DHd;
    #pragma unroll
    for (int nf = 0; nf < 8; nf++) {
        int c = nf*8 + tig*2;
        *(__half2*)(ob + (size_t)grp * Dm + c) =
            __floats2half2_rn(oacc[nf][0]*i0, oacc[nf][1]*i0);
        *(__half2*)(ob + (size_t)(grp+8) * Dm + c) =
            __floats2half2_rn(oacc[nf][2]*i1, oacc[nf][3]*i1);
    }
}

// ---------------- small kernels ----------------
__global__ void ln_kernel(const float* __restrict__ x, const float* __restrict__ g,
                          const float* __restrict__ b, __half* __restrict__ out) {
    int row = blockIdx.x;
    const float* xr = x + (size_t)row * Dm;
    float s = 0.f, ss = 0.f;
    for (int i = threadIdx.x; i < Dm; i += 256) {
        float v = xr[i];
        s += v; ss += v * v;
    }
    __shared__ float rs[256], rss[256];
    rs[threadIdx.x] = s; rss[threadIdx.x] = ss;
    __syncthreads();
    for (int st = 128; st > 0; st >>= 1) {
        if (threadIdx.x < st) { rs[threadIdx.x] += rs[threadIdx.x+st]; rss[threadIdx.x] += rss[threadIdx.x+st]; }
        __syncthreads();
    }
    float mu  = rs[0] * (1.0f / Dm);
    float var = rss[0] * (1.0f / Dm) - mu * mu;
    float inv = rsqrtf(var + EPS_LN);
    __half* orow = out + (size_t)row * Dm;
    for (int i = threadIdx.x; i < Dm; i += 256)
        orow[i] = __float2half((xr[i] - mu) * inv * g[i] + b[i]);
}

// cross KV projections fused: z=0 -> K (w2_k), z=1 -> V (w2_v)
__global__ void gemm_kv_h(const float* __restrict__ A,
                          const float* __restrict__ Wk, const float* __restrict__ Wv,
                          __half* __restrict__ Ck, __half* __restrict__ Cv,
                          int M, int K, int Nn) {
    __shared__ float As[64][17];
    __shared__ float Bs[16][64];
    const float* Bm = (blockIdx.z == 0) ? Wk : Wv;
    __half* C = (blockIdx.z == 0) ? Ck : Cv;
    int bm = blockIdx.y * 64, bn = blockIdx.x * 64;
    int tx = threadIdx.x & 15, ty = threadIdx.x >> 4;
    float acc[4][4] = {};
    for (int k0 = 0; k0 < K; k0 += 16) {
        #pragma unroll
        for (int i = 0; i < 4; i++) {
            int idx = threadIdx.x + i * 256;
            int r = idx >> 4, kk = idx & 15;
            int gr = bm + r;
            As[r][kk] = (gr < M) ? A[(size_t)gr * K + k0 + kk] : 0.f;
            int kb = idx >> 6, c = idx & 63;
            int gc = bn + c;
            Bs[kb][c] = (gc < Nn) ? Bm[(size_t)(k0 + kb) * Nn + gc] : 0.f;
        }
        __syncthreads();
        #pragma unroll
        for (int kk = 0; kk < 16; kk++) {
            float a[4], bb[4];
            #pragma unroll
            for (int i = 0; i < 4; i++) a[i]  = As[ty*4+i][kk];
            #pragma unroll
            for (int j = 0; j < 4; j++) bb[j] = Bs[kk][tx*4+j];
            #pragma unroll
            for (int i = 0; i < 4; i++)
                #pragma unroll
                for (int j = 0; j < 4; j++)
                    acc[i][j] += a[i] * bb[j];
        }
        __syncthreads();
    }
    #pragma unroll
    for (int i = 0; i < 4; i++) {
        int gr = bm + ty*4 + i;
        if (gr >= M) continue;
        #pragma unroll
        for (int j = 0; j < 4; j++) {
            int gc = bn + tx*4 + j;
            if (gc >= Nn) continue;
            C[(size_t)gr * Nn + gc] = __float2half(acc[i][j]);
        }
    }
}

// ---------------- launch ----------------
extern "C" void kernel_launch(void* const* d_in, const int* in_sizes, int n_in,
                              void* d_out, int out_size) {
    const float* x      = (const float*)d_in[0];
    const float* ctx    = (const float*)d_in[1];
    const float* w1_q   = (const float*)d_in[2];
    const float* w1_k   = (const float*)d_in[3];
    const float* w1_v   = (const float*)d_in[4];
    const float* w1_o   = (const float*)d_in[5];
    const float* b1_o   = (const float*)d_in[6];
    const float* w2_q   = (const float*)d_in[7];
    const float* w2_k   = (const float*)d_in[8];
    const float* w2_v   = (const float*)d_in[9];
    const float* w2_o   = (const float*)d_in[10];
    const float* b2_o   = (const float*)d_in[11];
    const float* ln1_g  = (const float*)d_in[12];
    const float* ln1_b  = (const float*)d_in[13];
    const float* ln2_g  = (const float*)d_in[14];
    const float* ln2_b  = (const float*)d_in[15];
    const float* ln3_g  = (const float*)d_in[16];
    const float* ln3_b  = (const float*)d_in[17];
    const float* ff_w1  = (const float*)d_in[18];
    const float* ff_b1  = (const float*)d_in[19];
    const float* ff_w2  = (const float*)d_in[20];
    const float* ff_b2  = (const float*)d_in[21];
    float* xbuf = (float*)d_out;

    __half *hh, *qkvh, *kh, *vh, *atth, *th, *wh;
    cudaGetSymbolAddress((void**)&hh,   g_hh);
    cudaGetSymbolAddress((void**)&qkvh, g_qkv);
    cudaGetSymbolAddress((void**)&kh,   g_kh);
    cudaGetSymbolAddress((void**)&vh,   g_vh);
    cudaGetSymbolAddress((void**)&atth, g_atth);
    cudaGetSymbolAddress((void**)&th,   g_th);
    cudaGetSymbolAddress((void**)&wh,   g_wh);

    cudaFuncSetAttribute(gemm_h<0>, cudaFuncAttributeMaxDynamicSharedMemorySize, GH_SMEM);
    cudaFuncSetAttribute(gemm_h<1>, cudaFuncAttributeMaxDynamicSharedMemorySize, GH_SMEM);
    cudaFuncSetAttribute(gemm_h<2>, cudaFuncAttributeMaxDynamicSharedMemorySize, GH_SMEM);
    cudaFuncSetAttribute(flash_h,     cudaFuncAttributeMaxDynamicSharedMemorySize, FLH_SMEM);
    cudaFuncSetAttribute(flash_cross, cudaFuncAttributeMaxDynamicSharedMemorySize, FLC_SMEM);

    dim3 gD(Dm/128, MROWS/128);
    dim3 gQKV(3*Dm/128, MROWS/128);
    dim3 gFF1(2*FFd/128, MROWS/128);
    dim3 gFlash(SEQ/128, Bq*Hh);
    dim3 tpb(32, 8);

    transpose_half<<<dim3(Dm/32,   Dm/32),  tpb>>>(w1_q,  wh+OWQKV,             Dm,  Dm);
    transpose_half<<<dim3(Dm/32,   Dm/32),  tpb>>>(w1_k,  wh+OWQKV+1024*1024,   Dm,  Dm);
    transpose_half<<<dim3(Dm/32,   Dm/32),  tpb>>>(w1_v,  wh+OWQKV+2*1024*1024, Dm,  Dm);
    transpose_half<<<dim3(Dm/32,   Dm/32),  tpb>>>(w1_o,  wh+OW1O, Dm,  Dm);
    transpose_half<<<dim3(Dm/32,   Dm/32),  tpb>>>(w2_q,  wh+OW2Q, Dm,  Dm);
    transpose_half<<<dim3(Dm/32,   Dm/32),  tpb>>>(w2_o,  wh+OW2O, Dm,  Dm);
    transpose_geglu<<<dim3(2*FFd/32, Dm/32), tpb>>>(ff_w1, wh+OFW1, Dm,  2*FFd);
    transpose_half<<<dim3(Dm/32,  FFd/32),  tpb>>>(ff_w2, wh+OFW2, FFd, Dm);

    // ---- self attention (ln1 reads x; W1O uses res=x, writes xbuf fully) ----
    ln_kernel<<<MROWS, 256>>>(x, ln1_g, ln1_b, hh);
    gemm_h<1><<<gQKV, 256, GH_SMEM>>>(hh, wh+OWQKV, nullptr, nullptr, qkvh, MROWS, 3*Dm, Dm);
    flash_h<<<gFlash, 256, FLH_SMEM>>>(qkvh, atth);
    gemm_h<0><<<gD, 256, GH_SMEM>>>(atth, wh+OW1O, b1_o, x, xbuf, MROWS, Dm, Dm);

    // ---- cross attention ----
    ln_kernel<<<MROWS, 256>>>(xbuf, ln2_g, ln2_b, hh);
    gemm_h<1><<<gD, 256, GH_SMEM>>>(hh, wh+OW2Q, nullptr, nullptr, atth, MROWS, Dm, Dm);
    dim3 gKV(Dm/64, (CROWS+63)/64, 2);
    gemm_kv_h<<<gKV, 256>>>(ctx, w2_k, w2_v, kh, vh, CROWS, DCx, Dm);
    flash_cross<<<gFlash, 256, FLC_SMEM>>>(atth, kh, vh, qkvh);
    gemm_h<0><<<gD, 256, GH_SMEM>>>(qkvh, wh+OW2O, b2_o, xbuf, xbuf, MROWS, Dm, Dm);

    // ---- GEGLU FFN ----
    ln_kernel<<<MROWS, 256>>>(xbuf, ln3_g, ln3_b, hh);
    gemm_h<2><<<gFF1, 256, GH_SMEM>>>(hh, wh+OFW1, ff_b1, nullptr, th, MROWS, 2*FFd, Dm);
    gemm_h<0><<<gD, 256, GH_SMEM>>>(th, wh+OFW2, ff_b2, xbuf, xbuf, MROWS, Dm, FFd);
}

// round 10
// speedup vs baseline: 2.5113x; 1.0248x over previous
#include <cuda_runtime.h>
#include <cuda_fp16.h>
#include <math.h>
#include <stdint.h>

#define Bq 2
#define SEQ 2048
#define Dm 1024
#define NCx 77
#define DCx 768
#define Hh 16
#define DHd 64
#define FFd 4096
#define SCALE_ATTN 0.125f
#define EPS_LN 1e-5f
#define MROWS (Bq*SEQ)          // 4096
#define CROWS (Bq*NCx)          // 154

// ---------------- scratch ----------------
__device__ __half g_hh[(size_t)MROWS*Dm];
__device__ __half g_qkv[(size_t)MROWS*3*Dm];
__device__ __half g_kh[(size_t)CROWS*Dm + 1024];
__device__ __half g_vh[(size_t)CROWS*Dm + 1024];
__device__ __half g_atth[(size_t)MROWS*Dm];
__device__ __half g_th[(size_t)MROWS*FFd];
__device__ __half g_wh[(size_t)18874368];        // transposed half weights [N,K]

#define OWQKV 0
#define OW1O 3145728
#define OW2Q 4194304
#define OW2O 5242880
#define OFW1 6291456
#define OFW2 14680064

// ---------------- helpers ----------------
__device__ __forceinline__ float ex2f(float x) {
    float y;
    asm("ex2.approx.f32 %0, %1;" : "=f"(y) : "f"(x));
    return y;
}
__device__ __forceinline__ void mma_f16(float c[4],
                                        uint32_t a0, uint32_t a1, uint32_t a2, uint32_t a3,
                                        uint32_t b0, uint32_t b1) {
    asm volatile(
        "mma.sync.aligned.m16n8k16.row.col.f32.f16.f16.f32 "
        "{%0,%1,%2,%3}, {%4,%5,%6,%7}, {%8,%9}, {%0,%1,%2,%3};"
        : "+f"(c[0]), "+f"(c[1]), "+f"(c[2]), "+f"(c[3])
        : "r"(a0), "r"(a1), "r"(a2), "r"(a3), "r"(b0), "r"(b1));
}
__device__ __forceinline__ void ldsm4(uint32_t& r0, uint32_t& r1, uint32_t& r2, uint32_t& r3,
                                      uint32_t addr) {
    asm volatile("ldmatrix.sync.aligned.m8n8.x4.shared.b16 {%0,%1,%2,%3}, [%4];"
                 : "=r"(r0), "=r"(r1), "=r"(r2), "=r"(r3) : "r"(addr));
}
__device__ __forceinline__ void ldsm4t(uint32_t& r0, uint32_t& r1, uint32_t& r2, uint32_t& r3,
                                       uint32_t addr) {
    asm volatile("ldmatrix.sync.aligned.m8n8.x4.trans.shared.b16 {%0,%1,%2,%3}, [%4];"
                 : "=r"(r0), "=r"(r1), "=r"(r2), "=r"(r3) : "r"(addr));
}
__device__ __forceinline__ void cpa16(uint32_t dst, const void* src) {
    asm volatile("cp.async.cg.shared.global [%0], [%1], 16;" :: "r"(dst), "l"(src));
}
#define CP_COMMIT() asm volatile("cp.async.commit_group;")
#define CP_WAIT1()  asm volatile("cp.async.wait_group 1;")

// ---------------- weight transpose + fp16 convert ----------------
// z-batched: 6 square Dm x Dm weights in one launch
__global__ void transpose_half6(const float* s0, const float* s1, const float* s2,
                                const float* s3, const float* s4, const float* s5,
                                __half* d0, __half* d1, __half* d2,
                                __half* d3, __half* d4, __half* d5) {
    const float* src; __half* dst;
    switch (blockIdx.z) {
        case 0: src = s0; dst = d0; break;
        case 1: src = s1; dst = d1; break;
        case 2: src = s2; dst = d2; break;
        case 3: src = s3; dst = d3; break;
        case 4: src = s4; dst = d4; break;
        default: src = s5; dst = d5; break;
    }
    __shared__ float t[32][33];
    int bx = blockIdx.x * 32;
    int by = blockIdx.y * 32;
    int x = bx + threadIdx.x;
    #pragma unroll
    for (int i = 0; i < 32; i += 8) {
        int y = by + threadIdx.y + i;
        t[threadIdx.y + i][threadIdx.x] = src[(size_t)y * Dm + x];
    }
    __syncthreads();
    int kx = by + threadIdx.x;
    #pragma unroll
    for (int i = 0; i < 32; i += 8) {
        int ny = bx + threadIdx.y + i;
        dst[(size_t)ny * Dm + kx] = __float2half(t[threadIdx.x][threadIdx.y + i]);
    }
}
__global__ void transpose_half(const float* __restrict__ src, __half* __restrict__ dst,
                               int K, int N) {
    __shared__ float t[32][33];
    int bx = blockIdx.x * 32;
    int by = blockIdx.y * 32;
    int x = bx + threadIdx.x;
    #pragma unroll
    for (int i = 0; i < 32; i += 8) {
        int y = by + threadIdx.y + i;
        t[threadIdx.y + i][threadIdx.x] = src[(size_t)y * N + x];
    }
    __syncthreads();
    int kx = by + threadIdx.x;
    #pragma unroll
    for (int i = 0; i < 32; i += 8) {
        int ny = bx + threadIdx.y + i;
        dst[(size_t)ny * K + kx] = __float2half(t[threadIdx.x][threadIdx.y + i]);
    }
}
__global__ void transpose_geglu(const float* __restrict__ src, __half* __restrict__ dst,
                                int K, int N) {
    __shared__ float t[32][33];
    int bx = blockIdx.x * 32;
    int by = blockIdx.y * 32;
    int x = bx + threadIdx.x;
    #pragma unroll
    for (int i = 0; i < 32; i += 8) {
        int y = by + threadIdx.y + i;
        t[threadIdx.y + i][threadIdx.x] = src[(size_t)y * N + x];
    }
    __syncthreads();
    int kx = by + threadIdx.x;
    #pragma unroll
    for (int i = 0; i < 32; i += 8) {
        int ny = bx + threadIdx.y + i;
        int iny = (ny < FFd) ? (2*ny) : (2*(ny - FFd) + 1);
        dst[(size_t)iny * K + kx] = __float2half(t[threadIdx.x][threadIdx.y + i]);
    }
}

// ================= fp16 dense GEMM (ldmatrix, BK=64, 3-stage) ===============
#define ASH 72
#define HTILE (128*ASH)
#define GH_SMEM (3*2*HTILE*2)

template<int MODE>
__global__ __launch_bounds__(256, 2)
void gemm_h(const __half* __restrict__ A, const __half* __restrict__ Bt,
            const float* __restrict__ bias, const float* __restrict__ res,
            void* __restrict__ Cv, int M, int N, int K) {
    extern __shared__ __half smh[];
    __half* As = smh;
    __half* Bs = smh + 3*HTILE;
    int bm = blockIdx.y * 128, bn = blockIdx.x * 128;
    int tid = threadIdx.x, warp = tid >> 5, lane = tid & 31;
    int grp = lane >> 2, tig = lane & 3;
    int wm = (warp >> 2) * 64, wn = (warp & 3) * 32;
    int sel = lane >> 3, lrow = lane & 7;
    int a_r = (sel & 1) * 8 + lrow, a_c = (sel >> 1) * 8;
    int b_r = (sel >> 1) * 8 + lrow, b_c = (sel & 1) * 8;
    uint32_t sAu = (uint32_t)__cvta_generic_to_shared(As);
    uint32_t sBu = (uint32_t)__cvta_generic_to_shared(Bs);
    int niter = K >> 6;

    float acc[4][4][4] = {};

    auto loadTile = [&](int it, int buf) {
        int k0 = it * 64;
        #pragma unroll
        for (int i = 0; i < 4; i++) {
            int c = tid + i * 256;
            int row = c >> 3, kq = c & 7;
            cpa16(sAu + (uint32_t)(buf*HTILE + row*ASH + kq*8) * 2,
                  A + (size_t)(bm + row) * K + k0 + kq * 8);
            cpa16(sBu + (uint32_t)(buf*HTILE + row*ASH + kq*8) * 2,
                  Bt + (size_t)(bn + row) * K + k0 + kq * 8);
        }
        CP_COMMIT();
    };

    loadTile(0, 0);
    loadTile(1, 1);

    for (int it = 0; it < niter; ++it) {
        CP_WAIT1();
        __syncthreads();
        if (it + 2 < niter) loadTile(it + 2, (it + 2) % 3);
        else CP_COMMIT();

        uint32_t Abu = sAu + (uint32_t)((it % 3) * HTILE) * 2;
        uint32_t Bbu = sBu + (uint32_t)((it % 3) * HTILE) * 2;
        #pragma unroll
        for (int ks = 0; ks < 64; ks += 16) {
            uint32_t af[4][4], bf[4][2];
            #pragma unroll
            for (int mf = 0; mf < 4; mf++) {
                uint32_t ad = Abu + (uint32_t)((wm + mf*16 + a_r) * ASH + ks + a_c) * 2;
                ldsm4(af[mf][0], af[mf][1], af[mf][2], af[mf][3], ad);
            }
            #pragma unroll
            for (int np = 0; np < 2; np++) {
                uint32_t bd = Bbu + (uint32_t)((wn + np*16 + b_r) * ASH + ks + b_c) * 2;
                ldsm4(bf[2*np][0], bf[2*np][1], bf[2*np+1][0], bf[2*np+1][1], bd);
            }
            #pragma unroll
            for (int mf = 0; mf < 4; mf++)
                #pragma unroll
                for (int nf = 0; nf < 4; nf++)
                    mma_f16(acc[mf][nf], af[mf][0], af[mf][1], af[mf][2], af[mf][3],
                            bf[nf][0], bf[nf][1]);
        }
    }

    #pragma unroll
    for (int mf = 0; mf < 4; mf++) {
        #pragma unroll
        for (int nf = 0; nf < 4; nf++) {
            int r = bm + wm + mf*16 + grp;
            int c = bn + wn + nf*8 + tig*2;
            float2 v0 = make_float2(acc[mf][nf][0], acc[mf][nf][1]);
            float2 v1 = make_float2(acc[mf][nf][2], acc[mf][nf][3]);
            if (MODE == 2) {
                int j = c >> 1;
                float bv = bias[j], bg = bias[FFd + j];
                float val0 = v0.x + bv, gat0 = v0.y + bg;
                float val1 = v1.x + bv, gat1 = v1.y + bg;
                float o0 = val0 * (0.5f * gat0 * (1.f + erff(gat0 * 0.70710678118654752f)));
                float o1 = val1 * (0.5f * gat1 * (1.f + erff(gat1 * 0.70710678118654752f)));
                __half* C = (__half*)Cv;
                C[(size_t)r * FFd + j]     = __float2half(o0);
                C[(size_t)(r+8) * FFd + j] = __float2half(o1);
            } else {
                if (bias) {
                    float2 bb = *(const float2*)(bias + c);
                    v0.x += bb.x; v0.y += bb.y; v1.x += bb.x; v1.y += bb.y;
                }
                if (MODE == 0 && res) {
                    float2 r0 = *(const float2*)(res + (size_t)r * N + c);
                    float2 r1 = *(const float2*)(res + (size_t)(r+8) * N + c);
                    v0.x += r0.x; v0.y += r0.y; v1.x += r1.x; v1.y += r1.y;
                }
                if (MODE == 1) {
                    __half* C = (__half*)Cv;
                    *(__half2*)(C + (size_t)r * N + c)     = __floats2half2_rn(v0.x, v0.y);
                    *(__half2*)(C + (size_t)(r+8) * N + c) = __floats2half2_rn(v1.x, v1.y);
                } else {
                    float* C = (float*)Cv;
                    *(float2*)(C + (size_t)r * N + c)     = v0;
                    *(float2*)(C + (size_t)(r+8) * N + c) = v1;
                }
            }
        }
    }
}

// ================= fp16 flash attention (self-attn, strided QKV) ============
// V now stored ROW-major like K; PV uses ldmatrix.trans fragments.
#define QSH 72
#define PSH 136
#define FLH_SMEM ((3*128*QSH + 128*PSH)*2)

__global__ __launch_bounds__(256, 2)
void flash_h(const __half* __restrict__ qkv, __half* __restrict__ o) {
    extern __shared__ __half smf[];
    __half* Qs = smf;
    __half* Ks = Qs + 128*QSH;
    __half* Vs = Ks + 128*QSH;          // [kv][d] row-major
    __half* Ps = Vs + 128*QSH;
    uint32_t Ksu = (uint32_t)__cvta_generic_to_shared(Ks);
    uint32_t Vsu = (uint32_t)__cvta_generic_to_shared(Vs);
    uint32_t Psu = (uint32_t)__cvta_generic_to_shared(Ps);

    const int ldq = 3*Dm;
    int qt = blockIdx.x, bh = blockIdx.y;
    int b = bh >> 4, h = bh & 15;
    int tid = threadIdx.x, warp = tid >> 5, lane = tid & 31;
    int grp = lane >> 2, tig = lane & 3;
    int sel = lane >> 3, lrow = lane & 7;
    int a_r = (sel & 1) * 8 + lrow, a_c = (sel >> 1) * 8;
    int b_r = (sel >> 1) * 8 + lrow, b_c = (sel & 1) * 8;

    const __half* qb = qkv + ((size_t)b*SEQ + qt*128) * ldq + h*DHd;
    const __half* kb = qkv + (size_t)b*SEQ*ldq + Dm + h*DHd;
    const __half* vb = qkv + (size_t)b*SEQ*ldq + 2*Dm + h*DHd;

    {
        int row = tid >> 1, part = tid & 1;
        const float4* s4 = (const float4*)(qb + (size_t)row * ldq + part*32);
        float4* d4 = (float4*)(Qs + row*QSH + part*32);
        #pragma unroll
        for (int i = 0; i < 4; i++) d4[i] = s4[i];
    }
    __syncthreads();

    uint32_t qf[4][4];
    {
        const __half* p = Qs + (warp*16 + grp) * QSH;
        #pragma unroll
        for (int ksi = 0; ksi < 4; ksi++) {
            qf[ksi][0] = *(const uint32_t*)(p + ksi*16 + tig*2);
            qf[ksi][1] = *(const uint32_t*)(p + 8*QSH + ksi*16 + tig*2);
            qf[ksi][2] = *(const uint32_t*)(p + ksi*16 + tig*2 + 8);
            qf[ksi][3] = *(const uint32_t*)(p + 8*QSH + ksi*16 + tig*2 + 8);
        }
    }

    float oacc[8][4] = {};
    float m0 = -1e30f, m1 = -1e30f, l0 = 0.f, l1 = 0.f;
    const float Csc = SCALE_ATTN * 1.4426950408889634f;
    int prow = warp*16 + grp;

    for (int kv0 = 0; kv0 < SEQ; kv0 += 128) {
        // K and V tiles: identical vectorized row loads
        {
            int row = tid >> 1, part = tid & 1;
            const float4* sk = (const float4*)(kb + (size_t)(kv0+row) * ldq + part*32);
            const float4* sv = (const float4*)(vb + (size_t)(kv0+row) * ldq + part*32);
            float4* dk = (float4*)(Ks + row*QSH + part*32);
            float4* dv = (float4*)(Vs + row*QSH + part*32);
            #pragma unroll
            for (int i = 0; i < 4; i++) { dk[i] = sk[i]; dv[i] = sv[i]; }
        }
        __syncthreads();

        float sacc[16][4] = {};
        #pragma unroll
        for (int ksi = 0; ksi < 4; ksi++) {
            #pragma unroll
            for (int np = 0; np < 8; np++) {
                uint32_t kd = Ksu + (uint32_t)((np*16 + b_r) * QSH + ksi*16 + b_c) * 2;
                uint32_t b00, b01, b10, b11;
                ldsm4(b00, b01, b10, b11, kd);
                mma_f16(sacc[2*np],   qf[ksi][0], qf[ksi][1], qf[ksi][2], qf[ksi][3], b00, b01);
                mma_f16(sacc[2*np+1], qf[ksi][0], qf[ksi][1], qf[ksi][2], qf[ksi][3], b10, b11);
            }
        }
        float mx0 = -1e30f, mx1 = -1e30f;
        #pragma unroll
        for (int nf = 0; nf < 16; nf++) {
            sacc[nf][0] *= Csc; sacc[nf][1] *= Csc; sacc[nf][2] *= Csc; sacc[nf][3] *= Csc;
            mx0 = fmaxf(mx0, fmaxf(sacc[nf][0], sacc[nf][1]));
            mx1 = fmaxf(mx1, fmaxf(sacc[nf][2], sacc[nf][3]));
        }
        mx0 = fmaxf(mx0, __shfl_xor_sync(0xffffffffu, mx0, 1));
        mx0 = fmaxf(mx0, __shfl_xor_sync(0xffffffffu, mx0, 2));
        mx1 = fmaxf(mx1, __shfl_xor_sync(0xffffffffu, mx1, 1));
        mx1 = fmaxf(mx1, __shfl_xor_sync(0xffffffffu, mx1, 2));
        float mn0 = fmaxf(m0, mx0), mn1 = fmaxf(m1, mx1);
        float sc0 = ex2f(m0 - mn0), sc1 = ex2f(m1 - mn1);
        float sum0 = 0.f, sum1 = 0.f;
        #pragma unroll
        for (int nf = 0; nf < 16; nf++) {
            float p0 = ex2f(sacc[nf][0] - mn0);
            float p1 = ex2f(sacc[nf][1] - mn0);
            float p2 = ex2f(sacc[nf][2] - mn1);
            float p3 = ex2f(sacc[nf][3] - mn1);
            sum0 += p0 + p1; sum1 += p2 + p3;
            int pc = nf*8 + tig*2;
            *(__half2*)(Ps + prow*PSH + pc)     = __floats2half2_rn(p0, p1);
            *(__half2*)(Ps + (prow+8)*PSH + pc) = __floats2half2_rn(p2, p3);
        }
        sum0 += __shfl_xor_sync(0xffffffffu, sum0, 1);
        sum0 += __shfl_xor_sync(0xffffffffu, sum0, 2);
        sum1 += __shfl_xor_sync(0xffffffffu, sum1, 1);
        sum1 += __shfl_xor_sync(0xffffffffu, sum1, 2);
        l0 = l0 * sc0 + sum0;  l1 = l1 * sc1 + sum1;
        m0 = mn0;  m1 = mn1;
        #pragma unroll
        for (int nf = 0; nf < 8; nf++) {
            oacc[nf][0] *= sc0; oacc[nf][1] *= sc0;
            oacc[nf][2] *= sc1; oacc[nf][3] *= sc1;
        }
        __syncwarp();

        // O += P V  — P via ldsm4, V via ldsm4.trans on row-major [kv][d]
        #pragma unroll
        for (int ks = 0; ks < 8; ks++) {
            uint32_t pd = Psu + (uint32_t)((warp*16 + a_r) * PSH + ks*16 + a_c) * 2;
            uint32_t a0, a1, a2, a3;
            ldsm4(a0, a1, a2, a3, pd);
            #pragma unroll
            for (int np = 0; np < 4; np++) {
                uint32_t vd = Vsu + (uint32_t)((ks*16 + a_r) * QSH + np*16 + a_c) * 2;
                uint32_t b00, b01, b10, b11;
                ldsm4t(b00, b01, b10, b11, vd);
                mma_f16(oacc[2*np],   a0, a1, a2, a3, b00, b01);
                mma_f16(oacc[2*np+1], a0, a1, a2, a3, b10, b11);
            }
        }
        __syncthreads();
    }

    float i0 = 1.f / l0, i1 = 1.f / l1;
    __half* ob = o + ((size_t)b*SEQ + qt*128 + warp*16) * Dm + h*DHd;
    #pragma unroll
    for (int nf = 0; nf < 8; nf++) {
        int c = nf*8 + tig*2;
        *(__half2*)(ob + (size_t)grp * Dm + c) =
            __floats2half2_rn(oacc[nf][0]*i0, oacc[nf][1]*i0);
        *(__half2*)(ob + (size_t)(grp+8) * Dm + c) =
            __floats2half2_rn(oacc[nf][2]*i1, oacc[nf][3]*i1);
    }
}

// ================= fp16 cross-attention (single KV tile, nk=77) =============
#define CKROWS 80
#define CPSH 88
#define FLC_SMEM ((128*QSH + 2*CKROWS*QSH + 128*CPSH)*2)

__global__ __launch_bounds__(256, 2)
void flash_cross(const __half* __restrict__ q, const __half* __restrict__ k,
                 const __half* __restrict__ v, __half* __restrict__ o) {
    extern __shared__ __half smc[];
    __half* Qs = smc;
    __half* Ks = Qs + 128*QSH;          // [80][QSH]
    __half* Vs = Ks + CKROWS*QSH;       // [80][QSH] row-major
    __half* Ps = Vs + CKROWS*QSH;
    uint32_t Vsu = (uint32_t)__cvta_generic_to_shared(Vs);
    uint32_t Psu = (uint32_t)__cvta_generic_to_shared(Ps);

    int qt = blockIdx.x, bh = blockIdx.y;
    int b = bh >> 4, h = bh & 15;
    int tid = threadIdx.x, warp = tid >> 5, lane = tid & 31;
    int grp = lane >> 2, tig = lane & 3;
    int sel = lane >> 3, lrow = lane & 7;
    int a_r = (sel & 1) * 8 + lrow, a_c = (sel >> 1) * 8;

    const __half* qb = q + ((size_t)b*SEQ + qt*128) * Dm + h*DHd;
    const __half* kb = k + (size_t)b*NCx*Dm + h*DHd;
    const __half* vb = v + (size_t)b*NCx*Dm + h*DHd;

    {
        int row = tid >> 1, part = tid & 1;
        const float4* s4 = (const float4*)(qb + (size_t)row * Dm + part*32);
        float4* d4 = (float4*)(Qs + row*QSH + part*32);
        #pragma unroll
        for (int i = 0; i < 4; i++) d4[i] = s4[i];
    }
    for (int rr = tid; rr < CKROWS*2; rr += 256) {
        int row = rr >> 1, part = rr & 1;
        float4* dk = (float4*)(Ks + row*QSH + part*32);
        float4* dv = (float4*)(Vs + row*QSH + part*32);
        if (row < NCx) {
            const float4* sk = (const float4*)(kb + (size_t)row * Dm + part*32);
            const float4* sv = (const float4*)(vb + (size_t)row * Dm + part*32);
            #pragma unroll
            for (int i = 0; i < 4; i++) { dk[i] = sk[i]; dv[i] = sv[i]; }
        } else {
            float4 z = make_float4(0.f,0.f,0.f,0.f);
            #pragma unroll
            for (int i = 0; i < 4; i++) { dk[i] = z; dv[i] = z; }
        }
    }
    __syncthreads();

    uint32_t qf[4][4];
    {
        const __half* p = Qs + (warp*16 + grp) * QSH;
        #pragma unroll
        for (int ksi = 0; ksi < 4; ksi++) {
            qf[ksi][0] = *(const uint32_t*)(p + ksi*16 + tig*2);
            qf[ksi][1] = *(const uint32_t*)(p + 8*QSH + ksi*16 + tig*2);
            qf[ksi][2] = *(const uint32_t*)(p + ksi*16 + tig*2 + 8);
            qf[ksi][3] = *(const uint32_t*)(p + 8*QSH + ksi*16 + tig*2 + 8);
        }
    }

    const float Csc = SCALE_ATTN * 1.4426950408889634f;
    int prow = warp*16 + grp;

    float sacc[10][4] = {};
    #pragma unroll
    for (int ksi = 0; ksi < 4; ksi++) {
        #pragma unroll
        for (int nf = 0; nf < 10; nf++) {
            const __half* kp = Ks + (nf*8 + grp) * QSH + ksi*16;
            uint32_t b0 = *(const uint32_t*)(kp + tig*2);
            uint32_t b1 = *(const uint32_t*)(kp + tig*2 + 8);
            mma_f16(sacc[nf], qf[ksi][0], qf[ksi][1], qf[ksi][2], qf[ksi][3], b0, b1);
        }
    }
    float mx0 = -1e30f, mx1 = -1e30f;
    #pragma unroll
    for (int nf = 0; nf < 10; nf++) {
        int c0 = nf*8 + tig*2, c1 = c0 + 1;
        sacc[nf][0] = (c0 < NCx) ? sacc[nf][0]*Csc : -1e30f;
        sacc[nf][1] = (c1 < NCx) ? sacc[nf][1]*Csc : -1e30f;
        sacc[nf][2] = (c0 < NCx) ? sacc[nf][2]*Csc : -1e30f;
        sacc[nf][3] = (c1 < NCx) ? sacc[nf][3]*Csc : -1e30f;
        mx0 = fmaxf(mx0, fmaxf(sacc[nf][0], sacc[nf][1]));
        mx1 = fmaxf(mx1, fmaxf(sacc[nf][2], sacc[nf][3]));
    }
    mx0 = fmaxf(mx0, __shfl_xor_sync(0xffffffffu, mx0, 1));
    mx0 = fmaxf(mx0, __shfl_xor_sync(0xffffffffu, mx0, 2));
    mx1 = fmaxf(mx1, __shfl_xor_sync(0xffffffffu, mx1, 1));
    mx1 = fmaxf(mx1, __shfl_xor_sync(0xffffffffu, mx1, 2));

    float sum0 = 0.f, sum1 = 0.f;
    #pragma unroll
    for (int nf = 0; nf < 10; nf++) {
        float p0 = ex2f(sacc[nf][0] - mx0);
        float p1 = ex2f(sacc[nf][1] - mx0);
        float p2 = ex2f(sacc[nf][2] - mx1);
        float p3 = ex2f(sacc[nf][3] - mx1);
        sum0 += p0 + p1; sum1 += p2 + p3;
        int pc = nf*8 + tig*2;
        *(__half2*)(Ps + prow*CPSH + pc)     = __floats2half2_rn(p0, p1);
        *(__half2*)(Ps + (prow+8)*CPSH + pc) = __floats2half2_rn(p2, p3);
    }
    sum0 += __shfl_xor_sync(0xffffffffu, sum0, 1);
    sum0 += __shfl_xor_sync(0xffffffffu, sum0, 2);
    sum1 += __shfl_xor_sync(0xffffffffu, sum1, 1);
    sum1 += __shfl_xor_sync(0xffffffffu, sum1, 2);
    __syncwarp();

    float oacc[8][4] = {};
    #pragma unroll
    for (int ks = 0; ks < 5; ks++) {
        uint32_t pd = Psu + (uint32_t)((warp*16 + a_r) * CPSH + ks*16 + a_c) * 2;
        uint32_t a0, a1, a2, a3;
        ldsm4(a0, a1, a2, a3, pd);
        #pragma unroll
        for (int np = 0; np < 4; np++) {
            uint32_t vd = Vsu + (uint32_t)((ks*16 + a_r) * QSH + np*16 + a_c) * 2;
            uint32_t b00, b01, b10, b11;
            ldsm4t(b00, b01, b10, b11, vd);
            mma_f16(oacc[2*np],   a0, a1, a2, a3, b00, b01);
            mma_f16(oacc[2*np+1], a0, a1, a2, a3, b10, b11);
        }
    }

    float i0 = 1.f / sum0, i1 = 1.f / sum1;
    __half* ob = o + ((size_t)b*SEQ + qt*128 + warp*16) * Dm + h*DHd;
    #pragma unroll
    for (int nf = 0; nf < 8; nf++) {
        int c = nf*8 + tig*2;
        *(__half2*)(ob + (size_t)grp * Dm + c) =
            __floats2half2_rn(oacc[nf][0]*i0, oacc[nf][1]*i0);
        *(__half2*)(ob + (size_t)(grp+8) * Dm + c) =
            __floats2half2_rn(oacc[nf][2]*i1, oacc[nf][3]*i1);
    }
}

// ---------------- small kernels ----------------
__global__ void ln_kernel(const float* __restrict__ x, const float* __restrict__ g,
                          const float* __restrict__ b, __half* __restrict__ out) {
    int row = blockIdx.x;
    const float* xr = x + (size_t)row * Dm;
    float s = 0.f, ss = 0.f;
    for (int i = threadIdx.x; i < Dm; i += 256) {
        float v = xr[i];
        s += v; ss += v * v;
    }
    __shared__ float rs[256], rss[256];
    rs[threadIdx.x] = s; rss[threadIdx.x] = ss;
    __syncthreads();
    for (int st = 128; st > 0; st >>= 1) {
        if (threadIdx.x < st) { rs[threadIdx.x] += rs[threadIdx.x+st]; rss[threadIdx.x] += rss[threadIdx.x+st]; }
        __syncthreads();
    }
    float mu  = rs[0] * (1.0f / Dm);
    float var = rss[0] * (1.0f / Dm) - mu * mu;
    float inv = rsqrtf(var + EPS_LN);
    __half* orow = out + (size_t)row * Dm;
    for (int i = threadIdx.x; i < Dm; i += 256)
        orow[i] = __float2half((xr[i] - mu) * inv * g[i] + b[i]);
}

__global__ void gemm_kv_h(const float* __restrict__ A,
                          const float* __restrict__ Wk, const float* __restrict__ Wv,
                          __half* __restrict__ Ck, __half* __restrict__ Cv,
                          int M, int K, int Nn) {
    __shared__ float As[64][17];
    __shared__ float Bs[16][64];
    const float* Bm = (blockIdx.z == 0) ? Wk : Wv;
    __half* C = (blockIdx.z == 0) ? Ck : Cv;
    int bm = blockIdx.y * 64, bn = blockIdx.x * 64;
    int tx = threadIdx.x & 15, ty = threadIdx.x >> 4;
    float acc[4][4] = {};
    for (int k0 = 0; k0 < K; k0 += 16) {
        #pragma unroll
        for (int i = 0; i < 4; i++) {
            int idx = threadIdx.x + i * 256;
            int r = idx >> 4, kk = idx & 15;
            int gr = bm + r;
            As[r][kk] = (gr < M) ? A[(size_t)gr * K + k0 + kk] : 0.f;
            int kb = idx >> 6, c = idx & 63;
            int gc = bn + c;
            Bs[kb][c] = (gc < Nn) ? Bm[(size_t)(k0 + kb) * Nn + gc] : 0.f;
        }
        __syncthreads();
        #pragma unroll
        for (int kk = 0; kk < 16; kk++) {
            float a[4], bb[4];
            #pragma unroll
            for (int i = 0; i < 4; i++) a[i]  = As[ty*4+i][kk];
            #pragma unroll
            for (int j = 0; j < 4; j++) bb[j] = Bs[kk][tx*4+j];
            #pragma unroll
            for (int i = 0; i < 4; i++)
                #pragma unroll
                for (int j = 0; j < 4; j++)
                    acc[i][j] += a[i] * bb[j];
        }
        __syncthreads();
    }
    #pragma unroll
    for (int i = 0; i < 4; i++) {
        int gr = bm + ty*4 + i;
        if (gr >= M) continue;
        #pragma unroll
        for (int j = 0; j < 4; j++) {
            int gc = bn + tx*4 + j;
            if (gc >= Nn) continue;
            C[(size_t)gr * Nn + gc] = __float2half(acc[i][j]);
        }
    }
}

// ---------------- launch ----------------
extern "C" void kernel_launch(void* const* d_in, const int* in_sizes, int n_in,
                              void* d_out, int out_size) {
    const float* x      = (const float*)d_in[0];
    const float* ctx    = (const float*)d_in[1];
    const float* w1_q   = (const float*)d_in[2];
    const float* w1_k   = (const float*)d_in[3];
    const float* w1_v   = (const float*)d_in[4];
    const float* w1_o   = (const float*)d_in[5];
    const float* b1_o   = (const float*)d_in[6];
    const float* w2_q   = (const float*)d_in[7];
    const float* w2_k   = (const float*)d_in[8];
    const float* w2_v   = (const float*)d_in[9];
    const float* w2_o   = (const float*)d_in[10];
    const float* b2_o   = (const float*)d_in[11];
    const float* ln1_g  = (const float*)d_in[12];
    const float* ln1_b  = (const float*)d_in[13];
    const float* ln2_g  = (const float*)d_in[14];
    const float* ln2_b  = (const float*)d_in[15];
    const float* ln3_g  = (const float*)d_in[16];
    const float* ln3_b  = (const float*)d_in[17];
    const float* ff_w1  = (const float*)d_in[18];
    const float* ff_b1  = (const float*)d_in[19];
    const float* ff_w2  = (const float*)d_in[20];
    const float* ff_b2  = (const float*)d_in[21];
    float* xbuf = (float*)d_out;

    __half *hh, *qkvh, *kh, *vh, *atth, *th, *wh;
    cudaGetSymbolAddress((void**)&hh,   g_hh);
    cudaGetSymbolAddress((void**)&qkvh, g_qkv);
    cudaGetSymbolAddress((void**)&kh,   g_kh);
    cudaGetSymbolAddress((void**)&vh,   g_vh);
    cudaGetSymbolAddress((void**)&atth, g_atth);
    cudaGetSymbolAddress((void**)&th,   g_th);
    cudaGetSymbolAddress((void**)&wh,   g_wh);

    cudaFuncSetAttribute(gemm_h<0>, cudaFuncAttributeMaxDynamicSharedMemorySize, GH_SMEM);
    cudaFuncSetAttribute(gemm_h<1>, cudaFuncAttributeMaxDynamicSharedMemorySize, GH_SMEM);
    cudaFuncSetAttribute(gemm_h<2>, cudaFuncAttributeMaxDynamicSharedMemorySize, GH_SMEM);
    cudaFuncSetAttribute(flash_h,     cudaFuncAttributeMaxDynamicSharedMemorySize, FLH_SMEM);
    cudaFuncSetAttribute(flash_cross, cudaFuncAttributeMaxDynamicSharedMemorySize, FLC_SMEM);

    dim3 gD(Dm/128, MROWS/128);
    dim3 gQKV(3*Dm/128, MROWS/128);
    dim3 gFF1(2*FFd/128, MROWS/128);
    dim3 gFlash(SEQ/128, Bq*Hh);
    dim3 tpb(32, 8);

    // weight prep: 6 square transposes batched + 2 FF transposes
    transpose_half6<<<dim3(Dm/32, Dm/32, 6), tpb>>>(
        w1_q, w1_k, w1_v, w1_o, w2_q, w2_o,
        wh+OWQKV, wh+OWQKV+1024*1024, wh+OWQKV+2*1024*1024,
        wh+OW1O, wh+OW2Q, wh+OW2O);
    transpose_geglu<<<dim3(2*FFd/32, Dm/32), tpb>>>(ff_w1, wh+OFW1, Dm,  2*FFd);
    transpose_half<<<dim3(Dm/32,  FFd/32),  tpb>>>(ff_w2, wh+OFW2, FFd, Dm);

    // ---- self attention ----
    ln_kernel<<<MROWS, 256>>>(x, ln1_g, ln1_b, hh);
    gemm_h<1><<<gQKV, 256, GH_SMEM>>>(hh, wh+OWQKV, nullptr, nullptr, qkvh, MROWS, 3*Dm, Dm);
    flash_h<<<gFlash, 256, FLH_SMEM>>>(qkvh, atth);
    gemm_h<0><<<gD, 256, GH_SMEM>>>(atth, wh+OW1O, b1_o, x, xbuf, MROWS, Dm, Dm);

    // ---- cross attention ----
    ln_kernel<<<MROWS, 256>>>(xbuf, ln2_g, ln2_b, hh);
    gemm_h<1><<<gD, 256, GH_SMEM>>>(hh, wh+OW2Q, nullptr, nullptr, atth, MROWS, Dm, Dm);
    dim3 gKV(Dm/64, (CROWS+63)/64, 2);
    gemm_kv_h<<<gKV, 256>>>(ctx, w2_k, w2_v, kh, vh, CROWS, DCx, Dm);
    flash_cross<<<gFlash, 256, FLC_SMEM>>>(atth, kh, vh, qkvh);
    gemm_h<0><<<gD, 256, GH_SMEM>>>(qkvh, wh+OW2O, b2_o, xbuf, xbuf, MROWS, Dm, Dm);

    // ---- GEGLU FFN ----
    ln_kernel<<<MROWS, 256>>>(xbuf, ln3_g, ln3_b, hh);
    gemm_h<2><<<gFF1, 256, GH_SMEM>>>(hh, wh+OFW1, ff_b1, nullptr, th, MROWS, 2*FFd, Dm);
    gemm_h<0><<<gD, 256, GH_SMEM>>>(th, wh+OFW2, ff_b2, xbuf, xbuf, MROWS, Dm, FFd);
}

// round 11
// speedup vs baseline: 2.5917x; 1.0320x over previous
#include <cuda_runtime.h>
#include <cuda_fp16.h>
#include <math.h>
#include <stdint.h>

#define Bq 2
#define SEQ 2048
#define Dm 1024
#define NCx 77
#define DCx 768
#define Hh 16
#define DHd 64
#define FFd 4096
#define SCALE_ATTN 0.125f
#define EPS_LN 1e-5f
#define MROWS (Bq*SEQ)          // 4096
#define CROWS (Bq*NCx)          // 154

// ---------------- scratch ----------------
__device__ __half g_hh[(size_t)MROWS*Dm];
__device__ __half g_qkv[(size_t)MROWS*3*Dm];
__device__ __half g_kh[(size_t)CROWS*Dm + 1024];
__device__ __half g_vh[(size_t)CROWS*Dm + 1024];
__device__ __half g_atth[(size_t)MROWS*Dm];
__device__ __half g_th[(size_t)MROWS*FFd];
__device__ __half g_wh[(size_t)18874368];        // transposed half weights [N,K]

#define OWQKV 0
#define OW1O 3145728
#define OW2Q 4194304
#define OW2O 5242880
#define OFW1 6291456
#define OFW2 14680064

// ---------------- helpers ----------------
__device__ __forceinline__ float ex2f(float x) {
    float y;
    asm("ex2.approx.f32 %0, %1;" : "=f"(y) : "f"(x));
    return y;
}
__device__ __forceinline__ void mma_f16(float c[4],
                                        uint32_t a0, uint32_t a1, uint32_t a2, uint32_t a3,
                                        uint32_t b0, uint32_t b1) {
    asm volatile(
        "mma.sync.aligned.m16n8k16.row.col.f32.f16.f16.f32 "
        "{%0,%1,%2,%3}, {%4,%5,%6,%7}, {%8,%9}, {%0,%1,%2,%3};"
        : "+f"(c[0]), "+f"(c[1]), "+f"(c[2]), "+f"(c[3])
        : "r"(a0), "r"(a1), "r"(a2), "r"(a3), "r"(b0), "r"(b1));
}
__device__ __forceinline__ void ldsm4(uint32_t& r0, uint32_t& r1, uint32_t& r2, uint32_t& r3,
                                      uint32_t addr) {
    asm volatile("ldmatrix.sync.aligned.m8n8.x4.shared.b16 {%0,%1,%2,%3}, [%4];"
                 : "=r"(r0), "=r"(r1), "=r"(r2), "=r"(r3) : "r"(addr));
}
__device__ __forceinline__ void ldsm4t(uint32_t& r0, uint32_t& r1, uint32_t& r2, uint32_t& r3,
                                       uint32_t addr) {
    asm volatile("ldmatrix.sync.aligned.m8n8.x4.trans.shared.b16 {%0,%1,%2,%3}, [%4];"
                 : "=r"(r0), "=r"(r1), "=r"(r2), "=r"(r3) : "r"(addr));
}
__device__ __forceinline__ void cpa16(uint32_t dst, const void* src) {
    asm volatile("cp.async.cg.shared.global [%0], [%1], 16;" :: "r"(dst), "l"(src));
}
#define CP_COMMIT() asm volatile("cp.async.commit_group;")
#define CP_WAIT1()  asm volatile("cp.async.wait_group 1;")

// ---------------- weight transpose + fp16 convert ----------------
__global__ void transpose_half6(const float* s0, const float* s1, const float* s2,
                                const float* s3, const float* s4, const float* s5,
                                __half* d0, __half* d1, __half* d2,
                                __half* d3, __half* d4, __half* d5) {
    const float* src; __half* dst;
    switch (blockIdx.z) {
        case 0: src = s0; dst = d0; break;
        case 1: src = s1; dst = d1; break;
        case 2: src = s2; dst = d2; break;
        case 3: src = s3; dst = d3; break;
        case 4: src = s4; dst = d4; break;
        default: src = s5; dst = d5; break;
    }
    __shared__ float t[32][33];
    int bx = blockIdx.x * 32;
    int by = blockIdx.y * 32;
    int x = bx + threadIdx.x;
    #pragma unroll
    for (int i = 0; i < 32; i += 8) {
        int y = by + threadIdx.y + i;
        t[threadIdx.y + i][threadIdx.x] = src[(size_t)y * Dm + x];
    }
    __syncthreads();
    int kx = by + threadIdx.x;
    #pragma unroll
    for (int i = 0; i < 32; i += 8) {
        int ny = bx + threadIdx.y + i;
        dst[(size_t)ny * Dm + kx] = __float2half(t[threadIdx.x][threadIdx.y + i]);
    }
}
__global__ void transpose_half(const float* __restrict__ src, __half* __restrict__ dst,
                               int K, int N) {
    __shared__ float t[32][33];
    int bx = blockIdx.x * 32;
    int by = blockIdx.y * 32;
    int x = bx + threadIdx.x;
    #pragma unroll
    for (int i = 0; i < 32; i += 8) {
        int y = by + threadIdx.y + i;
        t[threadIdx.y + i][threadIdx.x] = src[(size_t)y * N + x];
    }
    __syncthreads();
    int kx = by + threadIdx.x;
    #pragma unroll
    for (int i = 0; i < 32; i += 8) {
        int ny = bx + threadIdx.y + i;
        dst[(size_t)ny * K + kx] = __float2half(t[threadIdx.x][threadIdx.y + i]);
    }
}
__global__ void transpose_geglu(const float* __restrict__ src, __half* __restrict__ dst,
                                int K, int N) {
    __shared__ float t[32][33];
    int bx = blockIdx.x * 32;
    int by = blockIdx.y * 32;
    int x = bx + threadIdx.x;
    #pragma unroll
    for (int i = 0; i < 32; i += 8) {
        int y = by + threadIdx.y + i;
        t[threadIdx.y + i][threadIdx.x] = src[(size_t)y * N + x];
    }
    __syncthreads();
    int kx = by + threadIdx.x;
    #pragma unroll
    for (int i = 0; i < 32; i += 8) {
        int ny = bx + threadIdx.y + i;
        int iny = (ny < FFd) ? (2*ny) : (2*(ny - FFd) + 1);
        dst[(size_t)iny * K + kx] = __float2half(t[threadIdx.x][threadIdx.y + i]);
    }
}

// ================= fp16 dense GEMM (ldmatrix, BK=64, 3-stage) ===============
#define ASH 72
#define HTILE (128*ASH)
#define GH_SMEM (3*2*HTILE*2)

template<int MODE>
__global__ __launch_bounds__(256, 2)
void gemm_h(const __half* __restrict__ A, const __half* __restrict__ Bt,
            const float* __restrict__ bias, const float* __restrict__ res,
            void* __restrict__ Cv, int M, int N, int K) {
    extern __shared__ __half smh[];
    __half* As = smh;
    __half* Bs = smh + 3*HTILE;
    int bm = blockIdx.y * 128, bn = blockIdx.x * 128;
    int tid = threadIdx.x, warp = tid >> 5, lane = tid & 31;
    int grp = lane >> 2, tig = lane & 3;
    int wm = (warp >> 2) * 64, wn = (warp & 3) * 32;
    int sel = lane >> 3, lrow = lane & 7;
    int a_r = (sel & 1) * 8 + lrow, a_c = (sel >> 1) * 8;
    int b_r = (sel >> 1) * 8 + lrow, b_c = (sel & 1) * 8;
    uint32_t sAu = (uint32_t)__cvta_generic_to_shared(As);
    uint32_t sBu = (uint32_t)__cvta_generic_to_shared(Bs);
    int niter = K >> 6;

    float acc[4][4][4] = {};

    auto loadTile = [&](int it, int buf) {
        int k0 = it * 64;
        #pragma unroll
        for (int i = 0; i < 4; i++) {
            int c = tid + i * 256;
            int row = c >> 3, kq = c & 7;
            cpa16(sAu + (uint32_t)(buf*HTILE + row*ASH + kq*8) * 2,
                  A + (size_t)(bm + row) * K + k0 + kq * 8);
            cpa16(sBu + (uint32_t)(buf*HTILE + row*ASH + kq*8) * 2,
                  Bt + (size_t)(bn + row) * K + k0 + kq * 8);
        }
        CP_COMMIT();
    };

    loadTile(0, 0);
    loadTile(1, 1);

    for (int it = 0; it < niter; ++it) {
        CP_WAIT1();
        __syncthreads();
        if (it + 2 < niter) loadTile(it + 2, (it + 2) % 3);
        else CP_COMMIT();

        uint32_t Abu = sAu + (uint32_t)((it % 3) * HTILE) * 2;
        uint32_t Bbu = sBu + (uint32_t)((it % 3) * HTILE) * 2;
        #pragma unroll
        for (int ks = 0; ks < 64; ks += 16) {
            uint32_t af[4][4], bf[4][2];
            #pragma unroll
            for (int mf = 0; mf < 4; mf++) {
                uint32_t ad = Abu + (uint32_t)((wm + mf*16 + a_r) * ASH + ks + a_c) * 2;
                ldsm4(af[mf][0], af[mf][1], af[mf][2], af[mf][3], ad);
            }
            #pragma unroll
            for (int np = 0; np < 2; np++) {
                uint32_t bd = Bbu + (uint32_t)((wn + np*16 + b_r) * ASH + ks + b_c) * 2;
                ldsm4(bf[2*np][0], bf[2*np][1], bf[2*np+1][0], bf[2*np+1][1], bd);
            }
            #pragma unroll
            for (int mf = 0; mf < 4; mf++)
                #pragma unroll
                for (int nf = 0; nf < 4; nf++)
                    mma_f16(acc[mf][nf], af[mf][0], af[mf][1], af[mf][2], af[mf][3],
                            bf[nf][0], bf[nf][1]);
        }
    }

    #pragma unroll
    for (int mf = 0; mf < 4; mf++) {
        #pragma unroll
        for (int nf = 0; nf < 4; nf++) {
            int r = bm + wm + mf*16 + grp;
            int c = bn + wn + nf*8 + tig*2;
            float2 v0 = make_float2(acc[mf][nf][0], acc[mf][nf][1]);
            float2 v1 = make_float2(acc[mf][nf][2], acc[mf][nf][3]);
            if (MODE == 2) {
                int j = c >> 1;
                float bv = bias[j], bg = bias[FFd + j];
                float val0 = v0.x + bv, gat0 = v0.y + bg;
                float val1 = v1.x + bv, gat1 = v1.y + bg;
                float o0 = val0 * (0.5f * gat0 * (1.f + erff(gat0 * 0.70710678118654752f)));
                float o1 = val1 * (0.5f * gat1 * (1.f + erff(gat1 * 0.70710678118654752f)));
                __half* C = (__half*)Cv;
                C[(size_t)r * FFd + j]     = __float2half(o0);
                C[(size_t)(r+8) * FFd + j] = __float2half(o1);
            } else {
                if (bias) {
                    float2 bb = *(const float2*)(bias + c);
                    v0.x += bb.x; v0.y += bb.y; v1.x += bb.x; v1.y += bb.y;
                }
                if (MODE == 0 && res) {
                    float2 r0 = *(const float2*)(res + (size_t)r * N + c);
                    float2 r1 = *(const float2*)(res + (size_t)(r+8) * N + c);
                    v0.x += r0.x; v0.y += r0.y; v1.x += r1.x; v1.y += r1.y;
                }
                if (MODE == 1) {
                    __half* C = (__half*)Cv;
                    *(__half2*)(C + (size_t)r * N + c)     = __floats2half2_rn(v0.x, v0.y);
                    *(__half2*)(C + (size_t)(r+8) * N + c) = __floats2half2_rn(v1.x, v1.y);
                } else {
                    float* C = (float*)Cv;
                    *(float2*)(C + (size_t)r * N + c)     = v0;
                    *(float2*)(C + (size_t)(r+8) * N + c) = v1;
                }
            }
        }
    }
}

// ================= fp16 flash attention (self-attn, strided QKV) ============
#define QSH 72
#define PSH 136
#define FLH_SMEM ((3*128*QSH + 128*PSH)*2)

__global__ __launch_bounds__(256, 2)
void flash_h(const __half* __restrict__ qkv, __half* __restrict__ o) {
    extern __shared__ __half smf[];
    __half* Qs = smf;
    __half* Ks = Qs + 128*QSH;
    __half* Vs = Ks + 128*QSH;
    __half* Ps = Vs + 128*QSH;
    uint32_t Ksu = (uint32_t)__cvta_generic_to_shared(Ks);
    uint32_t Vsu = (uint32_t)__cvta_generic_to_shared(Vs);
    uint32_t Psu = (uint32_t)__cvta_generic_to_shared(Ps);

    const int ldq = 3*Dm;
    int qt = blockIdx.x, bh = blockIdx.y;
    int b = bh >> 4, h = bh & 15;
    int tid = threadIdx.x, warp = tid >> 5, lane = tid & 31;
    int grp = lane >> 2, tig = lane & 3;
    int sel = lane >> 3, lrow = lane & 7;
    int a_r = (sel & 1) * 8 + lrow, a_c = (sel >> 1) * 8;
    int b_r = (sel >> 1) * 8 + lrow, b_c = (sel & 1) * 8;

    const __half* qb = qkv + ((size_t)b*SEQ + qt*128) * ldq + h*DHd;
    const __half* kb = qkv + (size_t)b*SEQ*ldq + Dm + h*DHd;
    const __half* vb = qkv + (size_t)b*SEQ*ldq + 2*Dm + h*DHd;

    {
        int row = tid >> 1, part = tid & 1;
        const float4* s4 = (const float4*)(qb + (size_t)row * ldq + part*32);
        float4* d4 = (float4*)(Qs + row*QSH + part*32);
        #pragma unroll
        for (int i = 0; i < 4; i++) d4[i] = s4[i];
    }
    __syncthreads();

    uint32_t qf[4][4];
    {
        const __half* p = Qs + (warp*16 + grp) * QSH;
        #pragma unroll
        for (int ksi = 0; ksi < 4; ksi++) {
            qf[ksi][0] = *(const uint32_t*)(p + ksi*16 + tig*2);
            qf[ksi][1] = *(const uint32_t*)(p + 8*QSH + ksi*16 + tig*2);
            qf[ksi][2] = *(const uint32_t*)(p + ksi*16 + tig*2 + 8);
            qf[ksi][3] = *(const uint32_t*)(p + 8*QSH + ksi*16 + tig*2 + 8);
        }
    }

    float oacc[8][4] = {};
    float m0 = -1e30f, m1 = -1e30f, l0 = 0.f, l1 = 0.f;
    const float Csc = SCALE_ATTN * 1.4426950408889634f;
    int prow = warp*16 + grp;

    for (int kv0 = 0; kv0 < SEQ; kv0 += 128) {
        {
            int row = tid >> 1, part = tid & 1;
            const float4* sk = (const float4*)(kb + (size_t)(kv0+row) * ldq + part*32);
            const float4* sv = (const float4*)(vb + (size_t)(kv0+row) * ldq + part*32);
            float4* dk = (float4*)(Ks + row*QSH + part*32);
            float4* dv = (float4*)(Vs + row*QSH + part*32);
            #pragma unroll
            for (int i = 0; i < 4; i++) { dk[i] = sk[i]; dv[i] = sv[i]; }
        }
        __syncthreads();

        float sacc[16][4] = {};
        #pragma unroll
        for (int ksi = 0; ksi < 4; ksi++) {
            #pragma unroll
            for (int np = 0; np < 8; np++) {
                uint32_t kd = Ksu + (uint32_t)((np*16 + b_r) * QSH + ksi*16 + b_c) * 2;
                uint32_t b00, b01, b10, b11;
                ldsm4(b00, b01, b10, b11, kd);
                mma_f16(sacc[2*np],   qf[ksi][0], qf[ksi][1], qf[ksi][2], qf[ksi][3], b00, b01);
                mma_f16(sacc[2*np+1], qf[ksi][0], qf[ksi][1], qf[ksi][2], qf[ksi][3], b10, b11);
            }
        }
        float mx0 = -1e30f, mx1 = -1e30f;
        #pragma unroll
        for (int nf = 0; nf < 16; nf++) {
            sacc[nf][0] *= Csc; sacc[nf][1] *= Csc; sacc[nf][2] *= Csc; sacc[nf][3] *= Csc;
            mx0 = fmaxf(mx0, fmaxf(sacc[nf][0], sacc[nf][1]));
            mx1 = fmaxf(mx1, fmaxf(sacc[nf][2], sacc[nf][3]));
        }
        mx0 = fmaxf(mx0, __shfl_xor_sync(0xffffffffu, mx0, 1));
        mx0 = fmaxf(mx0, __shfl_xor_sync(0xffffffffu, mx0, 2));
        mx1 = fmaxf(mx1, __shfl_xor_sync(0xffffffffu, mx1, 1));
        mx1 = fmaxf(mx1, __shfl_xor_sync(0xffffffffu, mx1, 2));
        float mn0 = fmaxf(m0, mx0), mn1 = fmaxf(m1, mx1);
        float sc0 = ex2f(m0 - mn0), sc1 = ex2f(m1 - mn1);
        float sum0 = 0.f, sum1 = 0.f;
        #pragma unroll
        for (int nf = 0; nf < 16; nf++) {
            float p0 = ex2f(sacc[nf][0] - mn0);
            float p1 = ex2f(sacc[nf][1] - mn0);
            float p2 = ex2f(sacc[nf][2] - mn1);
            float p3 = ex2f(sacc[nf][3] - mn1);
            sum0 += p0 + p1; sum1 += p2 + p3;
            int pc = nf*8 + tig*2;
            *(__half2*)(Ps + prow*PSH + pc)     = __floats2half2_rn(p0, p1);
            *(__half2*)(Ps + (prow+8)*PSH + pc) = __floats2half2_rn(p2, p3);
        }
        sum0 += __shfl_xor_sync(0xffffffffu, sum0, 1);
        sum0 += __shfl_xor_sync(0xffffffffu, sum0, 2);
        sum1 += __shfl_xor_sync(0xffffffffu, sum1, 1);
        sum1 += __shfl_xor_sync(0xffffffffu, sum1, 2);
        l0 = l0 * sc0 + sum0;  l1 = l1 * sc1 + sum1;
        m0 = mn0;  m1 = mn1;
        #pragma unroll
        for (int nf = 0; nf < 8; nf++) {
            oacc[nf][0] *= sc0; oacc[nf][1] *= sc0;
            oacc[nf][2] *= sc1; oacc[nf][3] *= sc1;
        }
        __syncwarp();

        #pragma unroll
        for (int ks = 0; ks < 8; ks++) {
            uint32_t pd = Psu + (uint32_t)((warp*16 + a_r) * PSH + ks*16 + a_c) * 2;
            uint32_t a0, a1, a2, a3;
            ldsm4(a0, a1, a2, a3, pd);
            #pragma unroll
            for (int np = 0; np < 4; np++) {
                uint32_t vd = Vsu + (uint32_t)((ks*16 + a_r) * QSH + np*16 + a_c) * 2;
                uint32_t b00, b01, b10, b11;
                ldsm4t(b00, b01, b10, b11, vd);
                mma_f16(oacc[2*np],   a0, a1, a2, a3, b00, b01);
                mma_f16(oacc[2*np+1], a0, a1, a2, a3, b10, b11);
            }
        }
        __syncthreads();
    }

    float i0 = 1.f / l0, i1 = 1.f / l1;
    __half* ob = o + ((size_t)b*SEQ + qt*128 + warp*16) * Dm + h*DHd;
    #pragma unroll
    for (int nf = 0; nf < 8; nf++) {
        int c = nf*8 + tig*2;
        *(__half2*)(ob + (size_t)grp * Dm + c) =
            __floats2half2_rn(oacc[nf][0]*i0, oacc[nf][1]*i0);
        *(__half2*)(ob + (size_t)(grp+8) * Dm + c) =
            __floats2half2_rn(oacc[nf][2]*i1, oacc[nf][3]*i1);
    }
}

// ================= fp16 cross-attention (single KV tile, nk=77) =============
#define CKROWS 80
#define CPSH 88
#define FLC_SMEM ((128*QSH + 2*CKROWS*QSH + 128*CPSH)*2)

__global__ __launch_bounds__(256, 2)
void flash_cross(const __half* __restrict__ q, const __half* __restrict__ k,
                 const __half* __restrict__ v, __half* __restrict__ o) {
    extern __shared__ __half smc[];
    __half* Qs = smc;
    __half* Ks = Qs + 128*QSH;
    __half* Vs = Ks + CKROWS*QSH;
    __half* Ps = Vs + CKROWS*QSH;
    uint32_t Vsu = (uint32_t)__cvta_generic_to_shared(Vs);
    uint32_t Psu = (uint32_t)__cvta_generic_to_shared(Ps);

    int qt = blockIdx.x, bh = blockIdx.y;
    int b = bh >> 4, h = bh & 15;
    int tid = threadIdx.x, warp = tid >> 5, lane = tid & 31;
    int grp = lane >> 2, tig = lane & 3;
    int sel = lane >> 3, lrow = lane & 7;
    int a_r = (sel & 1) * 8 + lrow, a_c = (sel >> 1) * 8;

    const __half* qb = q + ((size_t)b*SEQ + qt*128) * Dm + h*DHd;
    const __half* kb = k + (size_t)b*NCx*Dm + h*DHd;
    const __half* vb = v + (size_t)b*NCx*Dm + h*DHd;

    {
        int row = tid >> 1, part = tid & 1;
        const float4* s4 = (const float4*)(qb + (size_t)row * Dm + part*32);
        float4* d4 = (float4*)(Qs + row*QSH + part*32);
        #pragma unroll
        for (int i = 0; i < 4; i++) d4[i] = s4[i];
    }
    for (int rr = tid; rr < CKROWS*2; rr += 256) {
        int row = rr >> 1, part = rr & 1;
        float4* dk = (float4*)(Ks + row*QSH + part*32);
        float4* dv = (float4*)(Vs + row*QSH + part*32);
        if (row < NCx) {
            const float4* sk = (const float4*)(kb + (size_t)row * Dm + part*32);
            const float4* sv = (const float4*)(vb + (size_t)row * Dm + part*32);
            #pragma unroll
            for (int i = 0; i < 4; i++) { dk[i] = sk[i]; dv[i] = sv[i]; }
        } else {
            float4 z = make_float4(0.f,0.f,0.f,0.f);
            #pragma unroll
            for (int i = 0; i < 4; i++) { dk[i] = z; dv[i] = z; }
        }
    }
    __syncthreads();

    uint32_t qf[4][4];
    {
        const __half* p = Qs + (warp*16 + grp) * QSH;
        #pragma unroll
        for (int ksi = 0; ksi < 4; ksi++) {
            qf[ksi][0] = *(const uint32_t*)(p + ksi*16 + tig*2);
            qf[ksi][1] = *(const uint32_t*)(p + 8*QSH + ksi*16 + tig*2);
            qf[ksi][2] = *(const uint32_t*)(p + ksi*16 + tig*2 + 8);
            qf[ksi][3] = *(const uint32_t*)(p + 8*QSH + ksi*16 + tig*2 + 8);
        }
    }

    const float Csc = SCALE_ATTN * 1.4426950408889634f;
    int prow = warp*16 + grp;

    float sacc[10][4] = {};
    #pragma unroll
    for (int ksi = 0; ksi < 4; ksi++) {
        #pragma unroll
        for (int nf = 0; nf < 10; nf++) {
            const __half* kp = Ks + (nf*8 + grp) * QSH + ksi*16;
            uint32_t b0 = *(const uint32_t*)(kp + tig*2);
            uint32_t b1 = *(const uint32_t*)(kp + tig*2 + 8);
            mma_f16(sacc[nf], qf[ksi][0], qf[ksi][1], qf[ksi][2], qf[ksi][3], b0, b1);
        }
    }
    float mx0 = -1e30f, mx1 = -1e30f;
    #pragma unroll
    for (int nf = 0; nf < 10; nf++) {
        int c0 = nf*8 + tig*2, c1 = c0 + 1;
        sacc[nf][0] = (c0 < NCx) ? sacc[nf][0]*Csc : -1e30f;
        sacc[nf][1] = (c1 < NCx) ? sacc[nf][1]*Csc : -1e30f;
        sacc[nf][2] = (c0 < NCx) ? sacc[nf][2]*Csc : -1e30f;
        sacc[nf][3] = (c1 < NCx) ? sacc[nf][3]*Csc : -1e30f;
        mx0 = fmaxf(mx0, fmaxf(sacc[nf][0], sacc[nf][1]));
        mx1 = fmaxf(mx1, fmaxf(sacc[nf][2], sacc[nf][3]));
    }
    mx0 = fmaxf(mx0, __shfl_xor_sync(0xffffffffu, mx0, 1));
    mx0 = fmaxf(mx0, __shfl_xor_sync(0xffffffffu, mx0, 2));
    mx1 = fmaxf(mx1, __shfl_xor_sync(0xffffffffu, mx1, 1));
    mx1 = fmaxf(mx1, __shfl_xor_sync(0xffffffffu, mx1, 2));

    float sum0 = 0.f, sum1 = 0.f;
    #pragma unroll
    for (int nf = 0; nf < 10; nf++) {
        float p0 = ex2f(sacc[nf][0] - mx0);
        float p1 = ex2f(sacc[nf][1] - mx0);
        float p2 = ex2f(sacc[nf][2] - mx1);
        float p3 = ex2f(sacc[nf][3] - mx1);
        sum0 += p0 + p1; sum1 += p2 + p3;
        int pc = nf*8 + tig*2;
        *(__half2*)(Ps + prow*CPSH + pc)     = __floats2half2_rn(p0, p1);
        *(__half2*)(Ps + (prow+8)*CPSH + pc) = __floats2half2_rn(p2, p3);
    }
    sum0 += __shfl_xor_sync(0xffffffffu, sum0, 1);
    sum0 += __shfl_xor_sync(0xffffffffu, sum0, 2);
    sum1 += __shfl_xor_sync(0xffffffffu, sum1, 1);
    sum1 += __shfl_xor_sync(0xffffffffu, sum1, 2);
    __syncwarp();

    float oacc[8][4] = {};
    #pragma unroll
    for (int ks = 0; ks < 5; ks++) {
        uint32_t pd = Psu + (uint32_t)((warp*16 + a_r) * CPSH + ks*16 + a_c) * 2;
        uint32_t a0, a1, a2, a3;
        ldsm4(a0, a1, a2, a3, pd);
        #pragma unroll
        for (int np = 0; np < 4; np++) {
            uint32_t vd = Vsu + (uint32_t)((ks*16 + a_r) * QSH + np*16 + a_c) * 2;
            uint32_t b00, b01, b10, b11;
            ldsm4t(b00, b01, b10, b11, vd);
            mma_f16(oacc[2*np],   a0, a1, a2, a3, b00, b01);
            mma_f16(oacc[2*np+1], a0, a1, a2, a3, b10, b11);
        }
    }

    float i0 = 1.f / sum0, i1 = 1.f / sum1;
    __half* ob = o + ((size_t)b*SEQ + qt*128 + warp*16) * Dm + h*DHd;
    #pragma unroll
    for (int nf = 0; nf < 8; nf++) {
        int c = nf*8 + tig*2;
        *(__half2*)(ob + (size_t)grp * Dm + c) =
            __floats2half2_rn(oacc[nf][0]*i0, oacc[nf][1]*i0);
        *(__half2*)(ob + (size_t)(grp+8) * Dm + c) =
            __floats2half2_rn(oacc[nf][2]*i1, oacc[nf][3]*i1);
    }
}

// ---------------- layernorm: single-pass float4 + warp shuffle ----------------
__global__ __launch_bounds__(256)
void ln_kernel(const float* __restrict__ x, const float* __restrict__ g,
               const float* __restrict__ b, __half* __restrict__ out) {
    int row = blockIdx.x;
    int tid = threadIdx.x, warp = tid >> 5, lane = tid & 31;
    const float4* xr = (const float4*)(x + (size_t)row * Dm);
    float4 v = xr[tid];                      // 256 threads x 4 = 1024
    float s  = v.x + v.y + v.z + v.w;
    float ss = v.x*v.x + v.y*v.y + v.z*v.z + v.w*v.w;
    #pragma unroll
    for (int o = 16; o > 0; o >>= 1) {
        s  += __shfl_xor_sync(0xffffffffu, s,  o);
        ss += __shfl_xor_sync(0xffffffffu, ss, o);
    }
    __shared__ float ws[8], wss[8];
    if (lane == 0) { ws[warp] = s; wss[warp] = ss; }
    __syncthreads();
    float ts = 0.f, tss = 0.f;
    #pragma unroll
    for (int i = 0; i < 8; i++) { ts += ws[i]; tss += wss[i]; }
    float mu  = ts * (1.0f / Dm);
    float var = tss * (1.0f / Dm) - mu * mu;
    float inv = rsqrtf(var + EPS_LN);
    float4 gv = ((const float4*)g)[tid];
    float4 bv = ((const float4*)b)[tid];
    float o0 = (v.x - mu) * inv * gv.x + bv.x;
    float o1 = (v.y - mu) * inv * gv.y + bv.y;
    float o2 = (v.z - mu) * inv * gv.z + bv.z;
    float o3 = (v.w - mu) * inv * gv.w + bv.w;
    __half2* orow = (__half2*)(out + (size_t)row * Dm) + tid * 2;
    orow[0] = __floats2half2_rn(o0, o1);
    orow[1] = __floats2half2_rn(o2, o3);
}

__global__ void gemm_kv_h(const float* __restrict__ A,
                          const float* __restrict__ Wk, const float* __restrict__ Wv,
                          __half* __restrict__ Ck, __half* __restrict__ Cv,
                          int M, int K, int Nn) {
    __shared__ float As[64][17];
    __shared__ float Bs[16][64];
    const float* Bm = (blockIdx.z == 0) ? Wk : Wv;
    __half* C = (blockIdx.z == 0) ? Ck : Cv;
    int bm = blockIdx.y * 64, bn = blockIdx.x * 64;
    int tx = threadIdx.x & 15, ty = threadIdx.x >> 4;
    float acc[4][4] = {};
    for (int k0 = 0; k0 < K; k0 += 16) {
        #pragma unroll
        for (int i = 0; i < 4; i++) {
            int idx = threadIdx.x + i * 256;
            int r = idx >> 4, kk = idx & 15;
            int gr = bm + r;
            As[r][kk] = (gr < M) ? A[(size_t)gr * K + k0 + kk] : 0.f;
            int kb = idx >> 6, c = idx & 63;
            int gc = bn + c;
            Bs[kb][c] = (gc < Nn) ? Bm[(size_t)(k0 + kb) * Nn + gc] : 0.f;
        }
        __syncthreads();
        #pragma unroll
        for (int kk = 0; kk < 16; kk++) {
            float a[4], bb[4];
            #pragma unroll
            for (int i = 0; i < 4; i++) a[i]  = As[ty*4+i][kk];
            #pragma unroll
            for (int j = 0; j < 4; j++) bb[j] = Bs[kk][tx*4+j];
            #pragma unroll
            for (int i = 0; i < 4; i++)
                #pragma unroll
                for (int j = 0; j < 4; j++)
                    acc[i][j] += a[i] * bb[j];
        }
        __syncthreads();
    }
    #pragma unroll
    for (int i = 0; i < 4; i++) {
        int gr = bm + ty*4 + i;
        if (gr >= M) continue;
        #pragma unroll
        for (int j = 0; j < 4; j++) {
            int gc = bn + tx*4 + j;
            if (gc >= Nn) continue;
            C[(size_t)gr * Nn + gc] = __float2half(acc[i][j]);
        }
    }
}

// ---------------- launch ----------------
extern "C" void kernel_launch(void* const* d_in, const int* in_sizes, int n_in,
                              void* d_out, int out_size) {
    const float* x      = (const float*)d_in[0];
    const float* ctx    = (const float*)d_in[1];
    const float* w1_q   = (const float*)d_in[2];
    const float* w1_k   = (const float*)d_in[3];
    const float* w1_v   = (const float*)d_in[4];
    const float* w1_o   = (const float*)d_in[5];
    const float* b1_o   = (const float*)d_in[6];
    const float* w2_q   = (const float*)d_in[7];
    const float* w2_k   = (const float*)d_in[8];
    const float* w2_v   = (const float*)d_in[9];
    const float* w2_o   = (const float*)d_in[10];
    const float* b2_o   = (const float*)d_in[11];
    const float* ln1_g  = (const float*)d_in[12];
    const float* ln1_b  = (const float*)d_in[13];
    const float* ln2_g  = (const float*)d_in[14];
    const float* ln2_b  = (const float*)d_in[15];
    const float* ln3_g  = (const float*)d_in[16];
    const float* ln3_b  = (const float*)d_in[17];
    const float* ff_w1  = (const float*)d_in[18];
    const float* ff_b1  = (const float*)d_in[19];
    const float* ff_w2  = (const float*)d_in[20];
    const float* ff_b2  = (const float*)d_in[21];
    float* xbuf = (float*)d_out;

    __half *hh, *qkvh, *kh, *vh, *atth, *th, *wh;
    cudaGetSymbolAddress((void**)&hh,   g_hh);
    cudaGetSymbolAddress((void**)&qkvh, g_qkv);
    cudaGetSymbolAddress((void**)&kh,   g_kh);
    cudaGetSymbolAddress((void**)&vh,   g_vh);
    cudaGetSymbolAddress((void**)&atth, g_atth);
    cudaGetSymbolAddress((void**)&th,   g_th);
    cudaGetSymbolAddress((void**)&wh,   g_wh);

    cudaFuncSetAttribute(gemm_h<0>, cudaFuncAttributeMaxDynamicSharedMemorySize, GH_SMEM);
    cudaFuncSetAttribute(gemm_h<1>, cudaFuncAttributeMaxDynamicSharedMemorySize, GH_SMEM);
    cudaFuncSetAttribute(gemm_h<2>, cudaFuncAttributeMaxDynamicSharedMemorySize, GH_SMEM);
    cudaFuncSetAttribute(flash_h,     cudaFuncAttributeMaxDynamicSharedMemorySize, FLH_SMEM);
    cudaFuncSetAttribute(flash_cross, cudaFuncAttributeMaxDynamicSharedMemorySize, FLC_SMEM);

    dim3 gD(Dm/128, MROWS/128);
    dim3 gQKV(3*Dm/128, MROWS/128);
    dim3 gFF1(2*FFd/128, MROWS/128);
    dim3 gFlash(SEQ/128, Bq*Hh);
    dim3 tpb(32, 8);

    transpose_half6<<<dim3(Dm/32, Dm/32, 6), tpb>>>(
        w1_q, w1_k, w1_v, w1_o, w2_q, w2_o,
        wh+OWQKV, wh+OWQKV+1024*1024, wh+OWQKV+2*1024*1024,
        wh+OW1O, wh+OW2Q, wh+OW2O);
    transpose_geglu<<<dim3(2*FFd/32, Dm/32), tpb>>>(ff_w1, wh+OFW1, Dm,  2*FFd);
    transpose_half<<<dim3(Dm/32,  FFd/32),  tpb>>>(ff_w2, wh+OFW2, FFd, Dm);

    // ---- self attention ----
    ln_kernel<<<MROWS, 256>>>(x, ln1_g, ln1_b, hh);
    gemm_h<1><<<gQKV, 256, GH_SMEM>>>(hh, wh+OWQKV, nullptr, nullptr, qkvh, MROWS, 3*Dm, Dm);
    flash_h<<<gFlash, 256, FLH_SMEM>>>(qkvh, atth);
    gemm_h<0><<<gD, 256, GH_SMEM>>>(atth, wh+OW1O, b1_o, x, xbuf, MROWS, Dm, Dm);

    // ---- cross attention ----
    ln_kernel<<<MROWS, 256>>>(xbuf, ln2_g, ln2_b, hh);
    gemm_h<1><<<gD, 256, GH_SMEM>>>(hh, wh+OW2Q, nullptr, nullptr, atth, MROWS, Dm, Dm);
    dim3 gKV(Dm/64, (CROWS+63)/64, 2);
    gemm_kv_h<<<gKV, 256>>>(ctx, w2_k, w2_v, kh, vh, CROWS, DCx, Dm);
    flash_cross<<<gFlash, 256, FLC_SMEM>>>(atth, kh, vh, qkvh);
    gemm_h<0><<<gD, 256, GH_SMEM>>>(qkvh, wh+OW2O, b2_o, xbuf, xbuf, MROWS, Dm, Dm);

    // ---- GEGLU FFN ----
    ln_kernel<<<MROWS, 256>>>(xbuf, ln3_g, ln3_b, hh);
    gemm_h<2><<<gFF1, 256, GH_SMEM>>>(hh, wh+OFW1, ff_b1, nullptr, th, MROWS, 2*FFd, Dm);
    gemm_h<0><<<gD, 256, GH_SMEM>>>(th, wh+OFW2, ff_b2, xbuf, xbuf, MROWS, Dm, FFd);
}

// round 13
// speedup vs baseline: 2.7170x; 1.0483x over previous
#include <cuda_runtime.h>
#include <cuda_fp16.h>
#include <math.h>
#include <stdint.h>

#define Bq 2
#define SEQ 2048
#define Dm 1024
#define NCx 77
#define DCx 768
#define Hh 16
#define DHd 64
#define FFd 4096
#define SCALE_ATTN 0.125f
#define EPS_LN 1e-5f
#define MROWS (Bq*SEQ)          // 4096
#define CROWS (Bq*NCx)          // 154

// ---------------- scratch ----------------
__device__ __half g_hh[(size_t)MROWS*Dm];
__device__ __half g_qkv[(size_t)MROWS*3*Dm];
__device__ __half g_kh[(size_t)CROWS*Dm + 1024];
__device__ __half g_vh[(size_t)CROWS*Dm + 1024];
__device__ __half g_atth[(size_t)MROWS*Dm];
__device__ __half g_th[(size_t)MROWS*FFd];
__device__ __half g_wh[(size_t)18874368];        // transposed half weights [N,K]

#define OWQKV 0
#define OW1O 3145728
#define OW2Q 4194304
#define OW2O 5242880
#define OFW1 6291456
#define OFW2 14680064

// ---------------- helpers ----------------
__device__ __forceinline__ float ex2f(float x) {
    float y;
    asm("ex2.approx.f32 %0, %1;" : "=f"(y) : "f"(x));
    return y;
}
// pack two floats to a half2 fragment (lo in lower 16 bits) — matches __floats2half2_rn(lo,hi)
__device__ __forceinline__ uint32_t pack_h2(float lo, float hi) {
    uint32_t u;
    asm("cvt.rn.f16x2.f32 %0, %1, %2;" : "=r"(u) : "f"(hi), "f"(lo));
    return u;
}
__device__ __forceinline__ void mma_f16(float c[4],
                                        uint32_t a0, uint32_t a1, uint32_t a2, uint32_t a3,
                                        uint32_t b0, uint32_t b1) {
    asm volatile(
        "mma.sync.aligned.m16n8k16.row.col.f32.f16.f16.f32 "
        "{%0,%1,%2,%3}, {%4,%5,%6,%7}, {%8,%9}, {%0,%1,%2,%3};"
        : "+f"(c[0]), "+f"(c[1]), "+f"(c[2]), "+f"(c[3])
        : "r"(a0), "r"(a1), "r"(a2), "r"(a3), "r"(b0), "r"(b1));
}
__device__ __forceinline__ void ldsm4(uint32_t& r0, uint32_t& r1, uint32_t& r2, uint32_t& r3,
                                      uint32_t addr) {
    asm volatile("ldmatrix.sync.aligned.m8n8.x4.shared.b16 {%0,%1,%2,%3}, [%4];"
                 : "=r"(r0), "=r"(r1), "=r"(r2), "=r"(r3) : "r"(addr));
}
__device__ __forceinline__ void ldsm4t(uint32_t& r0, uint32_t& r1, uint32_t& r2, uint32_t& r3,
                                       uint32_t addr) {
    asm volatile("ldmatrix.sync.aligned.m8n8.x4.trans.shared.b16 {%0,%1,%2,%3}, [%4];"
                 : "=r"(r0), "=r"(r1), "=r"(r2), "=r"(r3) : "r"(addr));
}
__device__ __forceinline__ void cpa16(uint32_t dst, const void* src) {
    asm volatile("cp.async.cg.shared.global [%0], [%1], 16;" :: "r"(dst), "l"(src));
}
#define CP_COMMIT() asm volatile("cp.async.commit_group;")
#define CP_WAIT1()  asm volatile("cp.async.wait_group 1;")
#define CP_WAIT0()  asm volatile("cp.async.wait_group 0;")

// ---------------- weight transpose + fp16 convert ----------------
__global__ void transpose_half6(const float* s0, const float* s1, const float* s2,
                                const float* s3, const float* s4, const float* s5,
                                __half* d0, __half* d1, __half* d2,
                                __half* d3, __half* d4, __half* d5) {
    const float* src; __half* dst;
    switch (blockIdx.z) {
        case 0: src = s0; dst = d0; break;
        case 1: src = s1; dst = d1; break;
        case 2: src = s2; dst = d2; break;
        case 3: src = s3; dst = d3; break;
        case 4: src = s4; dst = d4; break;
        default: src = s5; dst = d5; break;
    }
    __shared__ float t[32][33];
    int bx = blockIdx.x * 32;
    int by = blockIdx.y * 32;
    int x = bx + threadIdx.x;
    #pragma unroll
    for (int i = 0; i < 32; i += 8) {
        int y = by + threadIdx.y + i;
        t[threadIdx.y + i][threadIdx.x] = src[(size_t)y * Dm + x];
    }
    __syncthreads();
    int kx = by + threadIdx.x;
    #pragma unroll
    for (int i = 0; i < 32; i += 8) {
        int ny = bx + threadIdx.y + i;
        dst[(size_t)ny * Dm + kx] = __float2half(t[threadIdx.x][threadIdx.y + i]);
    }
}
__global__ void transpose_half(const float* __restrict__ src, __half* __restrict__ dst,
                               int K, int N) {
    __shared__ float t[32][33];
    int bx = blockIdx.x * 32;
    int by = blockIdx.y * 32;
    int x = bx + threadIdx.x;
    #pragma unroll
    for (int i = 0; i < 32; i += 8) {
        int y = by + threadIdx.y + i;
        t[threadIdx.y + i][threadIdx.x] = src[(size_t)y * N + x];
    }
    __syncthreads();
    int kx = by + threadIdx.x;
    #pragma unroll
    for (int i = 0; i < 32; i += 8) {
        int ny = bx + threadIdx.y + i;
        dst[(size_t)ny * K + kx] = __float2half(t[threadIdx.x][threadIdx.y + i]);
    }
}
__global__ void transpose_geglu(const float* __restrict__ src, __half* __restrict__ dst,
                                int K, int N) {
    __shared__ float t[32][33];
    int bx = blockIdx.x * 32;
    int by = blockIdx.y * 32;
    int x = bx + threadIdx.x;
    #pragma unroll
    for (int i = 0; i < 32; i += 8) {
        int y = by + threadIdx.y + i;
        t[threadIdx.y + i][threadIdx.x] = src[(size_t)y * N + x];
    }
    __syncthreads();
    int kx = by + threadIdx.x;
    #pragma unroll
    for (int i = 0; i < 32; i += 8) {
        int ny = bx + threadIdx.y + i;
        int iny = (ny < FFd) ? (2*ny) : (2*(ny - FFd) + 1);
        dst[(size_t)iny * K + kx] = __float2half(t[threadIdx.x][threadIdx.y + i]);
    }
}

// ================= fp16 dense GEMM (ldmatrix, BK=64, 3-stage) ===============
#define ASH 72
#define HTILE (128*ASH)
#define GH_SMEM (3*2*HTILE*2)

template<int MODE>
__global__ __launch_bounds__(256, 2)
void gemm_h(const __half* __restrict__ A, const __half* __restrict__ Bt,
            const float* __restrict__ bias, const float* __restrict__ res,
            void* __restrict__ Cv, int M, int N, int K) {
    extern __shared__ __half smh[];
    __half* As = smh;
    __half* Bs = smh + 3*HTILE;
    int bm = blockIdx.y * 128, bn = blockIdx.x * 128;
    int tid = threadIdx.x, warp = tid >> 5, lane = tid & 31;
    int grp = lane >> 2, tig = lane & 3;
    int wm = (warp >> 2) * 64, wn = (warp & 3) * 32;
    int sel = lane >> 3, lrow = lane & 7;
    int a_r = (sel & 1) * 8 + lrow, a_c = (sel >> 1) * 8;
    int b_r = (sel >> 1) * 8 + lrow, b_c = (sel & 1) * 8;
    uint32_t sAu = (uint32_t)__cvta_generic_to_shared(As);
    uint32_t sBu = (uint32_t)__cvta_generic_to_shared(Bs);
    int niter = K >> 6;

    float acc[4][4][4] = {};

    auto loadTile = [&](int it, int buf) {
        int k0 = it * 64;
        #pragma unroll
        for (int i = 0; i < 4; i++) {
            int c = tid + i * 256;
            int row = c >> 3, kq = c & 7;
            cpa16(sAu + (uint32_t)(buf*HTILE + row*ASH + kq*8) * 2,
                  A + (size_t)(bm + row) * K + k0 + kq * 8);
            cpa16(sBu + (uint32_t)(buf*HTILE + row*ASH + kq*8) * 2,
                  Bt + (size_t)(bn + row) * K + k0 + kq * 8);
        }
        CP_COMMIT();
    };

    loadTile(0, 0);
    loadTile(1, 1);

    for (int it = 0; it < niter; ++it) {
        CP_WAIT1();
        __syncthreads();
        if (it + 2 < niter) loadTile(it + 2, (it + 2) % 3);
        else CP_COMMIT();

        uint32_t Abu = sAu + (uint32_t)((it % 3) * HTILE) * 2;
        uint32_t Bbu = sBu + (uint32_t)((it % 3) * HTILE) * 2;
        #pragma unroll
        for (int ks = 0; ks < 64; ks += 16) {
            uint32_t af[4][4], bf[4][2];
            #pragma unroll
            for (int mf = 0; mf < 4; mf++) {
                uint32_t ad = Abu + (uint32_t)((wm + mf*16 + a_r) * ASH + ks + a_c) * 2;
                ldsm4(af[mf][0], af[mf][1], af[mf][2], af[mf][3], ad);
            }
            #pragma unroll
            for (int np = 0; np < 2; np++) {
                uint32_t bd = Bbu + (uint32_t)((wn + np*16 + b_r) * ASH + ks + b_c) * 2;
                ldsm4(bf[2*np][0], bf[2*np][1], bf[2*np+1][0], bf[2*np+1][1], bd);
            }
            #pragma unroll
            for (int mf = 0; mf < 4; mf++)
                #pragma unroll
                for (int nf = 0; nf < 4; nf++)
                    mma_f16(acc[mf][nf], af[mf][0], af[mf][1], af[mf][2], af[mf][3],
                            bf[nf][0], bf[nf][1]);
        }
    }

    #pragma unroll
    for (int mf = 0; mf < 4; mf++) {
        #pragma unroll
        for (int nf = 0; nf < 4; nf++) {
            int r = bm + wm + mf*16 + grp;
            int c = bn + wn + nf*8 + tig*2;
            float2 v0 = make_float2(acc[mf][nf][0], acc[mf][nf][1]);
            float2 v1 = make_float2(acc[mf][nf][2], acc[mf][nf][3]);
            if (MODE == 2) {
                int j = c >> 1;
                float bv = bias[j], bg = bias[FFd + j];
                float val0 = v0.x + bv, gat0 = v0.y + bg;
                float val1 = v1.x + bv, gat1 = v1.y + bg;
                float o0 = val0 * (0.5f * gat0 * (1.f + erff(gat0 * 0.70710678118654752f)));
                float o1 = val1 * (0.5f * gat1 * (1.f + erff(gat1 * 0.70710678118654752f)));
                __half* C = (__half*)Cv;
                C[(size_t)r * FFd + j]     = __float2half(o0);
                C[(size_t)(r+8) * FFd + j] = __float2half(o1);
            } else {
                if (bias) {
                    float2 bb = *(const float2*)(bias + c);
                    v0.x += bb.x; v0.y += bb.y; v1.x += bb.x; v1.y += bb.y;
                }
                if (MODE == 0 && res) {
                    float2 r0 = *(const float2*)(res + (size_t)r * N + c);
                    float2 r1 = *(const float2*)(res + (size_t)(r+8) * N + c);
                    v0.x += r0.x; v0.y += r0.y; v1.x += r1.x; v1.y += r1.y;
                }
                if (MODE == 1) {
                    __half* C = (__half*)Cv;
                    *(__half2*)(C + (size_t)r * N + c)     = __floats2half2_rn(v0.x, v0.y);
                    *(__half2*)(C + (size_t)(r+8) * N + c) = __floats2half2_rn(v1.x, v1.y);
                } else {
                    float* C = (float*)Cv;
                    *(float2*)(C + (size_t)r * N + c)     = v0;
                    *(float2*)(C + (size_t)(r+8) * N + c) = v1;
                }
            }
        }
    }
}

// ================= fp16 flash attention (register-P + double-buffered KV) ===
#define QSH 72
#define FTILE (128*QSH)
#define FLH_SMEM (5*FTILE*2)     // Q + 2*K + 2*V

__global__ __launch_bounds__(256, 2)
void flash_h(const __half* __restrict__ qkv, __half* __restrict__ o) {
    extern __shared__ __half smf[];
    __half* Qs = smf;
    uint32_t Qsu = (uint32_t)__cvta_generic_to_shared(Qs);
    uint32_t Ku[2] = { Qsu + (uint32_t)FTILE*2,   Qsu + (uint32_t)(2*FTILE)*2 };
    uint32_t Vu[2] = { Qsu + (uint32_t)(3*FTILE)*2, Qsu + (uint32_t)(4*FTILE)*2 };

    const int ldq = 3*Dm;
    int qt = blockIdx.x, bh = blockIdx.y;
    int b = bh >> 4, h = bh & 15;
    int tid = threadIdx.x, warp = tid >> 5, lane = tid & 31;
    int grp = lane >> 2, tig = lane & 3;
    int sel = lane >> 3, lrow = lane & 7;
    int a_r = (sel & 1) * 8 + lrow, a_c = (sel >> 1) * 8;
    int b_r = (sel >> 1) * 8 + lrow, b_c = (sel & 1) * 8;

    const __half* qb = qkv + ((size_t)b*SEQ + qt*128) * ldq + h*DHd;
    const __half* kb = qkv + (size_t)b*SEQ*ldq + Dm + h*DHd;
    const __half* vb = qkv + (size_t)b*SEQ*ldq + 2*Dm + h*DHd;

    // Q tile
    {
        int row = tid >> 1, part = tid & 1;
        const float4* s4 = (const float4*)(qb + (size_t)row * ldq + part*32);
        float4* d4 = (float4*)(Qs + row*QSH + part*32);
        #pragma unroll
        for (int i = 0; i < 4; i++) d4[i] = s4[i];
    }

    // KV tile loader via cp.async
    auto loadKV = [&](int kv0, int buf) {
        #pragma unroll
        for (int i = 0; i < 4; i++) {
            int c = tid + i * 256;
            int row = c >> 3, kq = c & 7;
            cpa16(Ku[buf] + (uint32_t)(row*QSH + kq*8) * 2,
                  kb + (size_t)(kv0 + row) * ldq + kq * 8);
            cpa16(Vu[buf] + (uint32_t)(row*QSH + kq*8) * 2,
                  vb + (size_t)(kv0 + row) * ldq + kq * 8);
        }
        CP_COMMIT();
    };
    loadKV(0, 0);

    __syncthreads();
    uint32_t qf[4][4];
    {
        const __half* p = Qs + (warp*16 + grp) * QSH;
        #pragma unroll
        for (int ksi = 0; ksi < 4; ksi++) {
            qf[ksi][0] = *(const uint32_t*)(p + ksi*16 + tig*2);
            qf[ksi][1] = *(const uint32_t*)(p + 8*QSH + ksi*16 + tig*2);
            qf[ksi][2] = *(const uint32_t*)(p + ksi*16 + tig*2 + 8);
            qf[ksi][3] = *(const uint32_t*)(p + 8*QSH + ksi*16 + tig*2 + 8);
        }
    }

    float oacc[8][4] = {};
    float m0 = -1e30f, m1 = -1e30f, l0 = 0.f, l1 = 0.f;
    const float Csc = SCALE_ATTN * 1.4426950408889634f;

    for (int it = 0; it < SEQ/128; ++it) {
        int buf = it & 1;
        CP_WAIT0();
        __syncthreads();
        if (it + 1 < SEQ/128) loadKV((it + 1) * 128, buf ^ 1);

        // S = Q K^T
        float sacc[16][4] = {};
        #pragma unroll
        for (int ksi = 0; ksi < 4; ksi++) {
            #pragma unroll
            for (int np = 0; np < 8; np++) {
                uint32_t kd = Ku[buf] + (uint32_t)((np*16 + b_r) * QSH + ksi*16 + b_c) * 2;
                uint32_t b00, b01, b10, b11;
                ldsm4(b00, b01, b10, b11, kd);
                mma_f16(sacc[2*np],   qf[ksi][0], qf[ksi][1], qf[ksi][2], qf[ksi][3], b00, b01);
                mma_f16(sacc[2*np+1], qf[ksi][0], qf[ksi][1], qf[ksi][2], qf[ksi][3], b10, b11);
            }
        }
        // online softmax — P stays in registers as A-fragments
        float mx0 = -1e30f, mx1 = -1e30f;
        #pragma unroll
        for (int nf = 0; nf < 16; nf++) {
            sacc[nf][0] *= Csc; sacc[nf][1] *= Csc; sacc[nf][2] *= Csc; sacc[nf][3] *= Csc;
            mx0 = fmaxf(mx0, fmaxf(sacc[nf][0], sacc[nf][1]));
            mx1 = fmaxf(mx1, fmaxf(sacc[nf][2], sacc[nf][3]));
        }
        mx0 = fmaxf(mx0, __shfl_xor_sync(0xffffffffu, mx0, 1));
        mx0 = fmaxf(mx0, __shfl_xor_sync(0xffffffffu, mx0, 2));
        mx1 = fmaxf(mx1, __shfl_xor_sync(0xffffffffu, mx1, 1));
        mx1 = fmaxf(mx1, __shfl_xor_sync(0xffffffffu, mx1, 2));
        float mn0 = fmaxf(m0, mx0), mn1 = fmaxf(m1, mx1);
        float sc0 = ex2f(m0 - mn0), sc1 = ex2f(m1 - mn1);
        float sum0 = 0.f, sum1 = 0.f;
        uint32_t ph[16][2];
        #pragma unroll
        for (int nf = 0; nf < 16; nf++) {
            float p0 = ex2f(sacc[nf][0] - mn0);
            float p1 = ex2f(sacc[nf][1] - mn0);
            float p2 = ex2f(sacc[nf][2] - mn1);
            float p3 = ex2f(sacc[nf][3] - mn1);
            sum0 += p0 + p1; sum1 += p2 + p3;
            ph[nf][0] = pack_h2(p0, p1);
            ph[nf][1] = pack_h2(p2, p3);
        }
        sum0 += __shfl_xor_sync(0xffffffffu, sum0, 1);
        sum0 += __shfl_xor_sync(0xffffffffu, sum0, 2);
        sum1 += __shfl_xor_sync(0xffffffffu, sum1, 1);
        sum1 += __shfl_xor_sync(0xffffffffu, sum1, 2);
        l0 = l0 * sc0 + sum0;  l1 = l1 * sc1 + sum1;
        m0 = mn0;  m1 = mn1;
        #pragma unroll
        for (int nf = 0; nf < 8; nf++) {
            oacc[nf][0] *= sc0; oacc[nf][1] *= sc0;
            oacc[nf][2] *= sc1; oacc[nf][3] *= sc1;
        }

        // O += P V  — P from registers, V via ldmatrix.trans
        #pragma unroll
        for (int ks = 0; ks < 8; ks++) {
            uint32_t a0 = ph[2*ks][0], a1 = ph[2*ks][1];
            uint32_t a2 = ph[2*ks+1][0], a3 = ph[2*ks+1][1];
            #pragma unroll
            for (int np = 0; np < 4; np++) {
                uint32_t vd = Vu[buf] + (uint32_t)((ks*16 + a_r) * QSH + np*16 + a_c) * 2;
                uint32_t b00, b01, b10, b11;
                ldsm4t(b00, b01, b10, b11, vd);
                mma_f16(oacc[2*np],   a0, a1, a2, a3, b00, b01);
                mma_f16(oacc[2*np+1], a0, a1, a2, a3, b10, b11);
            }
        }
    }

    float i0 = 1.f / l0, i1 = 1.f / l1;
    __half* ob = o + ((size_t)b*SEQ + qt*128 + warp*16) * Dm + h*DHd;
    #pragma unroll
    for (int nf = 0; nf < 8; nf++) {
        int c = nf*8 + tig*2;
        *(__half2*)(ob + (size_t)grp * Dm + c) =
            __floats2half2_rn(oacc[nf][0]*i0, oacc[nf][1]*i0);
        *(__half2*)(ob + (size_t)(grp+8) * Dm + c) =
            __floats2half2_rn(oacc[nf][2]*i1, oacc[nf][3]*i1);
    }
}

// ================= fp16 cross-attention (single KV tile, nk=77) =============
#define CKROWS 80
#define FLC_SMEM ((128*QSH + 2*CKROWS*QSH)*2)

__global__ __launch_bounds__(256, 2)
void flash_cross(const __half* __restrict__ q, const __half* __restrict__ k,
                 const __half* __restrict__ v, __half* __restrict__ o) {
    extern __shared__ __half smc[];
    __half* Qs = smc;
    __half* Ks = Qs + 128*QSH;
    __half* Vs = Ks + CKROWS*QSH;
    uint32_t Vsu = (uint32_t)__cvta_generic_to_shared(Vs);

    int qt = blockIdx.x, bh = blockIdx.y;
    int b = bh >> 4, h = bh & 15;
    int tid = threadIdx.x, warp = tid >> 5, lane = tid & 31;
    int grp = lane >> 2, tig = lane & 3;
    int sel = lane >> 3, lrow = lane & 7;
    int a_r = (sel & 1) * 8 + lrow, a_c = (sel >> 1) * 8;

    const __half* qb = q + ((size_t)b*SEQ + qt*128) * Dm + h*DHd;
    const __half* kb = k + (size_t)b*NCx*Dm + h*DHd;
    const __half* vb = v + (size_t)b*NCx*Dm + h*DHd;

    {
        int row = tid >> 1, part = tid & 1;
        const float4* s4 = (const float4*)(qb + (size_t)row * Dm + part*32);
        float4* d4 = (float4*)(Qs + row*QSH + part*32);
        #pragma unroll
        for (int i = 0; i < 4; i++) d4[i] = s4[i];
    }
    for (int rr = tid; rr < CKROWS*2; rr += 256) {
        int row = rr >> 1, part = rr & 1;
        float4* dk = (float4*)(Ks + row*QSH + part*32);
        float4* dv = (float4*)(Vs + row*QSH + part*32);
        if (row < NCx) {
            const float4* sk = (const float4*)(kb + (size_t)row * Dm + part*32);
            const float4* sv = (const float4*)(vb + (size_t)row * Dm + part*32);
            #pragma unroll
            for (int i = 0; i < 4; i++) { dk[i] = sk[i]; dv[i] = sv[i]; }
        } else {
            float4 z = make_float4(0.f,0.f,0.f,0.f);
            #pragma unroll
            for (int i = 0; i < 4; i++) { dk[i] = z; dv[i] = z; }
        }
    }
    __syncthreads();

    uint32_t qf[4][4];
    {
        const __half* p = Qs + (warp*16 + grp) * QSH;
        #pragma unroll
        for (int ksi = 0; ksi < 4; ksi++) {
            qf[ksi][0] = *(const uint32_t*)(p + ksi*16 + tig*2);
            qf[ksi][1] = *(const uint32_t*)(p + 8*QSH + ksi*16 + tig*2);
            qf[ksi][2] = *(const uint32_t*)(p + ksi*16 + tig*2 + 8);
            qf[ksi][3] = *(const uint32_t*)(p + 8*QSH + ksi*16 + tig*2 + 8);
        }
    }

    const float Csc = SCALE_ATTN * 1.4426950408889634f;

    float sacc[10][4] = {};
    #pragma unroll
    for (int ksi = 0; ksi < 4; ksi++) {
        #pragma unroll
        for (int nf = 0; nf < 10; nf++) {
            const __half* kp = Ks + (nf*8 + grp) * QSH + ksi*16;
            uint32_t b0 = *(const uint32_t*)(kp + tig*2);
            uint32_t b1 = *(const uint32_t*)(kp + tig*2 + 8);
            mma_f16(sacc[nf], qf[ksi][0], qf[ksi][1], qf[ksi][2], qf[ksi][3], b0, b1);
        }
    }
    float mx0 = -1e30f, mx1 = -1e30f;
    #pragma unroll
    for (int nf = 0; nf < 10; nf++) {
        int c0 = nf*8 + tig*2, c1 = c0 + 1;
        sacc[nf][0] = (c0 < NCx) ? sacc[nf][0]*Csc : -1e30f;
        sacc[nf][1] = (c1 < NCx) ? sacc[nf][1]*Csc : -1e30f;
        sacc[nf][2] = (c0 < NCx) ? sacc[nf][2]*Csc : -1e30f;
        sacc[nf][3] = (c1 < NCx) ? sacc[nf][3]*Csc : -1e30f;
        mx0 = fmaxf(mx0, fmaxf(sacc[nf][0], sacc[nf][1]));
        mx1 = fmaxf(mx1, fmaxf(sacc[nf][2], sacc[nf][3]));
    }
    mx0 = fmaxf(mx0, __shfl_xor_sync(0xffffffffu, mx0, 1));
    mx0 = fmaxf(mx0, __shfl_xor_sync(0xffffffffu, mx0, 2));
    mx1 = fmaxf(mx1, __shfl_xor_sync(0xffffffffu, mx1, 1));
    mx1 = fmaxf(mx1, __shfl_xor_sync(0xffffffffu, mx1, 2));

    float sum0 = 0.f, sum1 = 0.f;
    uint32_t ph[10][2];
    #pragma unroll
    for (int nf = 0; nf < 10; nf++) {
        float p0 = ex2f(sacc[nf][0] - mx0);
        float p1 = ex2f(sacc[nf][1] - mx0);
        float p2 = ex2f(sacc[nf][2] - mx1);
        float p3 = ex2f(sacc[nf][3] - mx1);
        sum0 += p0 + p1; sum1 += p2 + p3;
        ph[nf][0] = pack_h2(p0, p1);
        ph[nf][1] = pack_h2(p2, p3);
    }
    sum0 += __shfl_xor_sync(0xffffffffu, sum0, 1);
    sum0 += __shfl_xor_sync(0xffffffffu, sum0, 2);
    sum1 += __shfl_xor_sync(0xffffffffu, sum1, 1);
    sum1 += __shfl_xor_sync(0xffffffffu, sum1, 2);

    float oacc[8][4] = {};
    #pragma unroll
    for (int ks = 0; ks < 5; ks++) {
        uint32_t a0 = ph[2*ks][0], a1 = ph[2*ks][1];
        uint32_t a2 = ph[2*ks+1][0], a3 = ph[2*ks+1][1];
        #pragma unroll
        for (int np = 0; np < 4; np++) {
            uint32_t vd = Vsu + (uint32_t)((ks*16 + a_r) * QSH + np*16 + a_c) * 2;
            uint32_t b00, b01, b10, b11;
            ldsm4t(b00, b01, b10, b11, vd);
            mma_f16(oacc[2*np],   a0, a1, a2, a3, b00, b01);
            mma_f16(oacc[2*np+1], a0, a1, a2, a3, b10, b11);
        }
    }

    float i0 = 1.f / sum0, i1 = 1.f / sum1;
    __half* ob = o + ((size_t)b*SEQ + qt*128 + warp*16) * Dm + h*DHd;
    #pragma unroll
    for (int nf = 0; nf < 8; nf++) {
        int c = nf*8 + tig*2;
        *(__half2*)(ob + (size_t)grp * Dm + c) =
            __floats2half2_rn(oacc[nf][0]*i0, oacc[nf][1]*i0);
        *(__half2*)(ob + (size_t)(grp+8) * Dm + c) =
            __floats2half2_rn(oacc[nf][2]*i1, oacc[nf][3]*i1);
    }
}

// ---------------- layernorm: single-pass float4 + warp shuffle ----------------
__global__ __launch_bounds__(256)
void ln_kernel(const float* __restrict__ x, const float* __restrict__ g,
               const float* __restrict__ b, __half* __restrict__ out) {
    int row = blockIdx.x;
    int tid = threadIdx.x, warp = tid >> 5, lane = tid & 31;
    const float4* xr = (const float4*)(x + (size_t)row * Dm);
    float4 v = xr[tid];
    float s  = v.x + v.y + v.z + v.w;
    float ss = v.x*v.x + v.y*v.y + v.z*v.z + v.w*v.w;
    #pragma unroll
    for (int o = 16; o > 0; o >>= 1) {
        s  += __shfl_xor_sync(0xffffffffu, s,  o);
        ss += __shfl_xor_sync(0xffffffffu, ss, o);
    }
    __shared__ float ws[8], wss[8];
    if (lane == 0) { ws[warp] = s; wss[warp] = ss; }
    __syncthreads();
    float ts = 0.f, tss = 0.f;
    #pragma unroll
    for (int i = 0; i < 8; i++) { ts += ws[i]; tss += wss[i]; }
    float mu  = ts * (1.0f / Dm);
    float var = tss * (1.0f / Dm) - mu * mu;
    float inv = rsqrtf(var + EPS_LN);
    float4 gv = ((const float4*)g)[tid];
    float4 bv = ((const float4*)b)[tid];
    float o0 = (v.x - mu) * inv * gv.x + bv.x;
    float o1 = (v.y - mu) * inv * gv.y + bv.y;
    float o2 = (v.z - mu) * inv * gv.z + bv.z;
    float o3 = (v.w - mu) * inv * gv.w + bv.w;
    __half2* orow = (__half2*)(out + (size_t)row * Dm) + tid * 2;
    orow[0] = __floats2half2_rn(o0, o1);
    orow[1] = __floats2half2_rn(o2, o3);
}

__global__ void gemm_kv_h(const float* __restrict__ A,
                          const float* __restrict__ Wk, const float* __restrict__ Wv,
                          __half* __restrict__ Ck, __half* __restrict__ Cv,
                          int M, int K, int Nn) {
    __shared__ float As[64][17];
    __shared__ float Bs[16][64];
    const float* Bm = (blockIdx.z == 0) ? Wk : Wv;
    __half* C = (blockIdx.z == 0) ? Ck : Cv;
    int bm = blockIdx.y * 64, bn = blockIdx.x * 64;
    int tx = threadIdx.x & 15, ty = threadIdx.x >> 4;
    float acc[4][4] = {};
    for (int k0 = 0; k0 < K; k0 += 16) {
        #pragma unroll
        for (int i = 0; i < 4; i++) {
            int idx = threadIdx.x + i * 256;
            int r = idx >> 4, kk = idx & 15;
            int gr = bm + r;
            As[r][kk] = (gr < M) ? A[(size_t)gr * K + k0 + kk] : 0.f;
            int kb = idx >> 6, c = idx & 63;
            int gc = bn + c;
            Bs[kb][c] = (gc < Nn) ? Bm[(size_t)(k0 + kb) * Nn + gc] : 0.f;
        }
        __syncthreads();
        #pragma unroll
        for (int kk = 0; kk < 16; kk++) {
            float a[4], bb[4];
            #pragma unroll
            for (int i = 0; i < 4; i++) a[i]  = As[ty*4+i][kk];
            #pragma unroll
            for (int j = 0; j < 4; j++) bb[j] = Bs[kk][tx*4+j];
            #pragma unroll
            for (int i = 0; i < 4; i++)
                #pragma unroll
                for (int j = 0; j < 4; j++)
                    acc[i][j] += a[i] * bb[j];
        }
        __syncthreads();
    }
    #pragma unroll
    for (int i = 0; i < 4; i++) {
        int gr = bm + ty*4 + i;
        if (gr >= M) continue;
        #pragma unroll
        for (int j = 0; j < 4; j++) {
            int gc = bn + tx*4 + j;
            if (gc >= Nn) continue;
            C[(size_t)gr * Nn + gc] = __float2half(acc[i][j]);
        }
    }
}

// ---------------- launch ----------------
extern "C" void kernel_launch(void* const* d_in, const int* in_sizes, int n_in,
                              void* d_out, int out_size) {
    const float* x      = (const float*)d_in[0];
    const float* ctx    = (const float*)d_in[1];
    const float* w1_q   = (const float*)d_in[2];
    const float* w1_k   = (const float*)d_in[3];
    const float* w1_v   = (const float*)d_in[4];
    const float* w1_o   = (const float*)d_in[5];
    const float* b1_o   = (const float*)d_in[6];
    const float* w2_q   = (const float*)d_in[7];
    const float* w2_k   = (const float*)d_in[8];
    const float* w2_v   = (const float*)d_in[9];
    const float* w2_o   = (const float*)d_in[10];
    const float* b2_o   = (const float*)d_in[11];
    const float* ln1_g  = (const float*)d_in[12];
    const float* ln1_b  = (const float*)d_in[13];
    const float* ln2_g  = (const float*)d_in[14];
    const float* ln2_b  = (const float*)d_in[15];
    const float* ln3_g  = (const float*)d_in[16];
    const float* ln3_b  = (const float*)d_in[17];
    const float* ff_w1  = (const float*)d_in[18];
    const float* ff_b1  = (const float*)d_in[19];
    const float* ff_w2  = (const float*)d_in[20];
    const float* ff_b2  = (const float*)d_in[21];
    float* xbuf = (float*)d_out;

    __half *hh, *qkvh, *kh, *vh, *atth, *th, *wh;
    cudaGetSymbolAddress((void**)&hh,   g_hh);
    cudaGetSymbolAddress((void**)&qkvh, g_qkv);
    cudaGetSymbolAddress((void**)&kh,   g_kh);
    cudaGetSymbolAddress((void**)&vh,   g_vh);
    cudaGetSymbolAddress((void**)&atth, g_atth);
    cudaGetSymbolAddress((void**)&th,   g_th);
    cudaGetSymbolAddress((void**)&wh,   g_wh);

    cudaFuncSetAttribute(gemm_h<0>, cudaFuncAttributeMaxDynamicSharedMemorySize, GH_SMEM);
    cudaFuncSetAttribute(gemm_h<1>, cudaFuncAttributeMaxDynamicSharedMemorySize, GH_SMEM);
    cudaFuncSetAttribute(gemm_h<2>, cudaFuncAttributeMaxDynamicSharedMemorySize, GH_SMEM);
    cudaFuncSetAttribute(flash_h,     cudaFuncAttributeMaxDynamicSharedMemorySize, FLH_SMEM);
    cudaFuncSetAttribute(flash_cross, cudaFuncAttributeMaxDynamicSharedMemorySize, FLC_SMEM);

    dim3 gD(Dm/128, MROWS/128);
    dim3 gQKV(3*Dm/128, MROWS/128);
    dim3 gFF1(2*FFd/128, MROWS/128);
    dim3 gFlash(SEQ/128, Bq*Hh);
    dim3 tpb(32, 8);

    transpose_half6<<<dim3(Dm/32, Dm/32, 6), tpb>>>(
        w1_q, w1_k, w1_v, w1_o, w2_q, w2_o,
        wh+OWQKV, wh+OWQKV+1024*1024, wh+OWQKV+2*1024*1024,
        wh+OW1O, wh+OW2Q, wh+OW2O);
    transpose_geglu<<<dim3(2*FFd/32, Dm/32), tpb>>>(ff_w1, wh+OFW1, Dm,  2*FFd);
    transpose_half<<<dim3(Dm/32,  FFd/32),  tpb>>>(ff_w2, wh+OFW2, FFd, Dm);

    // ---- self attention ----
    ln_kernel<<<MROWS, 256>>>(x, ln1_g, ln1_b, hh);
    gemm_h<1><<<gQKV, 256, GH_SMEM>>>(hh, wh+OWQKV, nullptr, nullptr, qkvh, MROWS, 3*Dm, Dm);
    flash_h<<<gFlash, 256, FLH_SMEM>>>(qkvh, atth);
    gemm_h<0><<<gD, 256, GH_SMEM>>>(atth, wh+OW1O, b1_o, x, xbuf, MROWS, Dm, Dm);

    // ---- cross attention ----
    ln_kernel<<<MROWS, 256>>>(xbuf, ln2_g, ln2_b, hh);
    gemm_h<1><<<gD, 256, GH_SMEM>>>(hh, wh+OW2Q, nullptr, nullptr, atth, MROWS, Dm, Dm);
    dim3 gKV(Dm/64, (CROWS+63)/64, 2);
    gemm_kv_h<<<gKV, 256>>>(ctx, w2_k, w2_v, kh, vh, CROWS, DCx, Dm);
    flash_cross<<<gFlash, 256, FLC_SMEM>>>(atth, kh, vh, qkvh);
    gemm_h<0><<<gD, 256, GH_SMEM>>>(qkvh, wh+OW2O, b2_o, xbuf, xbuf, MROWS, Dm, Dm);

    // ---- GEGLU FFN ----
    ln_kernel<<<MROWS, 256>>>(xbuf, ln3_g, ln3_b, hh);
    gemm_h<2><<<gFF1, 256, GH_SMEM>>>(hh, wh+OFW1, ff_b1, nullptr, th, MROWS, 2*FFd, Dm);
    gemm_h<0><<<gD, 256, GH_SMEM>>>(th, wh+OFW2, ff_b2, xbuf, xbuf, MROWS, Dm, FFd);
}